// round 2
// baseline (speedup 1.0000x reference)
#include <cuda_runtime.h>
#include <math.h>

#define N_NODES  100000
#define N_EDGES  3200000
#define N_GRAPHS 512
#define DIM      128
#define NLAYERS  3
#define DCAT     384
#define NCLS     10
#define BN_EPS   1e-5f

// Scratch (device globals; no allocations allowed)
__device__ float g_aggr[N_NODES * DIM];
__device__ float g_z[N_NODES * DIM];
__device__ float g_h[N_NODES * DIM];
__device__ float g_pooled[N_GRAPHS * DCAT];
__device__ float g_hfin[N_GRAPHS * DCAT];

__global__ void zero_kernel(float4* __restrict__ p, int n4) {
    int i = blockIdx.x * blockDim.x + threadIdx.x;
    int stride = gridDim.x * blockDim.x;
    float4 z = make_float4(0.f, 0.f, 0.f, 0.f);
    for (; i < n4; i += stride) p[i] = z;
}

// One warp per edge: gather h[src] (128 floats = 32 lanes x float4),
// vector atomic add into aggr[dst]. edge_index is INT32 (JAX x64 disabled).
__global__ void __launch_bounds__(256) scatter_kernel(
        const float* __restrict__ h,
        const int* __restrict__ ei,
        float* __restrict__ aggr) {
    unsigned e = (blockIdx.x * 256u + threadIdx.x) >> 5;
    int lane = threadIdx.x & 31;
    if (e >= N_EDGES) return;
    int s = __ldg(&ei[e]);
    int d = __ldg(&ei[N_EDGES + e]);
    float4 v = __ldg((const float4*)(h + (long long)s * DIM) + lane);
    float* dst = aggr + (long long)d * DIM + lane * 4;
    asm volatile("red.global.add.v4.f32 [%0], {%1,%2,%3,%4};"
                 :: "l"(dst), "f"(v.x), "f"(v.y), "f"(v.z), "f"(v.w)
                 : "memory");
}

// Fused GEMM: out[row][j] = epilogue( (A[row]+A2[row]) @ W + bias )
// Tile: 128 rows x 128 cols per block, 256 threads, 8x8 per thread.
// A stored transposed in smem with XOR swizzle (k-major: As[k][row^(k>>2)]).
// mode 0: BN (eval) + ReLU epilogue -> out
// mode 1: ReLU epilogue -> out, plus atomic pooling into pooled[batch[row]*384+pool_off+col]
__global__ void __launch_bounds__(256, 2) gemm_kernel(
        const float* __restrict__ A, const float* __restrict__ A2,
        const float* __restrict__ W, const float* __restrict__ bias,
        const float* __restrict__ gamma, const float* __restrict__ beta,
        const float* __restrict__ rmean, const float* __restrict__ rvar,
        const int* __restrict__ batch, float* __restrict__ pooled, int pool_off,
        float* __restrict__ outp, int mode) {
    extern __shared__ float As[];   // 128*128 floats = 64KB
    __shared__ int sb[128];
    int tid = threadIdx.x;
    int row0 = blockIdx.x * 128;

    // Load A tile (coalesced), add A2 if present, store transposed + swizzled.
#pragma unroll
    for (int it = 0; it < 16; it++) {
        int i = tid + it * 256;
        int r = i >> 5;           // row within tile
        int c4 = i & 31;          // float4 index along k
        int row = row0 + r;
        float4 v = make_float4(0.f, 0.f, 0.f, 0.f);
        if (row < N_NODES) {
            v = __ldg((const float4*)(A + (long long)row * DIM) + c4);
            if (A2) {
                float4 u = __ldg((const float4*)(A2 + (long long)row * DIM) + c4);
                v.x += u.x; v.y += u.y; v.z += u.z; v.w += u.w;
            }
        }
        int k = c4 * 4;
        int rs = r ^ c4;          // swizzle: conflict-free stores, broadcast reads
        As[(k + 0) * DIM + rs] = v.x;
        As[(k + 1) * DIM + rs] = v.y;
        As[(k + 2) * DIM + rs] = v.z;
        As[(k + 3) * DIM + rs] = v.w;
    }
    if (mode == 1 && tid < 128) {
        int row = row0 + tid;
        sb[tid] = (row < N_NODES) ? __ldg(&batch[row]) : 0;
    }
    __syncthreads();

    int tr = tid >> 4;   // 0..15 -> rows tr*8..tr*8+7
    int tc = tid & 15;   // 0..15 -> cols tc*8..tc*8+7
    float acc[8][8];
#pragma unroll
    for (int a = 0; a < 8; a++)
#pragma unroll
        for (int b = 0; b < 8; b++) acc[a][b] = 0.f;

    const float4* Wv = (const float4*)W;
#pragma unroll 4
    for (int k = 0; k < 128; k++) {
        float4 w0 = __ldg(Wv + k * 32 + tc * 2);
        float4 w1 = __ldg(Wv + k * 32 + tc * 2 + 1);
        int xr = (k >> 2) & 31;
        float a[8];
#pragma unroll
        for (int rr = 0; rr < 8; rr++)
            a[rr] = As[k * DIM + ((tr * 8 + rr) ^ xr)];
#pragma unroll
        for (int rr = 0; rr < 8; rr++) {
            acc[rr][0] += a[rr] * w0.x; acc[rr][1] += a[rr] * w0.y;
            acc[rr][2] += a[rr] * w0.z; acc[rr][3] += a[rr] * w0.w;
            acc[rr][4] += a[rr] * w1.x; acc[rr][5] += a[rr] * w1.y;
            acc[rr][6] += a[rr] * w1.z; acc[rr][7] += a[rr] * w1.w;
        }
    }

    int col = tc * 8;
    float4 bi0 = __ldg((const float4*)(bias + col));
    float4 bi1 = __ldg((const float4*)(bias + col) + 1);
    float bb[8] = {bi0.x, bi0.y, bi0.z, bi0.w, bi1.x, bi1.y, bi1.z, bi1.w};

    float sc[8], sh[8];
    if (mode == 0) {
        float4 g0 = __ldg((const float4*)(gamma + col));
        float4 g1 = __ldg((const float4*)(gamma + col) + 1);
        float4 be0 = __ldg((const float4*)(beta + col));
        float4 be1 = __ldg((const float4*)(beta + col) + 1);
        float4 rm0 = __ldg((const float4*)(rmean + col));
        float4 rm1 = __ldg((const float4*)(rmean + col) + 1);
        float4 rv0 = __ldg((const float4*)(rvar + col));
        float4 rv1 = __ldg((const float4*)(rvar + col) + 1);
        float gg[8] = {g0.x, g0.y, g0.z, g0.w, g1.x, g1.y, g1.z, g1.w};
        float bt[8] = {be0.x, be0.y, be0.z, be0.w, be1.x, be1.y, be1.z, be1.w};
        float rm[8] = {rm0.x, rm0.y, rm0.z, rm0.w, rm1.x, rm1.y, rm1.z, rm1.w};
        float rv[8] = {rv0.x, rv0.y, rv0.z, rv0.w, rv1.x, rv1.y, rv1.z, rv1.w};
#pragma unroll
        for (int cc = 0; cc < 8; cc++) {
            sc[cc] = gg[cc] * rsqrtf(rv[cc] + BN_EPS);
            sh[cc] = bt[cc] - rm[cc] * sc[cc];
        }
    }

#pragma unroll
    for (int rr = 0; rr < 8; rr++) {
        int row = row0 + tr * 8 + rr;
        if (row >= N_NODES) continue;
        float v[8];
#pragma unroll
        for (int cc = 0; cc < 8; cc++) {
            float y = acc[rr][cc] + bb[cc];
            if (mode == 0) y = sc[cc] * y + sh[cc];
            v[cc] = fmaxf(y, 0.f);
        }
        float4 o0 = make_float4(v[0], v[1], v[2], v[3]);
        float4 o1 = make_float4(v[4], v[5], v[6], v[7]);
        float* op = outp + (long long)row * DIM + col;
        *(float4*)(op) = o0;
        *(float4*)(op + 4) = o1;
        if (mode == 1) {
            float* pb = pooled + sb[tr * 8 + rr] * DCAT + pool_off + col;
            asm volatile("red.global.add.v4.f32 [%0], {%1,%2,%3,%4};"
                         :: "l"(pb), "f"(o0.x), "f"(o0.y), "f"(o0.z), "f"(o0.w)
                         : "memory");
            asm volatile("red.global.add.v4.f32 [%0], {%1,%2,%3,%4};"
                         :: "l"(pb + 4), "f"(o1.x), "f"(o1.y), "f"(o1.z), "f"(o1.w)
                         : "memory");
        }
    }
}

// h_fin = relu(pooled @ Wfin + bfin): one block per graph, 384 threads.
__global__ void __launch_bounds__(DCAT) fin1_kernel(
        const float* __restrict__ pooled, const float* __restrict__ Wfin,
        const float* __restrict__ bfin, float* __restrict__ hfin) {
    __shared__ float s[DCAT];
    int g = blockIdx.x;
    int j = threadIdx.x;
    s[j] = pooled[g * DCAT + j];
    __syncthreads();
    float acc0 = 0.f, acc1 = 0.f, acc2 = 0.f, acc3 = 0.f;
#pragma unroll 4
    for (int k = 0; k < DCAT; k += 4) {
        acc0 += s[k + 0] * __ldg(&Wfin[(k + 0) * DCAT + j]);
        acc1 += s[k + 1] * __ldg(&Wfin[(k + 1) * DCAT + j]);
        acc2 += s[k + 2] * __ldg(&Wfin[(k + 2) * DCAT + j]);
        acc3 += s[k + 3] * __ldg(&Wfin[(k + 3) * DCAT + j]);
    }
    float acc = (acc0 + acc1) + (acc2 + acc3) + __ldg(&bfin[j]);
    hfin[g * DCAT + j] = fmaxf(acc, 0.f);
}

// logits + log_softmax: one warp per graph.
__global__ void __launch_bounds__(32) fin2_kernel(
        const float* __restrict__ hfin, const float* __restrict__ Wout,
        const float* __restrict__ bout, float* __restrict__ out, int out_size) {
    int g = blockIdx.x;
    int lane = threadIdx.x;
    bool valid = lane < NCLS;
    float acc = valid ? __ldg(&bout[lane]) : 0.f;
    for (int k = 0; k < DCAT; k++) {
        float v = __ldg(&hfin[g * DCAT + k]);
        if (valid) acc += v * __ldg(&Wout[k * NCLS + lane]);
    }
    float logit = acc;
    float m = valid ? logit : -INFINITY;
#pragma unroll
    for (int off = 16; off > 0; off >>= 1)
        m = fmaxf(m, __shfl_xor_sync(0xFFFFFFFFu, m, off));
    float e = valid ? expf(logit - m) : 0.f;
#pragma unroll
    for (int off = 16; off > 0; off >>= 1)
        e += __shfl_xor_sync(0xFFFFFFFFu, e, off);
    float ls = logit - m - logf(e);
    if (valid) {
        out[g * NCLS + lane] = logit;
        if (out_size >= 2 * N_GRAPHS * NCLS)
            out[N_GRAPHS * NCLS + g * NCLS + lane] = ls;
    }
}

extern "C" void kernel_launch(void* const* d_in, const int* in_sizes, int n_in,
                              void* d_out, int out_size) {
    const float* x        = (const float*)d_in[0];
    const int*   ei       = (const int*)d_in[1];     // int32 (JAX x64 off)
    const int*   batch    = (const int*)d_in[2];     // int32

    // num_layers scalar may or may not be materialized as an input; detect it.
    int w = 3;
    if (n_in >= 4 && in_sizes[3] == 1) w = 4;

    const float* W1   = (const float*)d_in[w + 0];
    const float* b1   = (const float*)d_in[w + 1];
    const float* gamma= (const float*)d_in[w + 2];
    const float* beta = (const float*)d_in[w + 3];
    const float* rmean= (const float*)d_in[w + 4];
    const float* rvar = (const float*)d_in[w + 5];
    const float* W2   = (const float*)d_in[w + 6];
    const float* b2   = (const float*)d_in[w + 7];
    const float* Wfin = (const float*)d_in[w + 8];
    const float* bfin = (const float*)d_in[w + 9];
    const float* Wout = (const float*)d_in[w + 10];
    const float* bout = (const float*)d_in[w + 11];
    float* out = (float*)d_out;

    float *aggr, *z, *h, *pooled, *hfin;
    cudaGetSymbolAddress((void**)&aggr,   g_aggr);
    cudaGetSymbolAddress((void**)&z,      g_z);
    cudaGetSymbolAddress((void**)&h,      g_h);
    cudaGetSymbolAddress((void**)&pooled, g_pooled);
    cudaGetSymbolAddress((void**)&hfin,   g_hfin);

    cudaFuncSetAttribute(gemm_kernel,
                         cudaFuncAttributeMaxDynamicSharedMemorySize, 65536);

    // zero pooled accumulator
    zero_kernel<<<192, 256>>>((float4*)pooled, N_GRAPHS * DCAT / 4);

    const int gemm_blocks = (N_NODES + 127) / 128;      // 782
    const int scat_blocks = N_EDGES / 8;                // 400000 (8 warps/block, 1 edge/warp)

    const float* hcur = x;
    for (int i = 0; i < NLAYERS; i++) {
        zero_kernel<<<12800, 256>>>((float4*)aggr, N_NODES * DIM / 4);
        scatter_kernel<<<scat_blocks, 256>>>(hcur, ei, aggr);
        gemm_kernel<<<gemm_blocks, 256, 65536>>>(
            hcur, aggr, W1 + i * DIM * DIM, b1 + i * DIM,
            gamma + i * DIM, beta + i * DIM, rmean + i * DIM, rvar + i * DIM,
            nullptr, nullptr, 0, z, /*mode=*/0);
        gemm_kernel<<<gemm_blocks, 256, 65536>>>(
            z, nullptr, W2 + i * DIM * DIM, b2 + i * DIM,
            nullptr, nullptr, nullptr, nullptr,
            batch, pooled, i * DIM, h, /*mode=*/1);
        hcur = h;
    }

    fin1_kernel<<<N_GRAPHS, DCAT>>>(pooled, Wfin, bfin, hfin);
    fin2_kernel<<<N_GRAPHS, 32>>>(hfin, Wout, bout, out, out_size);
}

// round 3
// speedup vs baseline: 1.7454x; 1.7454x over previous
#include <cuda_runtime.h>
#include <math.h>

#define N_NODES  100000
#define N_EDGES  3200000
#define N_GRAPHS 512
#define DIM      128
#define NLAYERS  3
#define DCAT     384
#define NCLS     10
#define BN_EPS   1e-5f

// Scratch (device globals; no allocations allowed)
__device__ float g_aggr[N_NODES * DIM];
__device__ float g_z[N_NODES * DIM];
__device__ float g_h[N_NODES * DIM];
__device__ float g_pooled[N_GRAPHS * DCAT];
__device__ float g_hfin[N_GRAPHS * DCAT];
// CSR scratch
__device__ int g_counts[N_NODES + 4];
__device__ int g_rowstart[N_NODES + 4];
__device__ int g_cursor[N_NODES + 4];
__device__ int g_col[N_EDGES];

__global__ void zero_kernel(float4* __restrict__ p, int n4) {
    int i = blockIdx.x * blockDim.x + threadIdx.x;
    int stride = gridDim.x * blockDim.x;
    float4 z = make_float4(0.f, 0.f, 0.f, 0.f);
    for (; i < n4; i += stride) p[i] = z;
}

__global__ void zero_int_kernel(int* __restrict__ p, int n) {
    int i = blockIdx.x * blockDim.x + threadIdx.x;
    if (i < n) p[i] = 0;
}

// ---------------- CSR build (counting sort of edges by dst) ----------------
__global__ void hist_kernel(const int* __restrict__ ei, int* __restrict__ counts) {
    int e = blockIdx.x * blockDim.x + threadIdx.x;
    if (e < N_EDGES) atomicAdd(&counts[__ldg(&ei[N_EDGES + e])], 1);
}

// Single block, 1024 threads: exclusive scan of counts -> rowstart, cursor.
__global__ void __launch_bounds__(1024) scan_kernel(
        const int* __restrict__ counts,
        int* __restrict__ rowstart, int* __restrict__ cursor) {
    __shared__ int s[1024];
    const int CHUNK = (N_NODES + 1023) / 1024;   // 98
    int t = threadIdx.x;
    int lo = t * CHUNK;
    int hi = min(lo + CHUNK, N_NODES);
    int part = 0;
    for (int i = lo; i < hi; i++) part += counts[i];
    s[t] = part;
    __syncthreads();
    // Kogge-Stone inclusive scan
    for (int off = 1; off < 1024; off <<= 1) {
        int v = (t >= off) ? s[t - off] : 0;
        __syncthreads();
        s[t] += v;
        __syncthreads();
    }
    int run = s[t] - part;   // exclusive prefix for this chunk
    for (int i = lo; i < hi; i++) {
        rowstart[i] = run;
        cursor[i] = run;
        run += counts[i];
    }
    if (hi == N_NODES && lo < N_NODES) rowstart[N_NODES] = run;
}

__global__ void fill_kernel(const int* __restrict__ ei,
                            int* __restrict__ cursor, int* __restrict__ col) {
    int e = blockIdx.x * blockDim.x + threadIdx.x;
    if (e >= N_EDGES) return;
    int s = __ldg(&ei[e]);
    int d = __ldg(&ei[N_EDGES + e]);
    int pos = atomicAdd(&cursor[d], 1);
    col[pos] = s;
}

// ---------------- Gather: aggr[n] = h[n] + sum_{s in N(n)} h[s] -----------
// One warp per node, float4 per lane (128 floats/row).
__global__ void __launch_bounds__(256) gather_kernel(
        const float* __restrict__ h,
        const int* __restrict__ rowstart, const int* __restrict__ col,
        float* __restrict__ aggr) {
    unsigned n = (blockIdx.x * 256u + threadIdx.x) >> 5;
    int lane = threadIdx.x & 31;
    if (n >= N_NODES) return;
    int beg = __ldg(&rowstart[n]);
    int end = __ldg(&rowstart[n + 1]);
    float4 acc = __ldg((const float4*)(h + (long long)n * DIM) + lane);
    int i = beg;
    for (; i + 4 <= end; i += 4) {
        int s0 = __ldg(&col[i]);
        int s1 = __ldg(&col[i + 1]);
        int s2 = __ldg(&col[i + 2]);
        int s3 = __ldg(&col[i + 3]);
        float4 v0 = __ldg((const float4*)(h + (long long)s0 * DIM) + lane);
        float4 v1 = __ldg((const float4*)(h + (long long)s1 * DIM) + lane);
        float4 v2 = __ldg((const float4*)(h + (long long)s2 * DIM) + lane);
        float4 v3 = __ldg((const float4*)(h + (long long)s3 * DIM) + lane);
        acc.x += v0.x; acc.y += v0.y; acc.z += v0.z; acc.w += v0.w;
        acc.x += v1.x; acc.y += v1.y; acc.z += v1.z; acc.w += v1.w;
        acc.x += v2.x; acc.y += v2.y; acc.z += v2.z; acc.w += v2.w;
        acc.x += v3.x; acc.y += v3.y; acc.z += v3.z; acc.w += v3.w;
    }
    for (; i < end; i++) {
        int s = __ldg(&col[i]);
        float4 v = __ldg((const float4*)(h + (long long)s * DIM) + lane);
        acc.x += v.x; acc.y += v.y; acc.z += v.z; acc.w += v.w;
    }
    ((float4*)(aggr + (long long)n * DIM))[lane] = acc;
}

// ---------------- Fused GEMM: out = epilogue(A @ W + bias) ----------------
// 128x128 tile, 256 threads, 8x8 per thread. A transposed in smem, swizzled
// at 4-row granularity: As[k][row ^ (((k>>2)&7)<<2)] -> LDS.128 loads.
// mode 0: BN(eval)+ReLU; mode 1: ReLU + atomic pool into pooled.
__global__ void __launch_bounds__(256, 2) gemm_kernel(
        const float* __restrict__ A,
        const float* __restrict__ W, const float* __restrict__ bias,
        const float* __restrict__ gamma, const float* __restrict__ beta,
        const float* __restrict__ rmean, const float* __restrict__ rvar,
        const int* __restrict__ batch, float* __restrict__ pooled, int pool_off,
        float* __restrict__ outp, int mode) {
    extern __shared__ float As[];   // 128*128 floats = 64KB
    __shared__ int sb[128];
    int tid = threadIdx.x;
    int row0 = blockIdx.x * 128;

#pragma unroll
    for (int it = 0; it < 16; it++) {
        int i = tid + it * 256;
        int r = i >> 5;           // row within tile
        int c4 = i & 31;          // float4 index along k (= k>>2)
        int row = row0 + r;
        float4 v = make_float4(0.f, 0.f, 0.f, 0.f);
        if (row < N_NODES)
            v = __ldg((const float4*)(A + (long long)row * DIM) + c4);
        int k = c4 * 4;
        int rs = r ^ ((c4 & 7) << 2);      // 4-row-granular swizzle
        As[(k + 0) * DIM + rs] = v.x;
        As[(k + 1) * DIM + rs] = v.y;
        As[(k + 2) * DIM + rs] = v.z;
        As[(k + 3) * DIM + rs] = v.w;
    }
    if (mode == 1 && tid < 128) {
        int row = row0 + tid;
        sb[tid] = (row < N_NODES) ? __ldg(&batch[row]) : 0;
    }
    __syncthreads();

    int tr = tid >> 4;   // rows tr*8 .. tr*8+7
    int tc = tid & 15;   // cols tc*8 .. tc*8+7
    float acc[8][8];
#pragma unroll
    for (int a = 0; a < 8; a++)
#pragma unroll
        for (int b = 0; b < 8; b++) acc[a][b] = 0.f;

    const float4* Wv = (const float4*)W;
#pragma unroll 4
    for (int k = 0; k < 128; k++) {
        float4 w0 = __ldg(Wv + k * 32 + tc * 2);
        float4 w1 = __ldg(Wv + k * 32 + tc * 2 + 1);
        int xr = ((k >> 2) & 7) << 2;
        float4 alo = *(const float4*)&As[k * DIM + ((tr * 8) ^ xr)];
        float4 ahi = *(const float4*)&As[k * DIM + ((tr * 8 + 4) ^ xr)];
        float a[8] = {alo.x, alo.y, alo.z, alo.w, ahi.x, ahi.y, ahi.z, ahi.w};
#pragma unroll
        for (int rr = 0; rr < 8; rr++) {
            acc[rr][0] += a[rr] * w0.x; acc[rr][1] += a[rr] * w0.y;
            acc[rr][2] += a[rr] * w0.z; acc[rr][3] += a[rr] * w0.w;
            acc[rr][4] += a[rr] * w1.x; acc[rr][5] += a[rr] * w1.y;
            acc[rr][6] += a[rr] * w1.z; acc[rr][7] += a[rr] * w1.w;
        }
    }

    int col = tc * 8;
    float4 bi0 = __ldg((const float4*)(bias + col));
    float4 bi1 = __ldg((const float4*)(bias + col) + 1);
    float bb[8] = {bi0.x, bi0.y, bi0.z, bi0.w, bi1.x, bi1.y, bi1.z, bi1.w};

    float sc[8], sh[8];
    if (mode == 0) {
        float4 g0 = __ldg((const float4*)(gamma + col));
        float4 g1 = __ldg((const float4*)(gamma + col) + 1);
        float4 be0 = __ldg((const float4*)(beta + col));
        float4 be1 = __ldg((const float4*)(beta + col) + 1);
        float4 rm0 = __ldg((const float4*)(rmean + col));
        float4 rm1 = __ldg((const float4*)(rmean + col) + 1);
        float4 rv0 = __ldg((const float4*)(rvar + col));
        float4 rv1 = __ldg((const float4*)(rvar + col) + 1);
        float gg[8] = {g0.x, g0.y, g0.z, g0.w, g1.x, g1.y, g1.z, g1.w};
        float bt[8] = {be0.x, be0.y, be0.z, be0.w, be1.x, be1.y, be1.z, be1.w};
        float rm[8] = {rm0.x, rm0.y, rm0.z, rm0.w, rm1.x, rm1.y, rm1.z, rm1.w};
        float rv[8] = {rv0.x, rv0.y, rv0.z, rv0.w, rv1.x, rv1.y, rv1.z, rv1.w};
#pragma unroll
        for (int cc = 0; cc < 8; cc++) {
            sc[cc] = gg[cc] * rsqrtf(rv[cc] + BN_EPS);
            sh[cc] = bt[cc] - rm[cc] * sc[cc];
        }
    }

#pragma unroll
    for (int rr = 0; rr < 8; rr++) {
        int row = row0 + tr * 8 + rr;
        if (row >= N_NODES) continue;
        float v[8];
#pragma unroll
        for (int cc = 0; cc < 8; cc++) {
            float y = acc[rr][cc] + bb[cc];
            if (mode == 0) y = sc[cc] * y + sh[cc];
            v[cc] = fmaxf(y, 0.f);
        }
        float4 o0 = make_float4(v[0], v[1], v[2], v[3]);
        float4 o1 = make_float4(v[4], v[5], v[6], v[7]);
        float* op = outp + (long long)row * DIM + col;
        *(float4*)(op) = o0;
        *(float4*)(op + 4) = o1;
        if (mode == 1) {
            float* pb = pooled + sb[tr * 8 + rr] * DCAT + pool_off + col;
            asm volatile("red.global.add.v4.f32 [%0], {%1,%2,%3,%4};"
                         :: "l"(pb), "f"(o0.x), "f"(o0.y), "f"(o0.z), "f"(o0.w)
                         : "memory");
            asm volatile("red.global.add.v4.f32 [%0], {%1,%2,%3,%4};"
                         :: "l"(pb + 4), "f"(o1.x), "f"(o1.y), "f"(o1.z), "f"(o1.w)
                         : "memory");
        }
    }
}

// h_fin = relu(pooled @ Wfin + bfin): one block per graph, 384 threads.
__global__ void __launch_bounds__(DCAT) fin1_kernel(
        const float* __restrict__ pooled, const float* __restrict__ Wfin,
        const float* __restrict__ bfin, float* __restrict__ hfin) {
    __shared__ float s[DCAT];
    int g = blockIdx.x;
    int j = threadIdx.x;
    s[j] = pooled[g * DCAT + j];
    __syncthreads();
    float acc0 = 0.f, acc1 = 0.f, acc2 = 0.f, acc3 = 0.f;
#pragma unroll 4
    for (int k = 0; k < DCAT; k += 4) {
        acc0 += s[k + 0] * __ldg(&Wfin[(k + 0) * DCAT + j]);
        acc1 += s[k + 1] * __ldg(&Wfin[(k + 1) * DCAT + j]);
        acc2 += s[k + 2] * __ldg(&Wfin[(k + 2) * DCAT + j]);
        acc3 += s[k + 3] * __ldg(&Wfin[(k + 3) * DCAT + j]);
    }
    float acc = (acc0 + acc1) + (acc2 + acc3) + __ldg(&bfin[j]);
    hfin[g * DCAT + j] = fmaxf(acc, 0.f);
}

// logits + log_softmax: one warp per graph.
__global__ void __launch_bounds__(32) fin2_kernel(
        const float* __restrict__ hfin, const float* __restrict__ Wout,
        const float* __restrict__ bout, float* __restrict__ out, int out_size) {
    int g = blockIdx.x;
    int lane = threadIdx.x;
    bool valid = lane < NCLS;
    float acc = valid ? __ldg(&bout[lane]) : 0.f;
    for (int k = 0; k < DCAT; k++) {
        float v = __ldg(&hfin[g * DCAT + k]);
        if (valid) acc += v * __ldg(&Wout[k * NCLS + lane]);
    }
    float logit = acc;
    float m = valid ? logit : -INFINITY;
#pragma unroll
    for (int off = 16; off > 0; off >>= 1)
        m = fmaxf(m, __shfl_xor_sync(0xFFFFFFFFu, m, off));
    float e = valid ? expf(logit - m) : 0.f;
#pragma unroll
    for (int off = 16; off > 0; off >>= 1)
        e += __shfl_xor_sync(0xFFFFFFFFu, e, off);
    float ls = logit - m - logf(e);
    if (valid) {
        out[g * NCLS + lane] = logit;
        if (out_size >= 2 * N_GRAPHS * NCLS)
            out[N_GRAPHS * NCLS + g * NCLS + lane] = ls;
    }
}

extern "C" void kernel_launch(void* const* d_in, const int* in_sizes, int n_in,
                              void* d_out, int out_size) {
    const float* x        = (const float*)d_in[0];
    const int*   ei       = (const int*)d_in[1];     // int32 (JAX x64 off)
    const int*   batch    = (const int*)d_in[2];     // int32

    int w = 3;
    if (n_in >= 4 && in_sizes[3] == 1) w = 4;

    const float* W1   = (const float*)d_in[w + 0];
    const float* b1   = (const float*)d_in[w + 1];
    const float* gamma= (const float*)d_in[w + 2];
    const float* beta = (const float*)d_in[w + 3];
    const float* rmean= (const float*)d_in[w + 4];
    const float* rvar = (const float*)d_in[w + 5];
    const float* W2   = (const float*)d_in[w + 6];
    const float* b2   = (const float*)d_in[w + 7];
    const float* Wfin = (const float*)d_in[w + 8];
    const float* bfin = (const float*)d_in[w + 9];
    const float* Wout = (const float*)d_in[w + 10];
    const float* bout = (const float*)d_in[w + 11];
    float* out = (float*)d_out;

    float *aggr, *z, *h, *pooled, *hfin;
    int *counts, *rowstart, *cursor, *colbuf;
    cudaGetSymbolAddress((void**)&aggr,     g_aggr);
    cudaGetSymbolAddress((void**)&z,        g_z);
    cudaGetSymbolAddress((void**)&h,        g_h);
    cudaGetSymbolAddress((void**)&pooled,   g_pooled);
    cudaGetSymbolAddress((void**)&hfin,     g_hfin);
    cudaGetSymbolAddress((void**)&counts,   g_counts);
    cudaGetSymbolAddress((void**)&rowstart, g_rowstart);
    cudaGetSymbolAddress((void**)&cursor,   g_cursor);
    cudaGetSymbolAddress((void**)&colbuf,   g_col);

    cudaFuncSetAttribute(gemm_kernel,
                         cudaFuncAttributeMaxDynamicSharedMemorySize, 65536);

    const int EB = (N_EDGES + 255) / 256;               // 12500
    const int NB = (N_NODES * 32 + 255) / 256;          // warp per node: 12500
    const int gemm_blocks = (N_NODES + 127) / 128;      // 782

    // CSR build (once per call)
    zero_int_kernel<<<(N_NODES + 4 + 255) / 256, 256>>>(counts, N_NODES + 4);
    zero_kernel<<<192, 256>>>((float4*)pooled, N_GRAPHS * DCAT / 4);
    hist_kernel<<<EB, 256>>>(ei, counts);
    scan_kernel<<<1, 1024>>>(counts, rowstart, cursor);
    fill_kernel<<<EB, 256>>>(ei, cursor, colbuf);

    const float* hcur = x;
    for (int i = 0; i < NLAYERS; i++) {
        gather_kernel<<<NB, 256>>>(hcur, rowstart, colbuf, aggr);
        gemm_kernel<<<gemm_blocks, 256, 65536>>>(
            aggr, W1 + i * DIM * DIM, b1 + i * DIM,
            gamma + i * DIM, beta + i * DIM, rmean + i * DIM, rvar + i * DIM,
            nullptr, nullptr, 0, z, /*mode=*/0);
        gemm_kernel<<<gemm_blocks, 256, 65536>>>(
            z, W2 + i * DIM * DIM, b2 + i * DIM,
            nullptr, nullptr, nullptr, nullptr,
            batch, pooled, i * DIM, h, /*mode=*/1);
        hcur = h;
    }

    fin1_kernel<<<N_GRAPHS, DCAT>>>(pooled, Wfin, bfin, hfin);
    fin2_kernel<<<N_GRAPHS, 32>>>(hfin, Wout, bout, out, out_size);
}

// round 4
// speedup vs baseline: 2.1749x; 1.2460x over previous
#include <cuda_runtime.h>
#include <math.h>

#define N_NODES  100000
#define N_EDGES  3200000
#define N_GRAPHS 512
#define DIM      128
#define NLAYERS  3
#define DCAT     384
#define NCLS     10
#define BN_EPS   1e-5f

#define M_TILES  6252           // ceil(100000/16) -> 100032 padded rows
#define SCAN_NB  98             // ceil(100000/1024)

// Scratch (device globals; no allocations allowed)
__device__ float g_aggr[N_NODES * DIM];
__device__ float g_z[N_NODES * DIM];
__device__ float g_h[N_NODES * DIM];
__device__ float g_pooled[N_GRAPHS * DCAT];
__device__ float g_hfin[N_GRAPHS * DCAT];
// CSR scratch
__device__ int g_counts[N_NODES + 4];
__device__ int g_rowstart[N_NODES + 4];
__device__ int g_cursor[N_NODES + 4];
__device__ int g_col[N_EDGES];
__device__ int g_bsum[SCAN_NB + 4];
// tf32 weight fragments: [l2(6)][w(16)][kt(16)][lane(32)][j(2)]
#define BFRAG_PER_L2 (16 * 16 * 32 * 2)
__device__ float g_bhi[6 * BFRAG_PER_L2];
__device__ float g_blo[6 * BFRAG_PER_L2];

__device__ __forceinline__ float tf32r(float x) {
    unsigned u;
    asm("cvt.rna.tf32.f32 %0, %1;" : "=r"(u) : "f"(x));
    return __uint_as_float(u);
}

__global__ void zero_kernel(float4* __restrict__ p, int n4) {
    int i = blockIdx.x * blockDim.x + threadIdx.x;
    int stride = gridDim.x * blockDim.x;
    float4 z = make_float4(0.f, 0.f, 0.f, 0.f);
    for (; i < n4; i += stride) p[i] = z;
}

__global__ void zero_int_kernel(int* __restrict__ p, int n) {
    int i = blockIdx.x * blockDim.x + threadIdx.x;
    if (i < n) p[i] = 0;
}

// ---------------- CSR build (counting sort of edges by dst) ----------------
__global__ void hist_kernel(const int* __restrict__ ei, int* __restrict__ counts) {
    int e = blockIdx.x * blockDim.x + threadIdx.x;
    if (e < N_EDGES) atomicAdd(&counts[__ldg(&ei[N_EDGES + e])], 1);
}

// Phase 1: per-block exclusive scan (1024 elems/block), block total -> bsum.
__global__ void __launch_bounds__(1024) scan1_kernel(
        const int* __restrict__ counts, int* __restrict__ rowstart,
        int* __restrict__ bsum) {
    __shared__ int wsum[32];
    int t = threadIdx.x;
    int i = blockIdx.x * 1024 + t;
    int c = (i < N_NODES) ? __ldg(&counts[i]) : 0;
    int v = c;
#pragma unroll
    for (int off = 1; off < 32; off <<= 1) {
        int u = __shfl_up_sync(0xFFFFFFFFu, v, off);
        if ((t & 31) >= off) v += u;
    }
    if ((t & 31) == 31) wsum[t >> 5] = v;
    __syncthreads();
    if (t < 32) {
        int w = wsum[t];
#pragma unroll
        for (int off = 1; off < 32; off <<= 1) {
            int u = __shfl_up_sync(0xFFFFFFFFu, w, off);
            if (t >= off) w += u;
        }
        wsum[t] = w;
    }
    __syncthreads();
    int excl = v - c + ((t >= 32) ? wsum[(t >> 5) - 1] : 0);
    if (i < N_NODES) rowstart[i] = excl;
    if (t == 1023) bsum[blockIdx.x] = excl + c;
}

// Phase 2: exclusive scan of SCAN_NB block sums (1 warp; 4 elems/thread).
__global__ void __launch_bounds__(32) scan2_kernel(int* __restrict__ bsum) {
    int t = threadIdx.x;
    int v[4];
    int part = 0;
#pragma unroll
    for (int j = 0; j < 4; j++) {
        int idx = t * 4 + j;
        v[j] = (idx < SCAN_NB) ? bsum[idx] : 0;
        part += v[j];
    }
    int p = part;
#pragma unroll
    for (int off = 1; off < 32; off <<= 1) {
        int u = __shfl_up_sync(0xFFFFFFFFu, p, off);
        if (t >= off) p += u;
    }
    int run = p - part;
#pragma unroll
    for (int j = 0; j < 4; j++) {
        int idx = t * 4 + j;
        if (idx < SCAN_NB) bsum[idx] = run;
        run += v[j];
    }
}

// Phase 3: add block offsets, write cursor copy, set rowstart[N].
__global__ void __launch_bounds__(1024) scan3_kernel(
        const int* __restrict__ bsum, int* __restrict__ rowstart,
        int* __restrict__ cursor) {
    int i = blockIdx.x * 1024 + threadIdx.x;
    if (i < N_NODES) {
        int v = rowstart[i] + __ldg(&bsum[blockIdx.x]);
        rowstart[i] = v;
        cursor[i] = v;
    }
    if (i == 0) rowstart[N_NODES] = N_EDGES;
}

__global__ void fill_kernel(const int* __restrict__ ei,
                            int* __restrict__ cursor, int* __restrict__ col) {
    int e = blockIdx.x * blockDim.x + threadIdx.x;
    if (e >= N_EDGES) return;
    int s = __ldg(&ei[e]);
    int d = __ldg(&ei[N_EDGES + e]);
    int pos = atomicAdd(&cursor[d], 1);
    col[pos] = s;
}

// ---------------- Weight fragment precompute (tf32 hi/lo split) ------------
// b_j(kt,lane): k = kt*8 + tg + 4j, n = w*8 + g  (g=lane>>2, tg=lane&3)
__global__ void bfrag_kernel(const float* __restrict__ W1,
                             const float* __restrict__ W2,
                             float* __restrict__ bhi, float* __restrict__ blo) {
    int idx = blockIdx.x * blockDim.x + threadIdx.x;
    if (idx >= 6 * BFRAG_PER_L2) return;
    int j    = idx & 1;
    int lane = (idx >> 1) & 31;
    int kt   = (idx >> 6) & 15;
    int w    = (idx >> 10) & 15;
    int l2   = idx >> 14;
    int g = lane >> 2, tg = lane & 3;
    int k = kt * 8 + tg + 4 * j;
    int n = w * 8 + g;
    const float* Wm = (l2 & 1) ? (W2 + (l2 >> 1) * DIM * DIM)
                               : (W1 + (l2 >> 1) * DIM * DIM);
    float v = __ldg(&Wm[k * DIM + n]);
    float hi = tf32r(v);
    float lo = tf32r(v - hi);
    bhi[idx] = hi;
    blo[idx] = lo;
}

// ---------------- Gather: aggr[n] = h[n] + sum_{s in N(n)} h[s] -----------
__global__ void __launch_bounds__(256) gather_kernel(
        const float* __restrict__ h,
        const int* __restrict__ rowstart, const int* __restrict__ col,
        float* __restrict__ aggr) {
    unsigned n = (blockIdx.x * 256u + threadIdx.x) >> 5;
    int lane = threadIdx.x & 31;
    if (n >= N_NODES) return;
    int beg = __ldg(&rowstart[n]);
    int end = __ldg(&rowstart[n + 1]);
    float4 acc = __ldg((const float4*)(h + (long long)n * DIM) + lane);
    int i = beg;
    for (; i + 4 <= end; i += 4) {
        int s0 = __ldg(&col[i]);
        int s1 = __ldg(&col[i + 1]);
        int s2 = __ldg(&col[i + 2]);
        int s3 = __ldg(&col[i + 3]);
        float4 v0 = __ldg((const float4*)(h + (long long)s0 * DIM) + lane);
        float4 v1 = __ldg((const float4*)(h + (long long)s1 * DIM) + lane);
        float4 v2 = __ldg((const float4*)(h + (long long)s2 * DIM) + lane);
        float4 v3 = __ldg((const float4*)(h + (long long)s3 * DIM) + lane);
        acc.x += v0.x; acc.y += v0.y; acc.z += v0.z; acc.w += v0.w;
        acc.x += v1.x; acc.y += v1.y; acc.z += v1.z; acc.w += v1.w;
        acc.x += v2.x; acc.y += v2.y; acc.z += v2.z; acc.w += v2.w;
        acc.x += v3.x; acc.y += v3.y; acc.z += v3.z; acc.w += v3.w;
    }
    for (; i < end; i++) {
        int s = __ldg(&col[i]);
        float4 v = __ldg((const float4*)(h + (long long)s * DIM) + lane);
        acc.x += v.x; acc.y += v.y; acc.z += v.z; acc.w += v.w;
    }
    ((float4*)(aggr + (long long)n * DIM))[lane] = acc;
}

// ---------------- tf32 tensor-core GEMM, fused epilogue --------------------
// D[100032,128] = epi(A[.,128] @ W[128,128] + bias)  via split-precision tf32
// mma.m16n8k8. 512 threads = 16 warps; warp w owns n-tile [8w, 8w+8).
// Grid-stride over 6252 m-tiles of 16 rows. W fragments (hi/lo) live in
// registers for the whole kernel. A staged per tile in double-buffered smem,
// permuted so (tg, tg+4) frag pairs are lds.64-contiguous.
// mode 0: BN(eval)+ReLU -> out.  mode 1: ReLU -> out + atomic pool.
#define MMA_TF32(C, A0, A1, A2, A3, B0, B1)                                  \
    asm volatile("mma.sync.aligned.m16n8k8.row.col.f32.tf32.tf32.f32 "       \
                 "{%0,%1,%2,%3}, {%4,%5,%6,%7}, {%8,%9}, {%0,%1,%2,%3};"     \
                 : "+f"(C[0]), "+f"(C[1]), "+f"(C[2]), "+f"(C[3])            \
                 : "r"(A0), "r"(A1), "r"(A2), "r"(A3), "r"(B0), "r"(B1))

#define AS_STRIDE 136

__global__ void __launch_bounds__(512, 1) gemm_tf32_kernel(
        const float* __restrict__ A,
        const float* __restrict__ bhi_l2, const float* __restrict__ blo_l2,
        const float* __restrict__ bias,
        const float* __restrict__ gamma, const float* __restrict__ beta,
        const float* __restrict__ rmean, const float* __restrict__ rvar,
        const int* __restrict__ batch, float* __restrict__ pooled, int pool_off,
        float* __restrict__ outp, int mode) {
    __shared__ float Ah[2][16 * AS_STRIDE];
    __shared__ float Al[2][16 * AS_STRIDE];

    int tid = threadIdx.x;
    int wid = tid >> 5;
    int lane = tid & 31;
    int g = lane >> 2, tg = lane & 3;

    // --- load W fragments for this warp's n-tile (held in regs) ---
    unsigned bh[16][2], bl[16][2];
    {
        const float2* bp = (const float2*)bhi_l2 + (wid * 16 * 32 + lane);
        const float2* lp = (const float2*)blo_l2 + (wid * 16 * 32 + lane);
#pragma unroll
        for (int kt = 0; kt < 16; kt++) {
            float2 fh = __ldg(bp + kt * 32);
            float2 fl = __ldg(lp + kt * 32);
            bh[kt][0] = __float_as_uint(fh.x);
            bh[kt][1] = __float_as_uint(fh.y);
            bl[kt][0] = __float_as_uint(fl.x);
            bl[kt][1] = __float_as_uint(fl.y);
        }
    }

    // --- per-thread epilogue constants (cols fixed for whole kernel) ---
    int col0 = wid * 8 + tg * 2;          // and col0+1
    float bb0 = __ldg(&bias[col0]), bb1 = __ldg(&bias[col0 + 1]);
    float sc0 = 1.f, sh0 = 0.f, sc1 = 1.f, sh1 = 0.f;
    if (mode == 0) {
        sc0 = __ldg(&gamma[col0]) * rsqrtf(__ldg(&rvar[col0]) + BN_EPS);
        sh0 = __ldg(&beta[col0]) - __ldg(&rmean[col0]) * sc0;
        sc1 = __ldg(&gamma[col0 + 1]) * rsqrtf(__ldg(&rvar[col0 + 1]) + BN_EPS);
        sh1 = __ldg(&beta[col0 + 1]) - __ldg(&rmean[col0 + 1]) * sc1;
    }

    // staging coords: one float4 per thread per tile
    int sr = tid >> 5;        // row within tile 0..15
    int sc4 = tid & 31;       // float4 index 0..31
    int skt = sc4 >> 1;
    int sodd = sc4 & 1;

    // prefetch first tile
    float4 v = make_float4(0.f, 0.f, 0.f, 0.f);
    {
        int row = blockIdx.x * 16 + sr;
        if (blockIdx.x < M_TILES && row < N_NODES)
            v = __ldg((const float4*)(A + (long long)row * DIM) + sc4);
    }

    int buf = 0;
    for (int mt = blockIdx.x; mt < M_TILES; mt += gridDim.x) {
        // stage current tile (cvt hi/lo + permuted store)
        {
            float* ah = Ah[buf];
            float* al = Al[buf];
            float vv[4] = {v.x, v.y, v.z, v.w};
#pragma unroll
            for (int j = 0; j < 4; j++) {
                float hi = tf32r(vv[j]);
                float lo = tf32r(vv[j] - hi);
                int slot = j * 2 + sodd;
                ah[sr * AS_STRIDE + skt * 8 + slot] = hi;
                al[sr * AS_STRIDE + skt * 8 + slot] = lo;
            }
        }
        __syncthreads();

        // prefetch next tile
        int mtn = mt + gridDim.x;
        if (mtn < M_TILES) {
            int row = mtn * 16 + sr;
            v = (row < N_NODES)
                ? __ldg((const float4*)(A + (long long)row * DIM) + sc4)
                : make_float4(0.f, 0.f, 0.f, 0.f);
        }

        // compute
        float cm[4] = {0.f, 0.f, 0.f, 0.f};
        float cc[4] = {0.f, 0.f, 0.f, 0.f};
        const float* ah = Ah[buf];
        const float* al = Al[buf];
#pragma unroll
        for (int kt = 0; kt < 16; kt++) {
            float2 h02 = *(const float2*)&ah[g * AS_STRIDE + kt * 8 + tg * 2];
            float2 h13 = *(const float2*)&ah[(g + 8) * AS_STRIDE + kt * 8 + tg * 2];
            float2 l02 = *(const float2*)&al[g * AS_STRIDE + kt * 8 + tg * 2];
            float2 l13 = *(const float2*)&al[(g + 8) * AS_STRIDE + kt * 8 + tg * 2];
            unsigned a0 = __float_as_uint(h02.x), a1 = __float_as_uint(h13.x);
            unsigned a2 = __float_as_uint(h02.y), a3 = __float_as_uint(h13.y);
            unsigned e0 = __float_as_uint(l02.x), e1 = __float_as_uint(l13.x);
            unsigned e2 = __float_as_uint(l02.y), e3 = __float_as_uint(l13.y);
            MMA_TF32(cm, a0, a1, a2, a3, bh[kt][0], bh[kt][1]);
            MMA_TF32(cc, a0, a1, a2, a3, bl[kt][0], bl[kt][1]);
            MMA_TF32(cc, e0, e1, e2, e3, bh[kt][0], bh[kt][1]);
        }

        // epilogue: c0,c1 -> row g; c2,c3 -> row g+8 (cols col0, col0+1)
        int r0 = mt * 16 + g;
        int r1 = r0 + 8;
        float y00 = cm[0] + cc[0] + bb0;
        float y01 = cm[1] + cc[1] + bb1;
        float y10 = cm[2] + cc[2] + bb0;
        float y11 = cm[3] + cc[3] + bb1;
        if (mode == 0) {
            y00 = sc0 * y00 + sh0; y01 = sc1 * y01 + sh1;
            y10 = sc0 * y10 + sh0; y11 = sc1 * y11 + sh1;
        }
        y00 = fmaxf(y00, 0.f); y01 = fmaxf(y01, 0.f);
        y10 = fmaxf(y10, 0.f); y11 = fmaxf(y11, 0.f);

        if (r0 < N_NODES) {
            *(float2*)(outp + (long long)r0 * DIM + col0) = make_float2(y00, y01);
            if (mode == 1) {
                int b0 = __ldg(&batch[r0]);
                float* pb = pooled + b0 * DCAT + pool_off + col0;
                asm volatile("red.global.add.v2.f32 [%0], {%1,%2};"
                             :: "l"(pb), "f"(y00), "f"(y01) : "memory");
            }
        }
        if (r1 < N_NODES) {
            *(float2*)(outp + (long long)r1 * DIM + col0) = make_float2(y10, y11);
            if (mode == 1) {
                int b1i = __ldg(&batch[r1]);
                float* pb = pooled + b1i * DCAT + pool_off + col0;
                asm volatile("red.global.add.v2.f32 [%0], {%1,%2};"
                             :: "l"(pb), "f"(y10), "f"(y11) : "memory");
            }
        }
        buf ^= 1;
    }
}

// h_fin = relu(pooled @ Wfin + bfin): one block per graph, 384 threads.
__global__ void __launch_bounds__(DCAT) fin1_kernel(
        const float* __restrict__ pooled, const float* __restrict__ Wfin,
        const float* __restrict__ bfin, float* __restrict__ hfin) {
    __shared__ float s[DCAT];
    int g = blockIdx.x;
    int j = threadIdx.x;
    s[j] = pooled[g * DCAT + j];
    __syncthreads();
    float acc0 = 0.f, acc1 = 0.f, acc2 = 0.f, acc3 = 0.f;
#pragma unroll 4
    for (int k = 0; k < DCAT; k += 4) {
        acc0 += s[k + 0] * __ldg(&Wfin[(k + 0) * DCAT + j]);
        acc1 += s[k + 1] * __ldg(&Wfin[(k + 1) * DCAT + j]);
        acc2 += s[k + 2] * __ldg(&Wfin[(k + 2) * DCAT + j]);
        acc3 += s[k + 3] * __ldg(&Wfin[(k + 3) * DCAT + j]);
    }
    float acc = (acc0 + acc1) + (acc2 + acc3) + __ldg(&bfin[j]);
    hfin[g * DCAT + j] = fmaxf(acc, 0.f);
}

// logits + log_softmax: one warp per graph.
__global__ void __launch_bounds__(32) fin2_kernel(
        const float* __restrict__ hfin, const float* __restrict__ Wout,
        const float* __restrict__ bout, float* __restrict__ out, int out_size) {
    int g = blockIdx.x;
    int lane = threadIdx.x;
    bool valid = lane < NCLS;
    float acc = valid ? __ldg(&bout[lane]) : 0.f;
    for (int k = 0; k < DCAT; k++) {
        float v = __ldg(&hfin[g * DCAT + k]);
        if (valid) acc += v * __ldg(&Wout[k * NCLS + lane]);
    }
    float logit = acc;
    float m = valid ? logit : -INFINITY;
#pragma unroll
    for (int off = 16; off > 0; off >>= 1)
        m = fmaxf(m, __shfl_xor_sync(0xFFFFFFFFu, m, off));
    float e = valid ? expf(logit - m) : 0.f;
#pragma unroll
    for (int off = 16; off > 0; off >>= 1)
        e += __shfl_xor_sync(0xFFFFFFFFu, e, off);
    float ls = logit - m - logf(e);
    if (valid) {
        out[g * NCLS + lane] = logit;
        if (out_size >= 2 * N_GRAPHS * NCLS)
            out[N_GRAPHS * NCLS + g * NCLS + lane] = ls;
    }
}

extern "C" void kernel_launch(void* const* d_in, const int* in_sizes, int n_in,
                              void* d_out, int out_size) {
    const float* x        = (const float*)d_in[0];
    const int*   ei       = (const int*)d_in[1];     // int32 (JAX x64 off)
    const int*   batch    = (const int*)d_in[2];     // int32

    int w = 3;
    if (n_in >= 4 && in_sizes[3] == 1) w = 4;

    const float* W1   = (const float*)d_in[w + 0];
    const float* b1   = (const float*)d_in[w + 1];
    const float* gamma= (const float*)d_in[w + 2];
    const float* beta = (const float*)d_in[w + 3];
    const float* rmean= (const float*)d_in[w + 4];
    const float* rvar = (const float*)d_in[w + 5];
    const float* W2   = (const float*)d_in[w + 6];
    const float* b2   = (const float*)d_in[w + 7];
    const float* Wfin = (const float*)d_in[w + 8];
    const float* bfin = (const float*)d_in[w + 9];
    const float* Wout = (const float*)d_in[w + 10];
    const float* bout = (const float*)d_in[w + 11];
    float* out = (float*)d_out;

    float *aggr, *z, *h, *pooled, *hfin, *bhi, *blo;
    int *counts, *rowstart, *cursor, *colbuf, *bsum;
    cudaGetSymbolAddress((void**)&aggr,     g_aggr);
    cudaGetSymbolAddress((void**)&z,        g_z);
    cudaGetSymbolAddress((void**)&h,        g_h);
    cudaGetSymbolAddress((void**)&pooled,   g_pooled);
    cudaGetSymbolAddress((void**)&hfin,     g_hfin);
    cudaGetSymbolAddress((void**)&counts,   g_counts);
    cudaGetSymbolAddress((void**)&rowstart, g_rowstart);
    cudaGetSymbolAddress((void**)&cursor,   g_cursor);
    cudaGetSymbolAddress((void**)&colbuf,   g_col);
    cudaGetSymbolAddress((void**)&bsum,     g_bsum);
    cudaGetSymbolAddress((void**)&bhi,      g_bhi);
    cudaGetSymbolAddress((void**)&blo,      g_blo);

    const int EB = (N_EDGES + 255) / 256;               // 12500
    const int NB = (N_NODES * 32 + 255) / 256;          // warp per node: 12500

    // CSR build + weight fragment precompute (once per call)
    zero_int_kernel<<<(N_NODES + 4 + 255) / 256, 256>>>(counts, N_NODES + 4);
    zero_kernel<<<192, 256>>>((float4*)pooled, N_GRAPHS * DCAT / 4);
    hist_kernel<<<EB, 256>>>(ei, counts);
    scan1_kernel<<<SCAN_NB, 1024>>>(counts, rowstart, bsum);
    scan2_kernel<<<1, 32>>>(bsum);
    scan3_kernel<<<SCAN_NB, 1024>>>(bsum, rowstart, cursor);
    fill_kernel<<<EB, 256>>>(ei, cursor, colbuf);
    bfrag_kernel<<<(6 * BFRAG_PER_L2 + 255) / 256, 256>>>(W1, W2, bhi, blo);

    const float* hcur = x;
    for (int i = 0; i < NLAYERS; i++) {
        gather_kernel<<<NB, 256>>>(hcur, rowstart, colbuf, aggr);
        int l2a = i * 2, l2b = i * 2 + 1;
        gemm_tf32_kernel<<<148, 512>>>(
            aggr, bhi + l2a * BFRAG_PER_L2, blo + l2a * BFRAG_PER_L2,
            b1 + i * DIM,
            gamma + i * DIM, beta + i * DIM, rmean + i * DIM, rvar + i * DIM,
            nullptr, nullptr, 0, z, /*mode=*/0);
        gemm_tf32_kernel<<<148, 512>>>(
            z, bhi + l2b * BFRAG_PER_L2, blo + l2b * BFRAG_PER_L2,
            b2 + i * DIM,
            nullptr, nullptr, nullptr, nullptr,
            batch, pooled, i * DIM, h, /*mode=*/1);
        hcur = h;
    }

    fin1_kernel<<<N_GRAPHS, DCAT>>>(pooled, Wfin, bfin, hfin);
    fin2_kernel<<<N_GRAPHS, 32>>>(hfin, Wout, bout, out, out_size);
}

// round 5
// speedup vs baseline: 2.3338x; 1.0731x over previous
#include <cuda_runtime.h>
#include <cuda_fp16.h>
#include <math.h>

#define N_NODES  100000
#define N_EDGES  3200000
#define N_GRAPHS 512
#define DIM      128
#define NLAYERS  3
#define DCAT     384
#define NCLS     10
#define BN_EPS   1e-5f

#define M_TILES  6252           // ceil(100000/16)
#define SCAN_NB  98             // ceil(100000/1024)

// Scratch (device globals; no allocations allowed)
__device__ float g_aggr[N_NODES * DIM];
__device__ float g_z[N_NODES * DIM];
__device__ __half g_hh[N_NODES * DIM];     // fp16 shadow of h (gather input)
__device__ float g_pooled[N_GRAPHS * DCAT];
__device__ float g_hfin[N_GRAPHS * DCAT];
// CSR scratch
__device__ int g_counts[N_NODES + 4];
__device__ int g_rowstart[N_NODES + 4];
__device__ int g_cursor[N_NODES + 4];
__device__ int g_col[N_EDGES];
__device__ int g_bsum[SCAN_NB + 4];
// tf32 weight fragments: [l2(6)][w(16)][kt(16)][lane(32)][j(2)]
#define BFRAG_PER_L2 (16 * 16 * 32 * 2)
__device__ float g_bhi[6 * BFRAG_PER_L2];
__device__ float g_blo[6 * BFRAG_PER_L2];

__device__ __forceinline__ float tf32r(float x) {
    unsigned u;
    asm("cvt.rna.tf32.f32 %0, %1;" : "=r"(u) : "f"(x));
    return __uint_as_float(u);
}

__global__ void zero_kernel(float4* __restrict__ p, int n4) {
    int i = blockIdx.x * blockDim.x + threadIdx.x;
    int stride = gridDim.x * blockDim.x;
    float4 z = make_float4(0.f, 0.f, 0.f, 0.f);
    for (; i < n4; i += stride) p[i] = z;
}

__global__ void zero_int_kernel(int* __restrict__ p, int n) {
    int i = blockIdx.x * blockDim.x + threadIdx.x;
    if (i < n) p[i] = 0;
}

// Convert x (fp32) -> fp16 shadow. One thread per half2.
__global__ void x2h_kernel(const float2* __restrict__ x, __half2* __restrict__ hh) {
    int i = blockIdx.x * blockDim.x + threadIdx.x;
    if (i < N_NODES * DIM / 2) hh[i] = __float22half2_rn(__ldg(&x[i]));
}

// ---------------- CSR build (counting sort of edges by dst) ----------------
__global__ void hist_kernel(const int* __restrict__ ei, int* __restrict__ counts) {
    int e = blockIdx.x * blockDim.x + threadIdx.x;
    if (e < N_EDGES) atomicAdd(&counts[__ldg(&ei[N_EDGES + e])], 1);
}

__global__ void __launch_bounds__(1024) scan1_kernel(
        const int* __restrict__ counts, int* __restrict__ rowstart,
        int* __restrict__ bsum) {
    __shared__ int wsum[32];
    int t = threadIdx.x;
    int i = blockIdx.x * 1024 + t;
    int c = (i < N_NODES) ? __ldg(&counts[i]) : 0;
    int v = c;
#pragma unroll
    for (int off = 1; off < 32; off <<= 1) {
        int u = __shfl_up_sync(0xFFFFFFFFu, v, off);
        if ((t & 31) >= off) v += u;
    }
    if ((t & 31) == 31) wsum[t >> 5] = v;
    __syncthreads();
    if (t < 32) {
        int w = wsum[t];
#pragma unroll
        for (int off = 1; off < 32; off <<= 1) {
            int u = __shfl_up_sync(0xFFFFFFFFu, w, off);
            if (t >= off) w += u;
        }
        wsum[t] = w;
    }
    __syncthreads();
    int excl = v - c + ((t >= 32) ? wsum[(t >> 5) - 1] : 0);
    if (i < N_NODES) rowstart[i] = excl;
    if (t == 1023) bsum[blockIdx.x] = excl + c;
}

__global__ void __launch_bounds__(32) scan2_kernel(int* __restrict__ bsum) {
    int t = threadIdx.x;
    int v[4];
    int part = 0;
#pragma unroll
    for (int j = 0; j < 4; j++) {
        int idx = t * 4 + j;
        v[j] = (idx < SCAN_NB) ? bsum[idx] : 0;
        part += v[j];
    }
    int p = part;
#pragma unroll
    for (int off = 1; off < 32; off <<= 1) {
        int u = __shfl_up_sync(0xFFFFFFFFu, p, off);
        if (t >= off) p += u;
    }
    int run = p - part;
#pragma unroll
    for (int j = 0; j < 4; j++) {
        int idx = t * 4 + j;
        if (idx < SCAN_NB) bsum[idx] = run;
        run += v[j];
    }
}

__global__ void __launch_bounds__(1024) scan3_kernel(
        const int* __restrict__ bsum, int* __restrict__ rowstart,
        int* __restrict__ cursor) {
    int i = blockIdx.x * 1024 + threadIdx.x;
    if (i < N_NODES) {
        int v = rowstart[i] + __ldg(&bsum[blockIdx.x]);
        rowstart[i] = v;
        cursor[i] = v;
    }
    if (i == 0) rowstart[N_NODES] = N_EDGES;
}

__global__ void fill_kernel(const int* __restrict__ ei,
                            int* __restrict__ cursor, int* __restrict__ col) {
    int e = blockIdx.x * blockDim.x + threadIdx.x;
    if (e >= N_EDGES) return;
    int s = __ldg(&ei[e]);
    int d = __ldg(&ei[N_EDGES + e]);
    int pos = atomicAdd(&cursor[d], 1);
    col[pos] = s;
}

// ---------------- Weight fragment precompute (tf32 hi/lo split) ------------
__global__ void bfrag_kernel(const float* __restrict__ W1,
                             const float* __restrict__ W2,
                             float* __restrict__ bhi, float* __restrict__ blo) {
    int idx = blockIdx.x * blockDim.x + threadIdx.x;
    if (idx >= 6 * BFRAG_PER_L2) return;
    int j    = idx & 1;
    int lane = (idx >> 1) & 31;
    int kt   = (idx >> 6) & 15;
    int w    = (idx >> 10) & 15;
    int l2   = idx >> 14;
    int g = lane >> 2, tg = lane & 3;
    int k = kt * 8 + tg + 4 * j;
    int n = w * 8 + g;
    const float* Wm = (l2 & 1) ? (W2 + (l2 >> 1) * DIM * DIM)
                               : (W1 + (l2 >> 1) * DIM * DIM);
    float v = __ldg(&Wm[k * DIM + n]);
    float hi = tf32r(v);
    float lo = tf32r(v - hi);
    bhi[idx] = hi;
    blo[idx] = lo;
}

// ---------------- Gather (fp16 rows): aggr[n] = h[n] + sum h[s] ------------
// One warp per node; each lane owns 4 halfs (8B load per row), fp32 accum.
__global__ void __launch_bounds__(256) gather_kernel(
        const __half* __restrict__ hh,
        const int* __restrict__ rowstart, const int* __restrict__ col,
        float* __restrict__ aggr) {
    unsigned n = (blockIdx.x * 256u + threadIdx.x) >> 5;
    int lane = threadIdx.x & 31;
    if (n >= N_NODES) return;
    int beg = __ldg(&rowstart[n]);
    int end = __ldg(&rowstart[n + 1]);
    const uint2* base = (const uint2*)hh;   // 8B per lane; 32 lanes = 256B row
    float4 acc;
    {
        uint2 r = __ldg(base + n * 16 + lane / 2 * 2 + (lane & 1));
        // simpler: row has 16 uint2? No: 128 halfs = 256B = 32 x 8B
    }
    // row = 32 uint2 chunks
    {
        uint2 r = __ldg((const uint2*)(hh + (long long)n * DIM) + lane);
        float2 f0 = __half22float2(*(__half2*)&r.x);
        float2 f1 = __half22float2(*(__half2*)&r.y);
        acc = make_float4(f0.x, f0.y, f1.x, f1.y);
    }
    int i = beg;
    for (; i + 4 <= end; i += 4) {
        int s0 = __ldg(&col[i]);
        int s1 = __ldg(&col[i + 1]);
        int s2 = __ldg(&col[i + 2]);
        int s3 = __ldg(&col[i + 3]);
        uint2 r0 = __ldg((const uint2*)(hh + (long long)s0 * DIM) + lane);
        uint2 r1 = __ldg((const uint2*)(hh + (long long)s1 * DIM) + lane);
        uint2 r2 = __ldg((const uint2*)(hh + (long long)s2 * DIM) + lane);
        uint2 r3 = __ldg((const uint2*)(hh + (long long)s3 * DIM) + lane);
        float2 a0 = __half22float2(*(__half2*)&r0.x);
        float2 a1 = __half22float2(*(__half2*)&r0.y);
        acc.x += a0.x; acc.y += a0.y; acc.z += a1.x; acc.w += a1.y;
        float2 b0 = __half22float2(*(__half2*)&r1.x);
        float2 b1 = __half22float2(*(__half2*)&r1.y);
        acc.x += b0.x; acc.y += b0.y; acc.z += b1.x; acc.w += b1.y;
        float2 c0 = __half22float2(*(__half2*)&r2.x);
        float2 c1 = __half22float2(*(__half2*)&r2.y);
        acc.x += c0.x; acc.y += c0.y; acc.z += c1.x; acc.w += c1.y;
        float2 d0 = __half22float2(*(__half2*)&r3.x);
        float2 d1 = __half22float2(*(__half2*)&r3.y);
        acc.x += d0.x; acc.y += d0.y; acc.z += d1.x; acc.w += d1.y;
    }
    for (; i < end; i++) {
        int s = __ldg(&col[i]);
        uint2 r = __ldg((const uint2*)(hh + (long long)s * DIM) + lane);
        float2 f0 = __half22float2(*(__half2*)&r.x);
        float2 f1 = __half22float2(*(__half2*)&r.y);
        acc.x += f0.x; acc.y += f0.y; acc.z += f1.x; acc.w += f1.y;
    }
    ((float4*)(aggr + (long long)n * DIM))[lane] = acc;
}

// ---------------- tf32 tensor-core GEMM, fused epilogue --------------------
#define MMA_TF32(C, A0, A1, A2, A3, B0, B1)                                  \
    asm volatile("mma.sync.aligned.m16n8k8.row.col.f32.tf32.tf32.f32 "       \
                 "{%0,%1,%2,%3}, {%4,%5,%6,%7}, {%8,%9}, {%0,%1,%2,%3};"     \
                 : "+f"(C[0]), "+f"(C[1]), "+f"(C[2]), "+f"(C[3])            \
                 : "r"(A0), "r"(A1), "r"(A2), "r"(A3), "r"(B0), "r"(B1))

#define AS_STRIDE 136

// mode 0: BN(eval)+ReLU -> fp32 out (z).
// mode 1: ReLU -> fp16 out (h shadow) + atomic pool into pooled.
__global__ void __launch_bounds__(512, 1) gemm_tf32_kernel(
        const float* __restrict__ A,
        const float* __restrict__ bhi_l2, const float* __restrict__ blo_l2,
        const float* __restrict__ bias,
        const float* __restrict__ gamma, const float* __restrict__ beta,
        const float* __restrict__ rmean, const float* __restrict__ rvar,
        const int* __restrict__ batch, float* __restrict__ pooled, int pool_off,
        float* __restrict__ outf, __half* __restrict__ outh, int mode) {
    __shared__ float Ah[2][16 * AS_STRIDE];
    __shared__ float Al[2][16 * AS_STRIDE];

    int tid = threadIdx.x;
    int wid = tid >> 5;
    int lane = tid & 31;
    int g = lane >> 2, tg = lane & 3;

    unsigned bh[16][2], bl[16][2];
    {
        const float2* bp = (const float2*)bhi_l2 + (wid * 16 * 32 + lane);
        const float2* lp = (const float2*)blo_l2 + (wid * 16 * 32 + lane);
#pragma unroll
        for (int kt = 0; kt < 16; kt++) {
            float2 fh = __ldg(bp + kt * 32);
            float2 fl = __ldg(lp + kt * 32);
            bh[kt][0] = __float_as_uint(fh.x);
            bh[kt][1] = __float_as_uint(fh.y);
            bl[kt][0] = __float_as_uint(fl.x);
            bl[kt][1] = __float_as_uint(fl.y);
        }
    }

    int col0 = wid * 8 + tg * 2;
    float bb0 = __ldg(&bias[col0]), bb1 = __ldg(&bias[col0 + 1]);
    float sc0 = 1.f, sh0 = 0.f, sc1 = 1.f, sh1 = 0.f;
    if (mode == 0) {
        sc0 = __ldg(&gamma[col0]) * rsqrtf(__ldg(&rvar[col0]) + BN_EPS);
        sh0 = __ldg(&beta[col0]) - __ldg(&rmean[col0]) * sc0;
        sc1 = __ldg(&gamma[col0 + 1]) * rsqrtf(__ldg(&rvar[col0 + 1]) + BN_EPS);
        sh1 = __ldg(&beta[col0 + 1]) - __ldg(&rmean[col0 + 1]) * sc1;
    }

    int sr = tid >> 5;
    int sc4 = tid & 31;
    int skt = sc4 >> 1;
    int sodd = sc4 & 1;

    float4 v = make_float4(0.f, 0.f, 0.f, 0.f);
    {
        int row = blockIdx.x * 16 + sr;
        if (blockIdx.x < M_TILES && row < N_NODES)
            v = __ldg((const float4*)(A + (long long)row * DIM) + sc4);
    }

    int buf = 0;
    for (int mt = blockIdx.x; mt < M_TILES; mt += gridDim.x) {
        {
            float* ah = Ah[buf];
            float* al = Al[buf];
            float vv[4] = {v.x, v.y, v.z, v.w};
#pragma unroll
            for (int j = 0; j < 4; j++) {
                float hi = tf32r(vv[j]);
                float lo = tf32r(vv[j] - hi);
                int slot = j * 2 + sodd;
                ah[sr * AS_STRIDE + skt * 8 + slot] = hi;
                al[sr * AS_STRIDE + skt * 8 + slot] = lo;
            }
        }
        __syncthreads();

        int mtn = mt + gridDim.x;
        if (mtn < M_TILES) {
            int row = mtn * 16 + sr;
            v = (row < N_NODES)
                ? __ldg((const float4*)(A + (long long)row * DIM) + sc4)
                : make_float4(0.f, 0.f, 0.f, 0.f);
        }

        float cm[4] = {0.f, 0.f, 0.f, 0.f};
        float cc[4] = {0.f, 0.f, 0.f, 0.f};
        const float* ah = Ah[buf];
        const float* al = Al[buf];
#pragma unroll
        for (int kt = 0; kt < 16; kt++) {
            float2 h02 = *(const float2*)&ah[g * AS_STRIDE + kt * 8 + tg * 2];
            float2 h13 = *(const float2*)&ah[(g + 8) * AS_STRIDE + kt * 8 + tg * 2];
            float2 l02 = *(const float2*)&al[g * AS_STRIDE + kt * 8 + tg * 2];
            float2 l13 = *(const float2*)&al[(g + 8) * AS_STRIDE + kt * 8 + tg * 2];
            unsigned a0 = __float_as_uint(h02.x), a1 = __float_as_uint(h13.x);
            unsigned a2 = __float_as_uint(h02.y), a3 = __float_as_uint(h13.y);
            unsigned e0 = __float_as_uint(l02.x), e1 = __float_as_uint(l13.x);
            unsigned e2 = __float_as_uint(l02.y), e3 = __float_as_uint(l13.y);
            MMA_TF32(cm, a0, a1, a2, a3, bh[kt][0], bh[kt][1]);
            MMA_TF32(cc, a0, a1, a2, a3, bl[kt][0], bl[kt][1]);
            MMA_TF32(cc, e0, e1, e2, e3, bh[kt][0], bh[kt][1]);
        }

        int r0 = mt * 16 + g;
        int r1 = r0 + 8;
        float y00 = cm[0] + cc[0] + bb0;
        float y01 = cm[1] + cc[1] + bb1;
        float y10 = cm[2] + cc[2] + bb0;
        float y11 = cm[3] + cc[3] + bb1;
        if (mode == 0) {
            y00 = sc0 * y00 + sh0; y01 = sc1 * y01 + sh1;
            y10 = sc0 * y10 + sh0; y11 = sc1 * y11 + sh1;
        }
        y00 = fmaxf(y00, 0.f); y01 = fmaxf(y01, 0.f);
        y10 = fmaxf(y10, 0.f); y11 = fmaxf(y11, 0.f);

        if (r0 < N_NODES) {
            if (mode == 0) {
                *(float2*)(outf + (long long)r0 * DIM + col0) = make_float2(y00, y01);
            } else {
                *(__half2*)(outh + (long long)r0 * DIM + col0) =
                    __float22half2_rn(make_float2(y00, y01));
                int b0 = __ldg(&batch[r0]);
                float* pb = pooled + b0 * DCAT + pool_off + col0;
                asm volatile("red.global.add.v2.f32 [%0], {%1,%2};"
                             :: "l"(pb), "f"(y00), "f"(y01) : "memory");
            }
        }
        if (r1 < N_NODES) {
            if (mode == 0) {
                *(float2*)(outf + (long long)r1 * DIM + col0) = make_float2(y10, y11);
            } else {
                *(__half2*)(outh + (long long)r1 * DIM + col0) =
                    __float22half2_rn(make_float2(y10, y11));
                int b1i = __ldg(&batch[r1]);
                float* pb = pooled + b1i * DCAT + pool_off + col0;
                asm volatile("red.global.add.v2.f32 [%0], {%1,%2};"
                             :: "l"(pb), "f"(y10), "f"(y11) : "memory");
            }
        }
        buf ^= 1;
    }
}

// h_fin = relu(pooled @ Wfin + bfin)
__global__ void __launch_bounds__(DCAT) fin1_kernel(
        const float* __restrict__ pooled, const float* __restrict__ Wfin,
        const float* __restrict__ bfin, float* __restrict__ hfin) {
    __shared__ float s[DCAT];
    int g = blockIdx.x;
    int j = threadIdx.x;
    s[j] = pooled[g * DCAT + j];
    __syncthreads();
    float acc0 = 0.f, acc1 = 0.f, acc2 = 0.f, acc3 = 0.f;
#pragma unroll 4
    for (int k = 0; k < DCAT; k += 4) {
        acc0 += s[k + 0] * __ldg(&Wfin[(k + 0) * DCAT + j]);
        acc1 += s[k + 1] * __ldg(&Wfin[(k + 1) * DCAT + j]);
        acc2 += s[k + 2] * __ldg(&Wfin[(k + 2) * DCAT + j]);
        acc3 += s[k + 3] * __ldg(&Wfin[(k + 3) * DCAT + j]);
    }
    float acc = (acc0 + acc1) + (acc2 + acc3) + __ldg(&bfin[j]);
    hfin[g * DCAT + j] = fmaxf(acc, 0.f);
}

// logits + log_softmax: one warp per graph.
__global__ void __launch_bounds__(32) fin2_kernel(
        const float* __restrict__ hfin, const float* __restrict__ Wout,
        const float* __restrict__ bout, float* __restrict__ out, int out_size) {
    int g = blockIdx.x;
    int lane = threadIdx.x;
    bool valid = lane < NCLS;
    float acc = valid ? __ldg(&bout[lane]) : 0.f;
    for (int k = 0; k < DCAT; k++) {
        float v = __ldg(&hfin[g * DCAT + k]);
        if (valid) acc += v * __ldg(&Wout[k * NCLS + lane]);
    }
    float logit = acc;
    float m = valid ? logit : -INFINITY;
#pragma unroll
    for (int off = 16; off > 0; off >>= 1)
        m = fmaxf(m, __shfl_xor_sync(0xFFFFFFFFu, m, off));
    float e = valid ? expf(logit - m) : 0.f;
#pragma unroll
    for (int off = 16; off > 0; off >>= 1)
        e += __shfl_xor_sync(0xFFFFFFFFu, e, off);
    float ls = logit - m - logf(e);
    if (valid) {
        out[g * NCLS + lane] = logit;
        if (out_size >= 2 * N_GRAPHS * NCLS)
            out[N_GRAPHS * NCLS + g * NCLS + lane] = ls;
    }
}

extern "C" void kernel_launch(void* const* d_in, const int* in_sizes, int n_in,
                              void* d_out, int out_size) {
    const float* x        = (const float*)d_in[0];
    const int*   ei       = (const int*)d_in[1];
    const int*   batch    = (const int*)d_in[2];

    int w = 3;
    if (n_in >= 4 && in_sizes[3] == 1) w = 4;

    const float* W1   = (const float*)d_in[w + 0];
    const float* b1   = (const float*)d_in[w + 1];
    const float* gamma= (const float*)d_in[w + 2];
    const float* beta = (const float*)d_in[w + 3];
    const float* rmean= (const float*)d_in[w + 4];
    const float* rvar = (const float*)d_in[w + 5];
    const float* W2   = (const float*)d_in[w + 6];
    const float* b2   = (const float*)d_in[w + 7];
    const float* Wfin = (const float*)d_in[w + 8];
    const float* bfin = (const float*)d_in[w + 9];
    const float* Wout = (const float*)d_in[w + 10];
    const float* bout = (const float*)d_in[w + 11];
    float* out = (float*)d_out;

    float *aggr, *z, *pooled, *hfin, *bhi, *blo;
    __half* hh;
    int *counts, *rowstart, *cursor, *colbuf, *bsum;
    cudaGetSymbolAddress((void**)&aggr,     g_aggr);
    cudaGetSymbolAddress((void**)&z,        g_z);
    cudaGetSymbolAddress((void**)&hh,       g_hh);
    cudaGetSymbolAddress((void**)&pooled,   g_pooled);
    cudaGetSymbolAddress((void**)&hfin,     g_hfin);
    cudaGetSymbolAddress((void**)&counts,   g_counts);
    cudaGetSymbolAddress((void**)&rowstart, g_rowstart);
    cudaGetSymbolAddress((void**)&cursor,   g_cursor);
    cudaGetSymbolAddress((void**)&colbuf,   g_col);
    cudaGetSymbolAddress((void**)&bsum,     g_bsum);
    cudaGetSymbolAddress((void**)&bhi,      g_bhi);
    cudaGetSymbolAddress((void**)&blo,      g_blo);

    const int EB = (N_EDGES + 255) / 256;
    const int NB = (N_NODES * 32 + 255) / 256;

    zero_int_kernel<<<(N_NODES + 4 + 255) / 256, 256>>>(counts, N_NODES + 4);
    zero_kernel<<<192, 256>>>((float4*)pooled, N_GRAPHS * DCAT / 4);
    x2h_kernel<<<(N_NODES * DIM / 2 + 255) / 256, 256>>>(
        (const float2*)x, (__half2*)hh);
    hist_kernel<<<EB, 256>>>(ei, counts);
    scan1_kernel<<<SCAN_NB, 1024>>>(counts, rowstart, bsum);
    scan2_kernel<<<1, 32>>>(bsum);
    scan3_kernel<<<SCAN_NB, 1024>>>(bsum, rowstart, cursor);
    fill_kernel<<<EB, 256>>>(ei, cursor, colbuf);
    bfrag_kernel<<<(6 * BFRAG_PER_L2 + 255) / 256, 256>>>(W1, W2, bhi, blo);

    for (int i = 0; i < NLAYERS; i++) {
        gather_kernel<<<NB, 256>>>(hh, rowstart, colbuf, aggr);
        int l2a = i * 2, l2b = i * 2 + 1;
        gemm_tf32_kernel<<<148, 512>>>(
            aggr, bhi + l2a * BFRAG_PER_L2, blo + l2a * BFRAG_PER_L2,
            b1 + i * DIM,
            gamma + i * DIM, beta + i * DIM, rmean + i * DIM, rvar + i * DIM,
            nullptr, nullptr, 0, z, nullptr, /*mode=*/0);
        gemm_tf32_kernel<<<148, 512>>>(
            z, bhi + l2b * BFRAG_PER_L2, blo + l2b * BFRAG_PER_L2,
            b2 + i * DIM,
            nullptr, nullptr, nullptr, nullptr,
            batch, pooled, i * DIM, nullptr, hh, /*mode=*/1);
    }

    fin1_kernel<<<N_GRAPHS, DCAT>>>(pooled, Wfin, bfin, hfin);
    fin2_kernel<<<N_GRAPHS, 32>>>(hfin, Wout, bout, out, out_size);
}

// round 8
// speedup vs baseline: 2.3470x; 1.0057x over previous
#include <cuda_runtime.h>
#include <cuda_fp16.h>
#include <math.h>

#define N_NODES  100000
#define N_EDGES  3200000
#define N_GRAPHS 512
#define DIM      128
#define NLAYERS  3
#define DCAT     384
#define NCLS     10
#define BN_EPS   1e-5f

#define M_TILES  6252           // ceil(100000/16)
#define SCAN_NB  98             // ceil(100000/1024)

// Scratch (device globals; no allocations allowed)
__device__ float g_aggr[N_NODES * DIM];
__device__ float g_z[N_NODES * DIM];
__device__ __half g_hh[N_NODES * DIM];     // fp16 shadow of h (gather input)
__device__ float g_pooled[N_GRAPHS * DCAT];
__device__ float g_hfin[N_GRAPHS * DCAT];
// CSR scratch
__device__ int g_counts[N_NODES + 4];
__device__ int g_rowstart[N_NODES + 4];
__device__ int g_cursor[N_NODES + 4];
__device__ int g_col[N_EDGES];
__device__ int g_bsum[SCAN_NB + 4];
// tf32 weight fragments: [l2(6)][w(16)][kt(16)][lane(32)][j(2)]
#define BFRAG_PER_L2 (16 * 16 * 32 * 2)
__device__ float g_bhi[6 * BFRAG_PER_L2];
__device__ float g_blo[6 * BFRAG_PER_L2];

__device__ __forceinline__ float tf32r(float x) {
    unsigned u;
    asm("cvt.rna.tf32.f32 %0, %1;" : "=r"(u) : "f"(x));
    return __uint_as_float(u);
}

__global__ void zero_kernel(float4* __restrict__ p, int n4) {
    int i = blockIdx.x * blockDim.x + threadIdx.x;
    int stride = gridDim.x * blockDim.x;
    float4 z = make_float4(0.f, 0.f, 0.f, 0.f);
    for (; i < n4; i += stride) p[i] = z;
}

__global__ void zero_int_kernel(int* __restrict__ p, int n) {
    int i = blockIdx.x * blockDim.x + threadIdx.x;
    if (i < n) p[i] = 0;
}

// Convert x (fp32) -> fp16 shadow. One thread per half2.
__global__ void x2h_kernel(const float2* __restrict__ x, __half2* __restrict__ hh) {
    int i = blockIdx.x * blockDim.x + threadIdx.x;
    if (i < N_NODES * DIM / 2) hh[i] = __float22half2_rn(__ldg(&x[i]));
}

// ---------------- CSR build (counting sort of edges by dst) ----------------
__global__ void hist_kernel(const int* __restrict__ ei, int* __restrict__ counts) {
    int e = blockIdx.x * blockDim.x + threadIdx.x;
    if (e < N_EDGES) atomicAdd(&counts[__ldg(&ei[N_EDGES + e])], 1);
}

__global__ void __launch_bounds__(1024) scan1_kernel(
        const int* __restrict__ counts, int* __restrict__ rowstart,
        int* __restrict__ bsum) {
    __shared__ int wsum[32];
    int t = threadIdx.x;
    int i = blockIdx.x * 1024 + t;
    int c = (i < N_NODES) ? __ldg(&counts[i]) : 0;
    int v = c;
#pragma unroll
    for (int off = 1; off < 32; off <<= 1) {
        int u = __shfl_up_sync(0xFFFFFFFFu, v, off);
        if ((t & 31) >= off) v += u;
    }
    if ((t & 31) == 31) wsum[t >> 5] = v;
    __syncthreads();
    if (t < 32) {
        int w = wsum[t];
#pragma unroll
        for (int off = 1; off < 32; off <<= 1) {
            int u = __shfl_up_sync(0xFFFFFFFFu, w, off);
            if (t >= off) w += u;
        }
        wsum[t] = w;
    }
    __syncthreads();
    int excl = v - c + ((t >= 32) ? wsum[(t >> 5) - 1] : 0);
    if (i < N_NODES) rowstart[i] = excl;
    if (t == 1023) bsum[blockIdx.x] = excl + c;
}

__global__ void __launch_bounds__(32) scan2_kernel(int* __restrict__ bsum) {
    int t = threadIdx.x;
    int v[4];
    int part = 0;
#pragma unroll
    for (int j = 0; j < 4; j++) {
        int idx = t * 4 + j;
        v[j] = (idx < SCAN_NB) ? bsum[idx] : 0;
        part += v[j];
    }
    int p = part;
#pragma unroll
    for (int off = 1; off < 32; off <<= 1) {
        int u = __shfl_up_sync(0xFFFFFFFFu, p, off);
        if (t >= off) p += u;
    }
    int run = p - part;
#pragma unroll
    for (int j = 0; j < 4; j++) {
        int idx = t * 4 + j;
        if (idx < SCAN_NB) bsum[idx] = run;
        run += v[j];
    }
}

__global__ void __launch_bounds__(1024) scan3_kernel(
        const int* __restrict__ bsum, int* __restrict__ rowstart,
        int* __restrict__ cursor) {
    int i = blockIdx.x * 1024 + threadIdx.x;
    if (i < N_NODES) {
        int v = rowstart[i] + __ldg(&bsum[blockIdx.x]);
        rowstart[i] = v;
        cursor[i] = v;
    }
    if (i == 0) rowstart[N_NODES] = N_EDGES;
}

__global__ void fill_kernel(const int* __restrict__ ei,
                            int* __restrict__ cursor, int* __restrict__ col) {
    int e = blockIdx.x * blockDim.x + threadIdx.x;
    if (e >= N_EDGES) return;
    int s = __ldg(&ei[e]);
    int d = __ldg(&ei[N_EDGES + e]);
    int pos = atomicAdd(&cursor[d], 1);
    col[pos] = s;
}

// ---------------- Weight fragment precompute (tf32 hi/lo split) ------------
__global__ void bfrag_kernel(const float* __restrict__ W1,
                             const float* __restrict__ W2,
                             float* __restrict__ bhi, float* __restrict__ blo) {
    int idx = blockIdx.x * blockDim.x + threadIdx.x;
    if (idx >= 6 * BFRAG_PER_L2) return;
    int j    = idx & 1;
    int lane = (idx >> 1) & 31;
    int kt   = (idx >> 6) & 15;
    int w    = (idx >> 10) & 15;
    int l2   = idx >> 14;
    int g = lane >> 2, tg = lane & 3;
    int k = kt * 8 + tg + 4 * j;
    int n = w * 8 + g;
    const float* Wm = (l2 & 1) ? (W2 + (l2 >> 1) * DIM * DIM)
                               : (W1 + (l2 >> 1) * DIM * DIM);
    float v = __ldg(&Wm[k * DIM + n]);
    float hi = tf32r(v);
    float lo = tf32r(v - hi);
    bhi[idx] = hi;
    blo[idx] = lo;
}

// ---------------- Gather (fp16 rows): aggr[n] = h[n] + sum h[s] ------------
// Half-warp (16 lanes) per node; lane owns 16B (uint4 = 8 halfs) of the row.
// 2 nodes per warp, 8-deep unrolled main loop -> 16 rows in flight per warp.
__device__ __forceinline__ void acc_add8(float* acc, uint4 r) {
    float2 f0 = __half22float2(*(__half2*)&r.x);
    float2 f1 = __half22float2(*(__half2*)&r.y);
    float2 f2 = __half22float2(*(__half2*)&r.z);
    float2 f3 = __half22float2(*(__half2*)&r.w);
    acc[0] += f0.x; acc[1] += f0.y; acc[2] += f1.x; acc[3] += f1.y;
    acc[4] += f2.x; acc[5] += f2.y; acc[6] += f3.x; acc[7] += f3.y;
}

__global__ void __launch_bounds__(256) gather_kernel(
        const __half* __restrict__ hh,
        const int* __restrict__ rowstart, const int* __restrict__ col,
        float* __restrict__ aggr) {
    unsigned gw = (blockIdx.x * 256u + threadIdx.x) >> 5;   // global warp id
    int lane = threadIdx.x & 31;
    int l16 = lane & 15;
    unsigned n = gw * 2 + (lane >> 4);
    if (n >= N_NODES) return;
    int beg = __ldg(&rowstart[n]);
    int end = __ldg(&rowstart[n + 1]);

    // init acc = self row (GIN eps=0: h[n] + sum of neighbors)
    float acc[8];
    {
        uint4 r = __ldg((const uint4*)(hh + (long long)n * DIM) + l16);
        float2 f0 = __half22float2(*(__half2*)&r.x);
        float2 f1 = __half22float2(*(__half2*)&r.y);
        float2 f2 = __half22float2(*(__half2*)&r.z);
        float2 f3 = __half22float2(*(__half2*)&r.w);
        acc[0] = f0.x; acc[1] = f0.y; acc[2] = f1.x; acc[3] = f1.y;
        acc[4] = f2.x; acc[5] = f2.y; acc[6] = f3.x; acc[7] = f3.y;
    }

    int i = beg;
    for (; i + 8 <= end; i += 8) {
        uint4 r[8];
#pragma unroll
        for (int j = 0; j < 8; j++) {
            int s = __ldg(&col[i + j]);
            r[j] = __ldg((const uint4*)(hh + (long long)s * DIM) + l16);
        }
#pragma unroll
        for (int j = 0; j < 8; j++) acc_add8(acc, r[j]);
    }
    if (i + 4 <= end) {
        uint4 r[4];
#pragma unroll
        for (int j = 0; j < 4; j++) {
            int s = __ldg(&col[i + j]);
            r[j] = __ldg((const uint4*)(hh + (long long)s * DIM) + l16);
        }
#pragma unroll
        for (int j = 0; j < 4; j++) acc_add8(acc, r[j]);
        i += 4;
    }
    if (i + 2 <= end) {
        int s0 = __ldg(&col[i]);
        int s1 = __ldg(&col[i + 1]);
        uint4 r0 = __ldg((const uint4*)(hh + (long long)s0 * DIM) + l16);
        uint4 r1 = __ldg((const uint4*)(hh + (long long)s1 * DIM) + l16);
        acc_add8(acc, r0);
        acc_add8(acc, r1);
        i += 2;
    }
    if (i < end) {
        int s = __ldg(&col[i]);
        acc_add8(acc, __ldg((const uint4*)(hh + (long long)s * DIM) + l16));
    }

    float4* ap = (float4*)(aggr + (long long)n * DIM) + l16 * 2;
    ap[0] = make_float4(acc[0], acc[1], acc[2], acc[3]);
    ap[1] = make_float4(acc[4], acc[5], acc[6], acc[7]);
}

// ---------------- tf32 tensor-core GEMM, fused epilogue --------------------
#define MMA_TF32(C, A0, A1, A2, A3, B0, B1)                                  \
    asm volatile("mma.sync.aligned.m16n8k8.row.col.f32.tf32.tf32.f32 "       \
                 "{%0,%1,%2,%3}, {%4,%5,%6,%7}, {%8,%9}, {%0,%1,%2,%3};"     \
                 : "+f"(C[0]), "+f"(C[1]), "+f"(C[2]), "+f"(C[3])            \
                 : "r"(A0), "r"(A1), "r"(A2), "r"(A3), "r"(B0), "r"(B1))

#define AS_STRIDE 136

// mode 0: BN(eval)+ReLU -> fp32 out (z).
// mode 1: ReLU -> fp16 out (h shadow) + atomic pool into pooled.
__global__ void __launch_bounds__(512, 1) gemm_tf32_kernel(
        const float* __restrict__ A,
        const float* __restrict__ bhi_l2, const float* __restrict__ blo_l2,
        const float* __restrict__ bias,
        const float* __restrict__ gamma, const float* __restrict__ beta,
        const float* __restrict__ rmean, const float* __restrict__ rvar,
        const int* __restrict__ batch, float* __restrict__ pooled, int pool_off,
        float* __restrict__ outf, __half* __restrict__ outh, int mode) {
    __shared__ float Ah[2][16 * AS_STRIDE];
    __shared__ float Al[2][16 * AS_STRIDE];

    int tid = threadIdx.x;
    int wid = tid >> 5;
    int lane = tid & 31;
    int g = lane >> 2, tg = lane & 3;

    unsigned bh[16][2], bl[16][2];
    {
        const float2* bp = (const float2*)bhi_l2 + (wid * 16 * 32 + lane);
        const float2* lp = (const float2*)blo_l2 + (wid * 16 * 32 + lane);
#pragma unroll
        for (int kt = 0; kt < 16; kt++) {
            float2 fh = __ldg(bp + kt * 32);
            float2 fl = __ldg(lp + kt * 32);
            bh[kt][0] = __float_as_uint(fh.x);
            bh[kt][1] = __float_as_uint(fh.y);
            bl[kt][0] = __float_as_uint(fl.x);
            bl[kt][1] = __float_as_uint(fl.y);
        }
    }

    int col0 = wid * 8 + tg * 2;
    float bb0 = __ldg(&bias[col0]), bb1 = __ldg(&bias[col0 + 1]);
    float sc0 = 1.f, sh0 = 0.f, sc1 = 1.f, sh1 = 0.f;
    if (mode == 0) {
        sc0 = __ldg(&gamma[col0]) * rsqrtf(__ldg(&rvar[col0]) + BN_EPS);
        sh0 = __ldg(&beta[col0]) - __ldg(&rmean[col0]) * sc0;
        sc1 = __ldg(&gamma[col0 + 1]) * rsqrtf(__ldg(&rvar[col0 + 1]) + BN_EPS);
        sh1 = __ldg(&beta[col0 + 1]) - __ldg(&rmean[col0 + 1]) * sc1;
    }

    int sr = tid >> 5;
    int sc4 = tid & 31;
    int skt = sc4 >> 1;
    int sodd = sc4 & 1;

    float4 v = make_float4(0.f, 0.f, 0.f, 0.f);
    {
        int row = blockIdx.x * 16 + sr;
        if (blockIdx.x < M_TILES && row < N_NODES)
            v = __ldg((const float4*)(A + (long long)row * DIM) + sc4);
    }

    int buf = 0;
    for (int mt = blockIdx.x; mt < M_TILES; mt += gridDim.x) {
        {
            float* ah = Ah[buf];
            float* al = Al[buf];
            float vv[4] = {v.x, v.y, v.z, v.w};
#pragma unroll
            for (int j = 0; j < 4; j++) {
                float hi = tf32r(vv[j]);
                float lo = tf32r(vv[j] - hi);
                int slot = j * 2 + sodd;
                ah[sr * AS_STRIDE + skt * 8 + slot] = hi;
                al[sr * AS_STRIDE + skt * 8 + slot] = lo;
            }
        }
        __syncthreads();

        int mtn = mt + gridDim.x;
        if (mtn < M_TILES) {
            int row = mtn * 16 + sr;
            v = (row < N_NODES)
                ? __ldg((const float4*)(A + (long long)row * DIM) + sc4)
                : make_float4(0.f, 0.f, 0.f, 0.f);
        }

        float cm[4] = {0.f, 0.f, 0.f, 0.f};
        float cc[4] = {0.f, 0.f, 0.f, 0.f};
        const float* ah = Ah[buf];
        const float* al = Al[buf];
#pragma unroll
        for (int kt = 0; kt < 16; kt++) {
            float2 h02 = *(const float2*)&ah[g * AS_STRIDE + kt * 8 + tg * 2];
            float2 h13 = *(const float2*)&ah[(g + 8) * AS_STRIDE + kt * 8 + tg * 2];
            float2 l02 = *(const float2*)&al[g * AS_STRIDE + kt * 8 + tg * 2];
            float2 l13 = *(const float2*)&al[(g + 8) * AS_STRIDE + kt * 8 + tg * 2];
            unsigned a0 = __float_as_uint(h02.x), a1 = __float_as_uint(h13.x);
            unsigned a2 = __float_as_uint(h02.y), a3 = __float_as_uint(h13.y);
            unsigned e0 = __float_as_uint(l02.x), e1 = __float_as_uint(l13.x);
            unsigned e2 = __float_as_uint(l02.y), e3 = __float_as_uint(l13.y);
            MMA_TF32(cm, a0, a1, a2, a3, bh[kt][0], bh[kt][1]);
            MMA_TF32(cc, a0, a1, a2, a3, bl[kt][0], bl[kt][1]);
            MMA_TF32(cc, e0, e1, e2, e3, bh[kt][0], bh[kt][1]);
        }

        int r0 = mt * 16 + g;
        int r1 = r0 + 8;
        float y00 = cm[0] + cc[0] + bb0;
        float y01 = cm[1] + cc[1] + bb1;
        float y10 = cm[2] + cc[2] + bb0;
        float y11 = cm[3] + cc[3] + bb1;
        if (mode == 0) {
            y00 = sc0 * y00 + sh0; y01 = sc1 * y01 + sh1;
            y10 = sc0 * y10 + sh0; y11 = sc1 * y11 + sh1;
        }
        y00 = fmaxf(y00, 0.f); y01 = fmaxf(y01, 0.f);
        y10 = fmaxf(y10, 0.f); y11 = fmaxf(y11, 0.f);

        if (r0 < N_NODES) {
            if (mode == 0) {
                *(float2*)(outf + (long long)r0 * DIM + col0) = make_float2(y00, y01);
            } else {
                *(__half2*)(outh + (long long)r0 * DIM + col0) =
                    __float22half2_rn(make_float2(y00, y01));
                int b0 = __ldg(&batch[r0]);
                float* pb = pooled + b0 * DCAT + pool_off + col0;
                asm volatile("red.global.add.v2.f32 [%0], {%1,%2};"
                             :: "l"(pb), "f"(y00), "f"(y01) : "memory");
            }
        }
        if (r1 < N_NODES) {
            if (mode == 0) {
                *(float2*)(outf + (long long)r1 * DIM + col0) = make_float2(y10, y11);
            } else {
                *(__half2*)(outh + (long long)r1 * DIM + col0) =
                    __float22half2_rn(make_float2(y10, y11));
                int b1i = __ldg(&batch[r1]);
                float* pb = pooled + b1i * DCAT + pool_off + col0;
                asm volatile("red.global.add.v2.f32 [%0], {%1,%2};"
                             :: "l"(pb), "f"(y10), "f"(y11) : "memory");
            }
        }
        buf ^= 1;
    }
}

// h_fin = relu(pooled @ Wfin + bfin)
__global__ void __launch_bounds__(DCAT) fin1_kernel(
        const float* __restrict__ pooled, const float* __restrict__ Wfin,
        const float* __restrict__ bfin, float* __restrict__ hfin) {
    __shared__ float s[DCAT];
    int g = blockIdx.x;
    int j = threadIdx.x;
    s[j] = pooled[g * DCAT + j];
    __syncthreads();
    float acc0 = 0.f, acc1 = 0.f, acc2 = 0.f, acc3 = 0.f;
#pragma unroll 4
    for (int k = 0; k < DCAT; k += 4) {
        acc0 += s[k + 0] * __ldg(&Wfin[(k + 0) * DCAT + j]);
        acc1 += s[k + 1] * __ldg(&Wfin[(k + 1) * DCAT + j]);
        acc2 += s[k + 2] * __ldg(&Wfin[(k + 2) * DCAT + j]);
        acc3 += s[k + 3] * __ldg(&Wfin[(k + 3) * DCAT + j]);
    }
    float acc = (acc0 + acc1) + (acc2 + acc3) + __ldg(&bfin[j]);
    hfin[g * DCAT + j] = fmaxf(acc, 0.f);
}

// logits + log_softmax: one warp per graph.
__global__ void __launch_bounds__(32) fin2_kernel(
        const float* __restrict__ hfin, const float* __restrict__ Wout,
        const float* __restrict__ bout, float* __restrict__ out, int out_size) {
    int g = blockIdx.x;
    int lane = threadIdx.x;
    bool valid = lane < NCLS;
    float acc = valid ? __ldg(&bout[lane]) : 0.f;
    for (int k = 0; k < DCAT; k++) {
        float v = __ldg(&hfin[g * DCAT + k]);
        if (valid) acc += v * __ldg(&Wout[k * NCLS + lane]);
    }
    float logit = acc;
    float m = valid ? logit : -INFINITY;
#pragma unroll
    for (int off = 16; off > 0; off >>= 1)
        m = fmaxf(m, __shfl_xor_sync(0xFFFFFFFFu, m, off));
    float e = valid ? expf(logit - m) : 0.f;
#pragma unroll
    for (int off = 16; off > 0; off >>= 1)
        e += __shfl_xor_sync(0xFFFFFFFFu, e, off);
    float ls = logit - m - logf(e);
    if (valid) {
        out[g * NCLS + lane] = logit;
        if (out_size >= 2 * N_GRAPHS * NCLS)
            out[N_GRAPHS * NCLS + g * NCLS + lane] = ls;
    }
}

extern "C" void kernel_launch(void* const* d_in, const int* in_sizes, int n_in,
                              void* d_out, int out_size) {
    const float* x        = (const float*)d_in[0];
    const int*   ei       = (const int*)d_in[1];
    const int*   batch    = (const int*)d_in[2];

    int w = 3;
    if (n_in >= 4 && in_sizes[3] == 1) w = 4;

    const float* W1   = (const float*)d_in[w + 0];
    const float* b1   = (const float*)d_in[w + 1];
    const float* gamma= (const float*)d_in[w + 2];
    const float* beta = (const float*)d_in[w + 3];
    const float* rmean= (const float*)d_in[w + 4];
    const float* rvar = (const float*)d_in[w + 5];
    const float* W2   = (const float*)d_in[w + 6];
    const float* b2   = (const float*)d_in[w + 7];
    const float* Wfin = (const float*)d_in[w + 8];
    const float* bfin = (const float*)d_in[w + 9];
    const float* Wout = (const float*)d_in[w + 10];
    const float* bout = (const float*)d_in[w + 11];
    float* out = (float*)d_out;

    float *aggr, *z, *pooled, *hfin, *bhi, *blo;
    __half* hh;
    int *counts, *rowstart, *cursor, *colbuf, *bsum;
    cudaGetSymbolAddress((void**)&aggr,     g_aggr);
    cudaGetSymbolAddress((void**)&z,        g_z);
    cudaGetSymbolAddress((void**)&hh,       g_hh);
    cudaGetSymbolAddress((void**)&pooled,   g_pooled);
    cudaGetSymbolAddress((void**)&hfin,     g_hfin);
    cudaGetSymbolAddress((void**)&counts,   g_counts);
    cudaGetSymbolAddress((void**)&rowstart, g_rowstart);
    cudaGetSymbolAddress((void**)&cursor,   g_cursor);
    cudaGetSymbolAddress((void**)&colbuf,   g_col);
    cudaGetSymbolAddress((void**)&bsum,     g_bsum);
    cudaGetSymbolAddress((void**)&bhi,      g_bhi);
    cudaGetSymbolAddress((void**)&blo,      g_blo);

    const int EB = (N_EDGES + 255) / 256;
    const int GB = ((N_NODES + 1) / 2 * 32 + 255) / 256;   // 2 nodes/warp

    zero_int_kernel<<<(N_NODES + 4 + 255) / 256, 256>>>(counts, N_NODES + 4);
    zero_kernel<<<192, 256>>>((float4*)pooled, N_GRAPHS * DCAT / 4);
    x2h_kernel<<<(N_NODES * DIM / 2 + 255) / 256, 256>>>(
        (const float2*)x, (__half2*)hh);
    hist_kernel<<<EB, 256>>>(ei, counts);
    scan1_kernel<<<SCAN_NB, 1024>>>(counts, rowstart, bsum);
    scan2_kernel<<<1, 32>>>(bsum);
    scan3_kernel<<<SCAN_NB, 1024>>>(bsum, rowstart, cursor);
    fill_kernel<<<EB, 256>>>(ei, cursor, colbuf);
    bfrag_kernel<<<(6 * BFRAG_PER_L2 + 255) / 256, 256>>>(W1, W2, bhi, blo);

    for (int i = 0; i < NLAYERS; i++) {
        gather_kernel<<<GB, 256>>>(hh, rowstart, colbuf, aggr);
        int l2a = i * 2, l2b = i * 2 + 1;
        gemm_tf32_kernel<<<148, 512>>>(
            aggr, bhi + l2a * BFRAG_PER_L2, blo + l2a * BFRAG_PER_L2,
            b1 + i * DIM,
            gamma + i * DIM, beta + i * DIM, rmean + i * DIM, rvar + i * DIM,
            nullptr, nullptr, 0, z, nullptr, /*mode=*/0);
        gemm_tf32_kernel<<<148, 512>>>(
            z, bhi + l2b * BFRAG_PER_L2, blo + l2b * BFRAG_PER_L2,
            b2 + i * DIM,
            nullptr, nullptr, nullptr, nullptr,
            batch, pooled, i * DIM, nullptr, hh, /*mode=*/1);
    }

    fin1_kernel<<<N_GRAPHS, DCAT>>>(pooled, Wfin, bfin, hfin);
    fin2_kernel<<<N_GRAPHS, 32>>>(hfin, Wout, bout, out, out_size);
}

// round 9
// speedup vs baseline: 2.9415x; 1.2533x over previous
#include <cuda_runtime.h>
#include <cuda_fp16.h>
#include <math.h>

#define N_NODES  100000
#define N_EDGES  3200000
#define N_GRAPHS 512
#define DIM      128
#define NLAYERS  3
#define DCAT     384
#define NCLS     10
#define BN_EPS   1e-5f

#define M_TILES  6252           // ceil(100000/16)
#define SCAN_NB  98             // ceil(100000/1024)

// Scratch (device globals; no allocations allowed)
__device__ float g_aggr[N_NODES * DIM];
__device__ __half g_hh[N_NODES * DIM];     // fp16 shadow of h (gather input)
__device__ float g_pooled[N_GRAPHS * DCAT];
__device__ float g_hfin[N_GRAPHS * DCAT];
// CSR scratch
__device__ int g_counts[N_NODES + 4];
__device__ int g_rowstart[N_NODES + 4];
__device__ int g_cursor[N_NODES + 4];
__device__ int g_col[N_EDGES];
__device__ int g_bsum[SCAN_NB + 4];
// fp16 weight fragments (m16n8k16 B layout): [l2(6)][w(16)][kt(8)][lane(32)]
// uint2 = {reg j=0, reg j=1}, each packed half2 (k, k+1)
#define WFRAG_PER_L2 (16 * 8 * 32)
__device__ uint2 g_wfh[6 * WFRAG_PER_L2];
__device__ uint2 g_wfl[6 * WFRAG_PER_L2];

__global__ void zero_kernel(float4* __restrict__ p, int n4) {
    int i = blockIdx.x * blockDim.x + threadIdx.x;
    int stride = gridDim.x * blockDim.x;
    float4 z = make_float4(0.f, 0.f, 0.f, 0.f);
    for (; i < n4; i += stride) p[i] = z;
}

__global__ void zero_int_kernel(int* __restrict__ p, int n) {
    int i = blockIdx.x * blockDim.x + threadIdx.x;
    if (i < n) p[i] = 0;
}

// Convert x (fp32) -> fp16 shadow.
__global__ void x2h_kernel(const float2* __restrict__ x, __half2* __restrict__ hh) {
    int i = blockIdx.x * blockDim.x + threadIdx.x;
    if (i < N_NODES * DIM / 2) hh[i] = __float22half2_rn(__ldg(&x[i]));
}

// ---------------- CSR build (counting sort of edges by dst) ----------------
__global__ void hist_kernel(const int* __restrict__ ei, int* __restrict__ counts) {
    int e = blockIdx.x * blockDim.x + threadIdx.x;
    if (e < N_EDGES) atomicAdd(&counts[__ldg(&ei[N_EDGES + e])], 1);
}

__global__ void __launch_bounds__(1024) scan1_kernel(
        const int* __restrict__ counts, int* __restrict__ rowstart,
        int* __restrict__ bsum) {
    __shared__ int wsum[32];
    int t = threadIdx.x;
    int i = blockIdx.x * 1024 + t;
    int c = (i < N_NODES) ? __ldg(&counts[i]) : 0;
    int v = c;
#pragma unroll
    for (int off = 1; off < 32; off <<= 1) {
        int u = __shfl_up_sync(0xFFFFFFFFu, v, off);
        if ((t & 31) >= off) v += u;
    }
    if ((t & 31) == 31) wsum[t >> 5] = v;
    __syncthreads();
    if (t < 32) {
        int w = wsum[t];
#pragma unroll
        for (int off = 1; off < 32; off <<= 1) {
            int u = __shfl_up_sync(0xFFFFFFFFu, w, off);
            if (t >= off) w += u;
        }
        wsum[t] = w;
    }
    __syncthreads();
    int excl = v - c + ((t >= 32) ? wsum[(t >> 5) - 1] : 0);
    if (i < N_NODES) rowstart[i] = excl;
    if (t == 1023) bsum[blockIdx.x] = excl + c;
}

__global__ void __launch_bounds__(32) scan2_kernel(int* __restrict__ bsum) {
    int t = threadIdx.x;
    int v[4];
    int part = 0;
#pragma unroll
    for (int j = 0; j < 4; j++) {
        int idx = t * 4 + j;
        v[j] = (idx < SCAN_NB) ? bsum[idx] : 0;
        part += v[j];
    }
    int p = part;
#pragma unroll
    for (int off = 1; off < 32; off <<= 1) {
        int u = __shfl_up_sync(0xFFFFFFFFu, p, off);
        if (t >= off) p += u;
    }
    int run = p - part;
#pragma unroll
    for (int j = 0; j < 4; j++) {
        int idx = t * 4 + j;
        if (idx < SCAN_NB) bsum[idx] = run;
        run += v[j];
    }
}

__global__ void __launch_bounds__(1024) scan3_kernel(
        const int* __restrict__ bsum, int* __restrict__ rowstart,
        int* __restrict__ cursor) {
    int i = blockIdx.x * 1024 + threadIdx.x;
    if (i < N_NODES) {
        int v = rowstart[i] + __ldg(&bsum[blockIdx.x]);
        rowstart[i] = v;
        cursor[i] = v;
    }
    if (i == 0) rowstart[N_NODES] = N_EDGES;
}

__global__ void fill_kernel(const int* __restrict__ ei,
                            int* __restrict__ cursor, int* __restrict__ col) {
    int e = blockIdx.x * blockDim.x + threadIdx.x;
    if (e >= N_EDGES) return;
    int s = __ldg(&ei[e]);
    int d = __ldg(&ei[N_EDGES + e]);
    int pos = atomicAdd(&cursor[d], 1);
    col[pos] = s;
}

// -------- Weight fragment precompute (fp16 hi/lo, m16n8k16 B layout) -------
// B frag (row.col): lane holds reg j: halfs at k = kt*16 + j*8 + tg*2 + {0,1},
// n = w*8 + g  (g = lane>>2, tg = lane&3).
__global__ void wfrag_kernel(const float* __restrict__ W1,
                             const float* __restrict__ W2,
                             uint2* __restrict__ wfh, uint2* __restrict__ wfl) {
    int idx = blockIdx.x * blockDim.x + threadIdx.x;
    if (idx >= 6 * WFRAG_PER_L2) return;
    int lane = idx & 31;
    int kt   = (idx >> 5) & 7;
    int w    = (idx >> 8) & 15;
    int l2   = idx >> 12;
    int g = lane >> 2, tg = lane & 3;
    int n = w * 8 + g;
    const float* Wm = (l2 & 1) ? (W2 + (l2 >> 1) * DIM * DIM)
                               : (W1 + (l2 >> 1) * DIM * DIM);
    unsigned rh[2], rl[2];
#pragma unroll
    for (int j = 0; j < 2; j++) {
        int k0 = kt * 16 + j * 8 + tg * 2;
        float v0 = __ldg(&Wm[k0 * DIM + n]);
        float v1 = __ldg(&Wm[(k0 + 1) * DIM + n]);
        __half h0 = __float2half_rn(v0);
        __half h1 = __float2half_rn(v1);
        __half l0 = __float2half_rn(v0 - __half2float(h0));
        __half l1 = __float2half_rn(v1 - __half2float(h1));
        __half2 ph = __halves2half2(h0, h1);
        __half2 pl = __halves2half2(l0, l1);
        rh[j] = *(unsigned*)&ph;
        rl[j] = *(unsigned*)&pl;
    }
    wfh[idx] = make_uint2(rh[0], rh[1]);
    wfl[idx] = make_uint2(rl[0], rl[1]);
}

// ---------------- Gather (fp16 rows): aggr[n] = h[n] + sum h[s] ------------
__device__ __forceinline__ void acc_add8(float* acc, uint4 r) {
    float2 f0 = __half22float2(*(__half2*)&r.x);
    float2 f1 = __half22float2(*(__half2*)&r.y);
    float2 f2 = __half22float2(*(__half2*)&r.z);
    float2 f3 = __half22float2(*(__half2*)&r.w);
    acc[0] += f0.x; acc[1] += f0.y; acc[2] += f1.x; acc[3] += f1.y;
    acc[4] += f2.x; acc[5] += f2.y; acc[6] += f3.x; acc[7] += f3.y;
}

__global__ void __launch_bounds__(256) gather_kernel(
        const __half* __restrict__ hh,
        const int* __restrict__ rowstart, const int* __restrict__ col,
        float* __restrict__ aggr) {
    unsigned gw = (blockIdx.x * 256u + threadIdx.x) >> 5;
    int lane = threadIdx.x & 31;
    int l16 = lane & 15;
    unsigned n = gw * 2 + (lane >> 4);
    if (n >= N_NODES) return;
    int beg = __ldg(&rowstart[n]);
    int end = __ldg(&rowstart[n + 1]);

    float acc[8];
    {
        uint4 r = __ldg((const uint4*)(hh + (long long)n * DIM) + l16);
        float2 f0 = __half22float2(*(__half2*)&r.x);
        float2 f1 = __half22float2(*(__half2*)&r.y);
        float2 f2 = __half22float2(*(__half2*)&r.z);
        float2 f3 = __half22float2(*(__half2*)&r.w);
        acc[0] = f0.x; acc[1] = f0.y; acc[2] = f1.x; acc[3] = f1.y;
        acc[4] = f2.x; acc[5] = f2.y; acc[6] = f3.x; acc[7] = f3.y;
    }

    int i = beg;
    for (; i + 8 <= end; i += 8) {
        uint4 r[8];
#pragma unroll
        for (int j = 0; j < 8; j++) {
            int s = __ldg(&col[i + j]);
            r[j] = __ldg((const uint4*)(hh + (long long)s * DIM) + l16);
        }
#pragma unroll
        for (int j = 0; j < 8; j++) acc_add8(acc, r[j]);
    }
    if (i + 4 <= end) {
        uint4 r[4];
#pragma unroll
        for (int j = 0; j < 4; j++) {
            int s = __ldg(&col[i + j]);
            r[j] = __ldg((const uint4*)(hh + (long long)s * DIM) + l16);
        }
#pragma unroll
        for (int j = 0; j < 4; j++) acc_add8(acc, r[j]);
        i += 4;
    }
    if (i + 2 <= end) {
        int s0 = __ldg(&col[i]);
        int s1 = __ldg(&col[i + 1]);
        uint4 r0 = __ldg((const uint4*)(hh + (long long)s0 * DIM) + l16);
        uint4 r1 = __ldg((const uint4*)(hh + (long long)s1 * DIM) + l16);
        acc_add8(acc, r0);
        acc_add8(acc, r1);
        i += 2;
    }
    if (i < end) {
        int s = __ldg(&col[i]);
        acc_add8(acc, __ldg((const uint4*)(hh + (long long)s * DIM) + l16));
    }

    float4* ap = (float4*)(aggr + (long long)n * DIM) + l16 * 2;
    ap[0] = make_float4(acc[0], acc[1], acc[2], acc[3]);
    ap[1] = make_float4(acc[4], acc[5], acc[6], acc[7]);
}

// -------- Fused layer MLP: hh/pool = relu(bn(relu(bn? no)) ... ) ----------
// One kernel: A(aggr fp32) -> stage fp16 hi/lo smem -> MMA1(W1)+BN+ReLU ->
// z hi/lo smem -> MMA2(W2)+ReLU -> hh(fp16) + pooled atomics.
// 512 threads = 16 warps; warp w owns output n-slice [8w, 8w+8).
#define MMA16816(C, A0, A1, A2, A3, B0, B1)                                   \
    asm volatile("mma.sync.aligned.m16n8k16.row.col.f32.f16.f16.f32 "         \
                 "{%0,%1,%2,%3}, {%4,%5,%6,%7}, {%8,%9}, {%0,%1,%2,%3};"      \
                 : "+f"(C[0]), "+f"(C[1]), "+f"(C[2]), "+f"(C[3])             \
                 : "r"(A0), "r"(A1), "r"(A2), "r"(A3), "r"(B0), "r"(B1))

#define LDSM4(R0, R1, R2, R3, ADDR)                                           \
    asm volatile("ldmatrix.sync.aligned.m8n8.x4.shared.b16 {%0,%1,%2,%3}, [%4];" \
                 : "=r"(R0), "=r"(R1), "=r"(R2), "=r"(R3) : "r"(ADDR))

#define ZSTR 136   // halfs per smem row (272B: conflict-free ldmatrix)

__global__ void __launch_bounds__(512, 1) mlp_fused_kernel(
        const float* __restrict__ A,
        const uint2* __restrict__ w1h, const uint2* __restrict__ w1l,
        const uint2* __restrict__ w2h, const uint2* __restrict__ w2l,
        const float* __restrict__ b1,
        const float* __restrict__ gamma, const float* __restrict__ beta,
        const float* __restrict__ rmean, const float* __restrict__ rvar,
        const float* __restrict__ b2,
        const int* __restrict__ batch, float* __restrict__ pooled, int pool_off,
        __half* __restrict__ outh) {
    __shared__ __half Ah[2][16 * ZSTR];
    __shared__ __half Al[2][16 * ZSTR];
    __shared__ __half Zh[16 * ZSTR];
    __shared__ __half Zl[16 * ZSTR];

    int tid = threadIdx.x;
    int wid = tid >> 5;
    int lane = tid & 31;
    int g = lane >> 2, tg = lane & 3;

    // epilogue constants (cols fixed per thread)
    int col0 = wid * 8 + tg * 2;
    float sc0 = __ldg(&gamma[col0]) * rsqrtf(__ldg(&rvar[col0]) + BN_EPS);
    float sh0 = __ldg(&beta[col0]) - __ldg(&rmean[col0]) * sc0
                + sc0 * __ldg(&b1[col0]);
    float sc1 = __ldg(&gamma[col0 + 1]) * rsqrtf(__ldg(&rvar[col0 + 1]) + BN_EPS);
    float sh1 = __ldg(&beta[col0 + 1]) - __ldg(&rmean[col0 + 1]) * sc1
                + sc1 * __ldg(&b1[col0 + 1]);
    float bb0 = __ldg(&b2[col0]), bb1 = __ldg(&b2[col0 + 1]);

    // ldmatrix smem addresses (byte): row (lane&15), k-group (lane>>4)*8 halfs
    unsigned baseAh0, baseAh1, baseAl0, baseAl1, baseZh, baseZl;
    {
        unsigned off = (lane & 15) * (ZSTR * 2) + (lane >> 4) * 16;
        baseAh0 = (unsigned)__cvta_generic_to_shared(&Ah[0][0]) + off;
        baseAh1 = (unsigned)__cvta_generic_to_shared(&Ah[1][0]) + off;
        baseAl0 = (unsigned)__cvta_generic_to_shared(&Al[0][0]) + off;
        baseAl1 = (unsigned)__cvta_generic_to_shared(&Al[1][0]) + off;
        baseZh  = (unsigned)__cvta_generic_to_shared(&Zh[0]) + off;
        baseZl  = (unsigned)__cvta_generic_to_shared(&Zl[0]) + off;
    }

    // staging coords: warp wid stages row sr=wid, lane sc4 owns float4 sc4
    int sr = wid;
    int sc4 = lane;

    // prefetch first tile
    float4 v = make_float4(0.f, 0.f, 0.f, 0.f);
    {
        int row = blockIdx.x * 16 + sr;
        if (blockIdx.x < M_TILES && row < N_NODES)
            v = __ldg((const float4*)(A + (long long)row * DIM) + sc4);
    }

    const uint2* w1hp = w1h + (wid * 8) * 32 + lane;
    const uint2* w1lp = w1l + (wid * 8) * 32 + lane;
    const uint2* w2hp = w2h + (wid * 8) * 32 + lane;
    const uint2* w2lp = w2l + (wid * 8) * 32 + lane;

    int buf = 0;
    for (int mt = blockIdx.x; mt < M_TILES; mt += gridDim.x) {
        // ---- stage A tile: fp32 -> fp16 hi/lo ----
        {
            __half* ah = Ah[buf];
            __half* al = Al[buf];
            float vv[4] = {v.x, v.y, v.z, v.w};
            __half h[4], l[4];
#pragma unroll
            for (int j = 0; j < 4; j++) {
                h[j] = __float2half_rn(vv[j]);
                l[j] = __float2half_rn(vv[j] - __half2float(h[j]));
            }
            __half2* dsth = (__half2*)&ah[sr * ZSTR + sc4 * 4];
            __half2* dstl = (__half2*)&al[sr * ZSTR + sc4 * 4];
            dsth[0] = __halves2half2(h[0], h[1]);
            dsth[1] = __halves2half2(h[2], h[3]);
            dstl[0] = __halves2half2(l[0], l[1]);
            dstl[1] = __halves2half2(l[2], l[3]);
        }
        __syncthreads();

        // prefetch next tile
        int mtn = mt + gridDim.x;
        if (mtn < M_TILES) {
            int row = mtn * 16 + sr;
            v = (row < N_NODES)
                ? __ldg((const float4*)(A + (long long)row * DIM) + sc4)
                : make_float4(0.f, 0.f, 0.f, 0.f);
        }

        unsigned bah = buf ? baseAh1 : baseAh0;
        unsigned bal = buf ? baseAl1 : baseAl0;

        // ---- MLP1: z = BN(aggr @ W1 + b1), ReLU ----
        float cm[4] = {0.f, 0.f, 0.f, 0.f};
        float cc[4] = {0.f, 0.f, 0.f, 0.f};
#pragma unroll
        for (int kt = 0; kt < 8; kt++) {
            unsigned x0, x1, x2, x3, y0, y1, y2, y3;
            LDSM4(x0, x1, x2, x3, bah + kt * 32);
            LDSM4(y0, y1, y2, y3, bal + kt * 32);
            uint2 wh = __ldg(w1hp + kt * 32);
            uint2 wl = __ldg(w1lp + kt * 32);
            MMA16816(cm, x0, x1, x2, x3, wh.x, wh.y);
            MMA16816(cc, x0, x1, x2, x3, wl.x, wl.y);
            MMA16816(cc, y0, y1, y2, y3, wh.x, wh.y);
        }
        {
            float y00 = fmaxf(sc0 * (cm[0] + cc[0]) + sh0, 0.f);
            float y01 = fmaxf(sc1 * (cm[1] + cc[1]) + sh1, 0.f);
            float y10 = fmaxf(sc0 * (cm[2] + cc[2]) + sh0, 0.f);
            float y11 = fmaxf(sc1 * (cm[3] + cc[3]) + sh1, 0.f);
            // split + store z to smem (rows g, g+8; cols col0, col0+1)
            __half h00 = __float2half_rn(y00);
            __half h01 = __float2half_rn(y01);
            __half h10 = __float2half_rn(y10);
            __half h11 = __float2half_rn(y11);
            *(__half2*)&Zh[g * ZSTR + col0] = __halves2half2(h00, h01);
            *(__half2*)&Zh[(g + 8) * ZSTR + col0] = __halves2half2(h10, h11);
            *(__half2*)&Zl[g * ZSTR + col0] = __halves2half2(
                __float2half_rn(y00 - __half2float(h00)),
                __float2half_rn(y01 - __half2float(h01)));
            *(__half2*)&Zl[(g + 8) * ZSTR + col0] = __halves2half2(
                __float2half_rn(y10 - __half2float(h10)),
                __float2half_rn(y11 - __half2float(h11)));
        }
        __syncthreads();

        // ---- MLP2: h = ReLU(z @ W2 + b2) ----
#pragma unroll
        for (int j = 0; j < 4; j++) { cm[j] = 0.f; cc[j] = 0.f; }
#pragma unroll
        for (int kt = 0; kt < 8; kt++) {
            unsigned x0, x1, x2, x3, y0, y1, y2, y3;
            LDSM4(x0, x1, x2, x3, baseZh + kt * 32);
            LDSM4(y0, y1, y2, y3, baseZl + kt * 32);
            uint2 wh = __ldg(w2hp + kt * 32);
            uint2 wl = __ldg(w2lp + kt * 32);
            MMA16816(cm, x0, x1, x2, x3, wh.x, wh.y);
            MMA16816(cc, x0, x1, x2, x3, wl.x, wl.y);
            MMA16816(cc, y0, y1, y2, y3, wh.x, wh.y);
        }
        {
            float y00 = fmaxf(cm[0] + cc[0] + bb0, 0.f);
            float y01 = fmaxf(cm[1] + cc[1] + bb1, 0.f);
            float y10 = fmaxf(cm[2] + cc[2] + bb0, 0.f);
            float y11 = fmaxf(cm[3] + cc[3] + bb1, 0.f);
            int r0 = mt * 16 + g;
            int r1 = r0 + 8;
            if (r0 < N_NODES) {
                *(__half2*)(outh + (long long)r0 * DIM + col0) =
                    __float22half2_rn(make_float2(y00, y01));
                int bi = __ldg(&batch[r0]);
                float* pb = pooled + bi * DCAT + pool_off + col0;
                asm volatile("red.global.add.v2.f32 [%0], {%1,%2};"
                             :: "l"(pb), "f"(y00), "f"(y01) : "memory");
            }
            if (r1 < N_NODES) {
                *(__half2*)(outh + (long long)r1 * DIM + col0) =
                    __float22half2_rn(make_float2(y10, y11));
                int bi = __ldg(&batch[r1]);
                float* pb = pooled + bi * DCAT + pool_off + col0;
                asm volatile("red.global.add.v2.f32 [%0], {%1,%2};"
                             :: "l"(pb), "f"(y10), "f"(y11) : "memory");
            }
        }
        buf ^= 1;
    }
}

// h_fin = relu(pooled @ Wfin + bfin)
__global__ void __launch_bounds__(DCAT) fin1_kernel(
        const float* __restrict__ pooled, const float* __restrict__ Wfin,
        const float* __restrict__ bfin, float* __restrict__ hfin) {
    __shared__ float s[DCAT];
    int g = blockIdx.x;
    int j = threadIdx.x;
    s[j] = pooled[g * DCAT + j];
    __syncthreads();
    float acc0 = 0.f, acc1 = 0.f, acc2 = 0.f, acc3 = 0.f;
#pragma unroll 4
    for (int k = 0; k < DCAT; k += 4) {
        acc0 += s[k + 0] * __ldg(&Wfin[(k + 0) * DCAT + j]);
        acc1 += s[k + 1] * __ldg(&Wfin[(k + 1) * DCAT + j]);
        acc2 += s[k + 2] * __ldg(&Wfin[(k + 2) * DCAT + j]);
        acc3 += s[k + 3] * __ldg(&Wfin[(k + 3) * DCAT + j]);
    }
    float acc = (acc0 + acc1) + (acc2 + acc3) + __ldg(&bfin[j]);
    hfin[g * DCAT + j] = fmaxf(acc, 0.f);
}

// logits + log_softmax: one warp per graph.
__global__ void __launch_bounds__(32) fin2_kernel(
        const float* __restrict__ hfin, const float* __restrict__ Wout,
        const float* __restrict__ bout, float* __restrict__ out, int out_size) {
    int g = blockIdx.x;
    int lane = threadIdx.x;
    bool valid = lane < NCLS;
    float acc = valid ? __ldg(&bout[lane]) : 0.f;
    for (int k = 0; k < DCAT; k++) {
        float v = __ldg(&hfin[g * DCAT + k]);
        if (valid) acc += v * __ldg(&Wout[k * NCLS + lane]);
    }
    float logit = acc;
    float m = valid ? logit : -INFINITY;
#pragma unroll
    for (int off = 16; off > 0; off >>= 1)
        m = fmaxf(m, __shfl_xor_sync(0xFFFFFFFFu, m, off));
    float e = valid ? expf(logit - m) : 0.f;
#pragma unroll
    for (int off = 16; off > 0; off >>= 1)
        e += __shfl_xor_sync(0xFFFFFFFFu, e, off);
    float ls = logit - m - logf(e);
    if (valid) {
        out[g * NCLS + lane] = logit;
        if (out_size >= 2 * N_GRAPHS * NCLS)
            out[N_GRAPHS * NCLS + g * NCLS + lane] = ls;
    }
}

extern "C" void kernel_launch(void* const* d_in, const int* in_sizes, int n_in,
                              void* d_out, int out_size) {
    const float* x        = (const float*)d_in[0];
    const int*   ei       = (const int*)d_in[1];
    const int*   batch    = (const int*)d_in[2];

    int w = 3;
    if (n_in >= 4 && in_sizes[3] == 1) w = 4;

    const float* W1   = (const float*)d_in[w + 0];
    const float* b1   = (const float*)d_in[w + 1];
    const float* gamma= (const float*)d_in[w + 2];
    const float* beta = (const float*)d_in[w + 3];
    const float* rmean= (const float*)d_in[w + 4];
    const float* rvar = (const float*)d_in[w + 5];
    const float* W2   = (const float*)d_in[w + 6];
    const float* b2   = (const float*)d_in[w + 7];
    const float* Wfin = (const float*)d_in[w + 8];
    const float* bfin = (const float*)d_in[w + 9];
    const float* Wout = (const float*)d_in[w + 10];
    const float* bout = (const float*)d_in[w + 11];
    float* out = (float*)d_out;

    float *aggr, *pooled, *hfin;
    __half* hh;
    uint2 *wfh, *wfl;
    int *counts, *rowstart, *cursor, *colbuf, *bsum;
    cudaGetSymbolAddress((void**)&aggr,     g_aggr);
    cudaGetSymbolAddress((void**)&hh,       g_hh);
    cudaGetSymbolAddress((void**)&pooled,   g_pooled);
    cudaGetSymbolAddress((void**)&hfin,     g_hfin);
    cudaGetSymbolAddress((void**)&counts,   g_counts);
    cudaGetSymbolAddress((void**)&rowstart, g_rowstart);
    cudaGetSymbolAddress((void**)&cursor,   g_cursor);
    cudaGetSymbolAddress((void**)&colbuf,   g_col);
    cudaGetSymbolAddress((void**)&bsum,     g_bsum);
    cudaGetSymbolAddress((void**)&wfh,      g_wfh);
    cudaGetSymbolAddress((void**)&wfl,      g_wfl);

    const int EB = (N_EDGES + 255) / 256;
    const int GB = ((N_NODES + 1) / 2 * 32 + 255) / 256;

    zero_int_kernel<<<(N_NODES + 4 + 255) / 256, 256>>>(counts, N_NODES + 4);
    zero_kernel<<<192, 256>>>((float4*)pooled, N_GRAPHS * DCAT / 4);
    x2h_kernel<<<(N_NODES * DIM / 2 + 255) / 256, 256>>>(
        (const float2*)x, (__half2*)hh);
    hist_kernel<<<EB, 256>>>(ei, counts);
    scan1_kernel<<<SCAN_NB, 1024>>>(counts, rowstart, bsum);
    scan2_kernel<<<1, 32>>>(bsum);
    scan3_kernel<<<SCAN_NB, 1024>>>(bsum, rowstart, cursor);
    fill_kernel<<<EB, 256>>>(ei, cursor, colbuf);
    wfrag_kernel<<<(6 * WFRAG_PER_L2 + 255) / 256, 256>>>(W1, W2, wfh, wfl);

    for (int i = 0; i < NLAYERS; i++) {
        gather_kernel<<<GB, 256>>>(hh, rowstart, colbuf, aggr);
        int l2a = i * 2, l2b = i * 2 + 1;
        mlp_fused_kernel<<<148, 512>>>(
            aggr,
            wfh + l2a * WFRAG_PER_L2, wfl + l2a * WFRAG_PER_L2,
            wfh + l2b * WFRAG_PER_L2, wfl + l2b * WFRAG_PER_L2,
            b1 + i * DIM,
            gamma + i * DIM, beta + i * DIM, rmean + i * DIM, rvar + i * DIM,
            b2 + i * DIM,
            batch, pooled, i * DIM, hh);
    }

    fin1_kernel<<<N_GRAPHS, DCAT>>>(pooled, Wfin, bfin, hfin);
    fin2_kernel<<<N_GRAPHS, 32>>>(hfin, Wout, bout, out, out_size);
}

// round 11
// speedup vs baseline: 3.0348x; 1.0317x over previous
#include <cuda_runtime.h>
#include <cuda_fp16.h>
#include <math.h>

#define N_NODES  100000
#define N_EDGES  3200000
#define N_GRAPHS 512
#define DIM      128
#define NLAYERS  3
#define DCAT     384
#define NCLS     10
#define BN_EPS   1e-5f

#define M_TILES  6252           // ceil(100000/16)
#define SCAN_NB  98             // ceil(100000/1024)

// Scratch (device globals; no allocations allowed)
__device__ float g_aggr[N_NODES * DIM];
__device__ __half g_hh[N_NODES * DIM];     // fp16 shadow of h (gather input)
__device__ float g_pooled[N_GRAPHS * DCAT];
__device__ float g_hfin[N_GRAPHS * DCAT];
// CSR scratch
__device__ int g_counts[N_NODES + 4];
__device__ int g_rowstart[N_NODES + 4];
__device__ int g_cursor[N_NODES + 4];
__device__ int g_col[N_EDGES];
__device__ int g_bsum[SCAN_NB + 4];
// fp16 weight fragments (m16n8k16 B layout): [l2(6)][w(16)][kt(8)][lane(32)]
#define WFRAG_PER_L2 (16 * 8 * 32)
__device__ uint2 g_wfh[6 * WFRAG_PER_L2];
__device__ uint2 g_wfl[6 * WFRAG_PER_L2];

__global__ void zero_kernel(float4* __restrict__ p, int n4) {
    int i = blockIdx.x * blockDim.x + threadIdx.x;
    int stride = gridDim.x * blockDim.x;
    float4 z = make_float4(0.f, 0.f, 0.f, 0.f);
    for (; i < n4; i += stride) p[i] = z;
}

__global__ void zero_int_kernel(int* __restrict__ p, int n) {
    int i = blockIdx.x * blockDim.x + threadIdx.x;
    if (i < n) p[i] = 0;
}

// Convert x (fp32) -> fp16 shadow.
__global__ void x2h_kernel(const float2* __restrict__ x, __half2* __restrict__ hh) {
    int i = blockIdx.x * blockDim.x + threadIdx.x;
    if (i < N_NODES * DIM / 2) hh[i] = __float22half2_rn(__ldg(&x[i]));
}

// ---------------- CSR build (counting sort of edges by dst) ----------------
__global__ void hist_kernel(const int* __restrict__ ei, int* __restrict__ counts) {
    int e = blockIdx.x * blockDim.x + threadIdx.x;
    if (e < N_EDGES) atomicAdd(&counts[__ldg(&ei[N_EDGES + e])], 1);
}

__global__ void __launch_bounds__(1024) scan1_kernel(
        const int* __restrict__ counts, int* __restrict__ rowstart,
        int* __restrict__ bsum) {
    __shared__ int wsum[32];
    int t = threadIdx.x;
    int i = blockIdx.x * 1024 + t;
    int c = (i < N_NODES) ? __ldg(&counts[i]) : 0;
    int v = c;
#pragma unroll
    for (int off = 1; off < 32; off <<= 1) {
        int u = __shfl_up_sync(0xFFFFFFFFu, v, off);
        if ((t & 31) >= off) v += u;
    }
    if ((t & 31) == 31) wsum[t >> 5] = v;
    __syncthreads();
    if (t < 32) {
        int w = wsum[t];
#pragma unroll
        for (int off = 1; off < 32; off <<= 1) {
            int u = __shfl_up_sync(0xFFFFFFFFu, w, off);
            if (t >= off) w += u;
        }
        wsum[t] = w;
    }
    __syncthreads();
    int excl = v - c + ((t >= 32) ? wsum[(t >> 5) - 1] : 0);
    if (i < N_NODES) rowstart[i] = excl;
    if (t == 1023) bsum[blockIdx.x] = excl + c;
}

__global__ void __launch_bounds__(32) scan2_kernel(int* __restrict__ bsum) {
    int t = threadIdx.x;
    int v[4];
    int part = 0;
#pragma unroll
    for (int j = 0; j < 4; j++) {
        int idx = t * 4 + j;
        v[j] = (idx < SCAN_NB) ? bsum[idx] : 0;
        part += v[j];
    }
    int p = part;
#pragma unroll
    for (int off = 1; off < 32; off <<= 1) {
        int u = __shfl_up_sync(0xFFFFFFFFu, p, off);
        if (t >= off) p += u;
    }
    int run = p - part;
#pragma unroll
    for (int j = 0; j < 4; j++) {
        int idx = t * 4 + j;
        if (idx < SCAN_NB) bsum[idx] = run;
        run += v[j];
    }
}

__global__ void __launch_bounds__(1024) scan3_kernel(
        const int* __restrict__ bsum, int* __restrict__ rowstart,
        int* __restrict__ cursor) {
    int i = blockIdx.x * 1024 + threadIdx.x;
    if (i < N_NODES) {
        int v = rowstart[i] + __ldg(&bsum[blockIdx.x]);
        rowstart[i] = v;
        cursor[i] = v;
    }
    if (i == 0) rowstart[N_NODES] = N_EDGES;
}

__global__ void fill_kernel(const int* __restrict__ ei,
                            int* __restrict__ cursor, int* __restrict__ col) {
    int e = blockIdx.x * blockDim.x + threadIdx.x;
    if (e >= N_EDGES) return;
    int s = __ldg(&ei[e]);
    int d = __ldg(&ei[N_EDGES + e]);
    int pos = atomicAdd(&cursor[d], 1);
    col[pos] = s;
}

// -------- Weight fragment precompute (fp16 hi/lo, m16n8k16 B layout) -------
__global__ void wfrag_kernel(const float* __restrict__ W1,
                             const float* __restrict__ W2,
                             uint2* __restrict__ wfh, uint2* __restrict__ wfl) {
    int idx = blockIdx.x * blockDim.x + threadIdx.x;
    if (idx >= 6 * WFRAG_PER_L2) return;
    int lane = idx & 31;
    int kt   = (idx >> 5) & 7;
    int w    = (idx >> 8) & 15;
    int l2   = idx >> 12;
    int g = lane >> 2, tg = lane & 3;
    int n = w * 8 + g;
    const float* Wm = (l2 & 1) ? (W2 + (l2 >> 1) * DIM * DIM)
                               : (W1 + (l2 >> 1) * DIM * DIM);
    unsigned rh[2], rl[2];
#pragma unroll
    for (int j = 0; j < 2; j++) {
        int k0 = kt * 16 + j * 8 + tg * 2;
        float v0 = __ldg(&Wm[k0 * DIM + n]);
        float v1 = __ldg(&Wm[(k0 + 1) * DIM + n]);
        __half h0 = __float2half_rn(v0);
        __half h1 = __float2half_rn(v1);
        __half l0 = __float2half_rn(v0 - __half2float(h0));
        __half l1 = __float2half_rn(v1 - __half2float(h1));
        __half2 ph = __halves2half2(h0, h1);
        __half2 pl = __halves2half2(l0, l1);
        rh[j] = *(unsigned*)&ph;
        rl[j] = *(unsigned*)&pl;
    }
    wfh[idx] = make_uint2(rh[0], rh[1]);
    wfl[idx] = make_uint2(rl[0], rl[1]);
}

// ---------------- Gather (fp16 rows): aggr[n] = h[n] + sum h[s] ------------
// Half-warp per node, LDG.128 per lane; neighbor batches of 8 reduced with a
// packed HADD2 tree (7 HADD2/slot), one cvt+add per group partial.
__device__ __forceinline__ void acc_addh2(float* acc, __half2 vx, __half2 vy,
                                          __half2 vz, __half2 vw) {
    float2 f0 = __half22float2(vx);
    float2 f1 = __half22float2(vy);
    float2 f2 = __half22float2(vz);
    float2 f3 = __half22float2(vw);
    acc[0] += f0.x; acc[1] += f0.y; acc[2] += f1.x; acc[3] += f1.y;
    acc[4] += f2.x; acc[5] += f2.y; acc[6] += f3.x; acc[7] += f3.y;
}
#define H2(u) (*(__half2*)&(u))

__global__ void __launch_bounds__(256) gather_kernel(
        const __half* __restrict__ hh,
        const int* __restrict__ rowstart, const int* __restrict__ col,
        float* __restrict__ aggr) {
    unsigned gw = (blockIdx.x * 256u + threadIdx.x) >> 5;
    int lane = threadIdx.x & 31;
    int l16 = lane & 15;
    unsigned n = gw * 2 + (lane >> 4);
    if (n >= N_NODES) return;
    int beg = __ldg(&rowstart[n]);
    int end = __ldg(&rowstart[n + 1]);

    // init acc = self row
    float acc[8];
    {
        uint4 r = __ldg((const uint4*)(hh + (long long)n * DIM) + l16);
        float2 f0 = __half22float2(H2(r.x));
        float2 f1 = __half22float2(H2(r.y));
        float2 f2 = __half22float2(H2(r.z));
        float2 f3 = __half22float2(H2(r.w));
        acc[0] = f0.x; acc[1] = f0.y; acc[2] = f1.x; acc[3] = f1.y;
        acc[4] = f2.x; acc[5] = f2.y; acc[6] = f3.x; acc[7] = f3.y;
    }

    int i = beg;
    for (; i + 8 <= end; i += 8) {
        uint4 r[8];
#pragma unroll
        for (int j = 0; j < 8; j++) {
            int s = __ldg(&col[i + j]);
            r[j] = __ldg((const uint4*)(hh + (long long)s * DIM) + l16);
        }
        // HADD2 tree per slot: ((r0+r1)+(r2+r3)) + ((r4+r5)+(r6+r7))
        __half2 sx = __hadd2(__hadd2(__hadd2(H2(r[0].x), H2(r[1].x)),
                                     __hadd2(H2(r[2].x), H2(r[3].x))),
                             __hadd2(__hadd2(H2(r[4].x), H2(r[5].x)),
                                     __hadd2(H2(r[6].x), H2(r[7].x))));
        __half2 sy = __hadd2(__hadd2(__hadd2(H2(r[0].y), H2(r[1].y)),
                                     __hadd2(H2(r[2].y), H2(r[3].y))),
                             __hadd2(__hadd2(H2(r[4].y), H2(r[5].y)),
                                     __hadd2(H2(r[6].y), H2(r[7].y))));
        __half2 sz = __hadd2(__hadd2(__hadd2(H2(r[0].z), H2(r[1].z)),
                                     __hadd2(H2(r[2].z), H2(r[3].z))),
                             __hadd2(__hadd2(H2(r[4].z), H2(r[5].z)),
                                     __hadd2(H2(r[6].z), H2(r[7].z))));
        __half2 sw = __hadd2(__hadd2(__hadd2(H2(r[0].w), H2(r[1].w)),
                                     __hadd2(H2(r[2].w), H2(r[3].w))),
                             __hadd2(__hadd2(H2(r[4].w), H2(r[5].w)),
                                     __hadd2(H2(r[6].w), H2(r[7].w))));
        acc_addh2(acc, sx, sy, sz, sw);
    }
    if (i + 4 <= end) {
        uint4 r[4];
#pragma unroll
        for (int j = 0; j < 4; j++) {
            int s = __ldg(&col[i + j]);
            r[j] = __ldg((const uint4*)(hh + (long long)s * DIM) + l16);
        }
        __half2 sx = __hadd2(__hadd2(H2(r[0].x), H2(r[1].x)),
                             __hadd2(H2(r[2].x), H2(r[3].x)));
        __half2 sy = __hadd2(__hadd2(H2(r[0].y), H2(r[1].y)),
                             __hadd2(H2(r[2].y), H2(r[3].y)));
        __half2 sz = __hadd2(__hadd2(H2(r[0].z), H2(r[1].z)),
                             __hadd2(H2(r[2].z), H2(r[3].z)));
        __half2 sw = __hadd2(__hadd2(H2(r[0].w), H2(r[1].w)),
                             __hadd2(H2(r[2].w), H2(r[3].w)));
        acc_addh2(acc, sx, sy, sz, sw);
        i += 4;
    }
    if (i + 2 <= end) {
        int s0 = __ldg(&col[i]);
        int s1 = __ldg(&col[i + 1]);
        uint4 r0 = __ldg((const uint4*)(hh + (long long)s0 * DIM) + l16);
        uint4 r1 = __ldg((const uint4*)(hh + (long long)s1 * DIM) + l16);
        acc_addh2(acc, __hadd2(H2(r0.x), H2(r1.x)), __hadd2(H2(r0.y), H2(r1.y)),
                  __hadd2(H2(r0.z), H2(r1.z)), __hadd2(H2(r0.w), H2(r1.w)));
        i += 2;
    }
    if (i < end) {
        int s = __ldg(&col[i]);
        uint4 r = __ldg((const uint4*)(hh + (long long)s * DIM) + l16);
        acc_addh2(acc, H2(r.x), H2(r.y), H2(r.z), H2(r.w));
    }

    float4* ap = (float4*)(aggr + (long long)n * DIM) + l16 * 2;
    ap[0] = make_float4(acc[0], acc[1], acc[2], acc[3]);
    ap[1] = make_float4(acc[4], acc[5], acc[6], acc[7]);
}

// -------- Fused layer MLP (fp16 hi/lo split, m16n8k16) ---------------------
#define MMA16816(C, A0, A1, A2, A3, B0, B1)                                   \
    asm volatile("mma.sync.aligned.m16n8k16.row.col.f32.f16.f16.f32 "         \
                 "{%0,%1,%2,%3}, {%4,%5,%6,%7}, {%8,%9}, {%0,%1,%2,%3};"      \
                 : "+f"(C[0]), "+f"(C[1]), "+f"(C[2]), "+f"(C[3])             \
                 : "r"(A0), "r"(A1), "r"(A2), "r"(A3), "r"(B0), "r"(B1))

#define LDSM4(R0, R1, R2, R3, ADDR)                                           \
    asm volatile("ldmatrix.sync.aligned.m8n8.x4.shared.b16 {%0,%1,%2,%3}, [%4];" \
                 : "=r"(R0), "=r"(R1), "=r"(R2), "=r"(R3) : "r"(ADDR))

#define ZSTR 136

__global__ void __launch_bounds__(512, 1) mlp_fused_kernel(
        const float* __restrict__ A,
        const uint2* __restrict__ w1h, const uint2* __restrict__ w1l,
        const uint2* __restrict__ w2h, const uint2* __restrict__ w2l,
        const float* __restrict__ b1,
        const float* __restrict__ gamma, const float* __restrict__ beta,
        const float* __restrict__ rmean, const float* __restrict__ rvar,
        const float* __restrict__ b2,
        const int* __restrict__ batch, float* __restrict__ pooled, int pool_off,
        __half* __restrict__ outh) {
    __shared__ __half Ah[2][16 * ZSTR];
    __shared__ __half Al[2][16 * ZSTR];
    __shared__ __half Zh[16 * ZSTR];
    __shared__ __half Zl[16 * ZSTR];

    int tid = threadIdx.x;
    int wid = tid >> 5;
    int lane = tid & 31;
    int g = lane >> 2, tg = lane & 3;

    int col0 = wid * 8 + tg * 2;
    float sc0 = __ldg(&gamma[col0]) * rsqrtf(__ldg(&rvar[col0]) + BN_EPS);
    float sh0 = __ldg(&beta[col0]) - __ldg(&rmean[col0]) * sc0
                + sc0 * __ldg(&b1[col0]);
    float sc1 = __ldg(&gamma[col0 + 1]) * rsqrtf(__ldg(&rvar[col0 + 1]) + BN_EPS);
    float sh1 = __ldg(&beta[col0 + 1]) - __ldg(&rmean[col0 + 1]) * sc1
                + sc1 * __ldg(&b1[col0 + 1]);
    float bb0 = __ldg(&b2[col0]), bb1 = __ldg(&b2[col0 + 1]);

    unsigned baseAh0, baseAh1, baseAl0, baseAl1, baseZh, baseZl;
    {
        unsigned off = (lane & 15) * (ZSTR * 2) + (lane >> 4) * 16;
        baseAh0 = (unsigned)__cvta_generic_to_shared(&Ah[0][0]) + off;
        baseAh1 = (unsigned)__cvta_generic_to_shared(&Ah[1][0]) + off;
        baseAl0 = (unsigned)__cvta_generic_to_shared(&Al[0][0]) + off;
        baseAl1 = (unsigned)__cvta_generic_to_shared(&Al[1][0]) + off;
        baseZh  = (unsigned)__cvta_generic_to_shared(&Zh[0]) + off;
        baseZl  = (unsigned)__cvta_generic_to_shared(&Zl[0]) + off;
    }

    int sr = wid;
    int sc4 = lane;

    float4 v = make_float4(0.f, 0.f, 0.f, 0.f);
    {
        int row = blockIdx.x * 16 + sr;
        if (blockIdx.x < M_TILES && row < N_NODES)
            v = __ldg((const float4*)(A + (long long)row * DIM) + sc4);
    }

    const uint2* w1hp = w1h + (wid * 8) * 32 + lane;
    const uint2* w1lp = w1l + (wid * 8) * 32 + lane;
    const uint2* w2hp = w2h + (wid * 8) * 32 + lane;
    const uint2* w2lp = w2l + (wid * 8) * 32 + lane;

    int buf = 0;
    for (int mt = blockIdx.x; mt < M_TILES; mt += gridDim.x) {
        {
            __half* ah = Ah[buf];
            __half* al = Al[buf];
            float vv[4] = {v.x, v.y, v.z, v.w};
            __half h[4], l[4];
#pragma unroll
            for (int j = 0; j < 4; j++) {
                h[j] = __float2half_rn(vv[j]);
                l[j] = __float2half_rn(vv[j] - __half2float(h[j]));
            }
            __half2* dsth = (__half2*)&ah[sr * ZSTR + sc4 * 4];
            __half2* dstl = (__half2*)&al[sr * ZSTR + sc4 * 4];
            dsth[0] = __halves2half2(h[0], h[1]);
            dsth[1] = __halves2half2(h[2], h[3]);
            dstl[0] = __halves2half2(l[0], l[1]);
            dstl[1] = __halves2half2(l[2], l[3]);
        }
        __syncthreads();

        int mtn = mt + gridDim.x;
        if (mtn < M_TILES) {
            int row = mtn * 16 + sr;
            v = (row < N_NODES)
                ? __ldg((const float4*)(A + (long long)row * DIM) + sc4)
                : make_float4(0.f, 0.f, 0.f, 0.f);
        }

        unsigned bah = buf ? baseAh1 : baseAh0;
        unsigned bal = buf ? baseAl1 : baseAl0;

        float cm[4] = {0.f, 0.f, 0.f, 0.f};
        float cc[4] = {0.f, 0.f, 0.f, 0.f};
#pragma unroll
        for (int kt = 0; kt < 8; kt++) {
            unsigned x0, x1, x2, x3, y0, y1, y2, y3;
            LDSM4(x0, x1, x2, x3, bah + kt * 32);
            LDSM4(y0, y1, y2, y3, bal + kt * 32);
            uint2 wh = __ldg(w1hp + kt * 32);
            uint2 wl = __ldg(w1lp + kt * 32);
            MMA16816(cm, x0, x1, x2, x3, wh.x, wh.y);
            MMA16816(cc, x0, x1, x2, x3, wl.x, wl.y);
            MMA16816(cc, y0, y1, y2, y3, wh.x, wh.y);
        }
        {
            float y00 = fmaxf(sc0 * (cm[0] + cc[0]) + sh0, 0.f);
            float y01 = fmaxf(sc1 * (cm[1] + cc[1]) + sh1, 0.f);
            float y10 = fmaxf(sc0 * (cm[2] + cc[2]) + sh0, 0.f);
            float y11 = fmaxf(sc1 * (cm[3] + cc[3]) + sh1, 0.f);
            __half h00 = __float2half_rn(y00);
            __half h01 = __float2half_rn(y01);
            __half h10 = __float2half_rn(y10);
            __half h11 = __float2half_rn(y11);
            *(__half2*)&Zh[g * ZSTR + col0] = __halves2half2(h00, h01);
            *(__half2*)&Zh[(g + 8) * ZSTR + col0] = __halves2half2(h10, h11);
            *(__half2*)&Zl[g * ZSTR + col0] = __halves2half2(
                __float2half_rn(y00 - __half2float(h00)),
                __float2half_rn(y01 - __half2float(h01)));
            *(__half2*)&Zl[(g + 8) * ZSTR + col0] = __halves2half2(
                __float2half_rn(y10 - __half2float(h10)),
                __float2half_rn(y11 - __half2float(h11)));
        }
        __syncthreads();

#pragma unroll
        for (int j = 0; j < 4; j++) { cm[j] = 0.f; cc[j] = 0.f; }
#pragma unroll
        for (int kt = 0; kt < 8; kt++) {
            unsigned x0, x1, x2, x3, y0, y1, y2, y3;
            LDSM4(x0, x1, x2, x3, baseZh + kt * 32);
            LDSM4(y0, y1, y2, y3, baseZl + kt * 32);
            uint2 wh = __ldg(w2hp + kt * 32);
            uint2 wl = __ldg(w2lp + kt * 32);
            MMA16816(cm, x0, x1, x2, x3, wh.x, wh.y);
            MMA16816(cc, x0, x1, x2, x3, wl.x, wl.y);
            MMA16816(cc, y0, y1, y2, y3, wh.x, wh.y);
        }
        {
            float y00 = fmaxf(cm[0] + cc[0] + bb0, 0.f);
            float y01 = fmaxf(cm[1] + cc[1] + bb1, 0.f);
            float y10 = fmaxf(cm[2] + cc[2] + bb0, 0.f);
            float y11 = fmaxf(cm[3] + cc[3] + bb1, 0.f);
            int r0 = mt * 16 + g;
            int r1 = r0 + 8;
            if (r0 < N_NODES) {
                *(__half2*)(outh + (long long)r0 * DIM + col0) =
                    __float22half2_rn(make_float2(y00, y01));
                int bi = __ldg(&batch[r0]);
                float* pb = pooled + bi * DCAT + pool_off + col0;
                asm volatile("red.global.add.v2.f32 [%0], {%1,%2};"
                             :: "l"(pb), "f"(y00), "f"(y01) : "memory");
            }
            if (r1 < N_NODES) {
                *(__half2*)(outh + (long long)r1 * DIM + col0) =
                    __float22half2_rn(make_float2(y10, y11));
                int bi = __ldg(&batch[r1]);
                float* pb = pooled + bi * DCAT + pool_off + col0;
                asm volatile("red.global.add.v2.f32 [%0], {%1,%2};"
                             :: "l"(pb), "f"(y10), "f"(y11) : "memory");
            }
        }
        buf ^= 1;
    }
}

// h_fin = relu(pooled @ Wfin + bfin)
__global__ void __launch_bounds__(DCAT) fin1_kernel(
        const float* __restrict__ pooled, const float* __restrict__ Wfin,
        const float* __restrict__ bfin, float* __restrict__ hfin) {
    __shared__ float s[DCAT];
    int g = blockIdx.x;
    int j = threadIdx.x;
    s[j] = pooled[g * DCAT + j];
    __syncthreads();
    float acc0 = 0.f, acc1 = 0.f, acc2 = 0.f, acc3 = 0.f;
#pragma unroll 4
    for (int k = 0; k < DCAT; k += 4) {
        acc0 += s[k + 0] * __ldg(&Wfin[(k + 0) * DCAT + j]);
        acc1 += s[k + 1] * __ldg(&Wfin[(k + 1) * DCAT + j]);
        acc2 += s[k + 2] * __ldg(&Wfin[(k + 2) * DCAT + j]);
        acc3 += s[k + 3] * __ldg(&Wfin[(k + 3) * DCAT + j]);
    }
    float acc = (acc0 + acc1) + (acc2 + acc3) + __ldg(&bfin[j]);
    hfin[g * DCAT + j] = fmaxf(acc, 0.f);
}

// logits + log_softmax: one warp per graph.
__global__ void __launch_bounds__(32) fin2_kernel(
        const float* __restrict__ hfin, const float* __restrict__ Wout,
        const float* __restrict__ bout, float* __restrict__ out, int out_size) {
    int g = blockIdx.x;
    int lane = threadIdx.x;
    bool valid = lane < NCLS;
    float acc = valid ? __ldg(&bout[lane]) : 0.f;
    for (int k = 0; k < DCAT; k++) {
        float v = __ldg(&hfin[g * DCAT + k]);
        if (valid) acc += v * __ldg(&Wout[k * NCLS + lane]);
    }
    float logit = acc;
    float m = valid ? logit : -INFINITY;
#pragma unroll
    for (int off = 16; off > 0; off >>= 1)
        m = fmaxf(m, __shfl_xor_sync(0xFFFFFFFFu, m, off));
    float e = valid ? expf(logit - m) : 0.f;
#pragma unroll
    for (int off = 16; off > 0; off >>= 1)
        e += __shfl_xor_sync(0xFFFFFFFFu, e, off);
    float ls = logit - m - logf(e);
    if (valid) {
        out[g * NCLS + lane] = logit;
        if (out_size >= 2 * N_GRAPHS * NCLS)
            out[N_GRAPHS * NCLS + g * NCLS + lane] = ls;
    }
}

extern "C" void kernel_launch(void* const* d_in, const int* in_sizes, int n_in,
                              void* d_out, int out_size) {
    const float* x        = (const float*)d_in[0];
    const int*   ei       = (const int*)d_in[1];
    const int*   batch    = (const int*)d_in[2];

    int w = 3;
    if (n_in >= 4 && in_sizes[3] == 1) w = 4;

    const float* W1   = (const float*)d_in[w + 0];
    const float* b1   = (const float*)d_in[w + 1];
    const float* gamma= (const float*)d_in[w + 2];
    const float* beta = (const float*)d_in[w + 3];
    const float* rmean= (const float*)d_in[w + 4];
    const float* rvar = (const float*)d_in[w + 5];
    const float* W2   = (const float*)d_in[w + 6];
    const float* b2   = (const float*)d_in[w + 7];
    const float* Wfin = (const float*)d_in[w + 8];
    const float* bfin = (const float*)d_in[w + 9];
    const float* Wout = (const float*)d_in[w + 10];
    const float* bout = (const float*)d_in[w + 11];
    float* out = (float*)d_out;

    float *aggr, *pooled, *hfin;
    __half* hh;
    uint2 *wfh, *wfl;
    int *counts, *rowstart, *cursor, *colbuf, *bsum;
    cudaGetSymbolAddress((void**)&aggr,     g_aggr);
    cudaGetSymbolAddress((void**)&hh,       g_hh);
    cudaGetSymbolAddress((void**)&pooled,   g_pooled);
    cudaGetSymbolAddress((void**)&hfin,     g_hfin);
    cudaGetSymbolAddress((void**)&counts,   g_counts);
    cudaGetSymbolAddress((void**)&rowstart, g_rowstart);
    cudaGetSymbolAddress((void**)&cursor,   g_cursor);
    cudaGetSymbolAddress((void**)&colbuf,   g_col);
    cudaGetSymbolAddress((void**)&bsum,     g_bsum);
    cudaGetSymbolAddress((void**)&wfh,      g_wfh);
    cudaGetSymbolAddress((void**)&wfl,      g_wfl);

    const int EB = (N_EDGES + 255) / 256;
    const int GB = ((N_NODES + 1) / 2 * 32 + 255) / 256;

    zero_int_kernel<<<(N_NODES + 4 + 255) / 256, 256>>>(counts, N_NODES + 4);
    zero_kernel<<<192, 256>>>((float4*)pooled, N_GRAPHS * DCAT / 4);
    x2h_kernel<<<(N_NODES * DIM / 2 + 255) / 256, 256>>>(
        (const float2*)x, (__half2*)hh);
    hist_kernel<<<EB, 256>>>(ei, counts);
    scan1_kernel<<<SCAN_NB, 1024>>>(counts, rowstart, bsum);
    scan2_kernel<<<1, 32>>>(bsum);
    scan3_kernel<<<SCAN_NB, 1024>>>(bsum, rowstart, cursor);
    fill_kernel<<<EB, 256>>>(ei, cursor, colbuf);
    wfrag_kernel<<<(6 * WFRAG_PER_L2 + 255) / 256, 256>>>(W1, W2, wfh, wfl);

    for (int i = 0; i < NLAYERS; i++) {
        gather_kernel<<<GB, 256>>>(hh, rowstart, colbuf, aggr);
        int l2a = i * 2, l2b = i * 2 + 1;
        mlp_fused_kernel<<<148, 512>>>(
            aggr,
            wfh + l2a * WFRAG_PER_L2, wfl + l2a * WFRAG_PER_L2,
            wfh + l2b * WFRAG_PER_L2, wfl + l2b * WFRAG_PER_L2,
            b1 + i * DIM,
            gamma + i * DIM, beta + i * DIM, rmean + i * DIM, rvar + i * DIM,
            b2 + i * DIM,
            batch, pooled, i * DIM, hh);
    }

    fin1_kernel<<<N_GRAPHS, DCAT>>>(pooled, Wfin, bfin, hfin);
    fin2_kernel<<<N_GRAPHS, 32>>>(hfin, Wout, bout, out, out_size);
}

// round 12
// speedup vs baseline: 3.2466x; 1.0698x over previous
#include <cuda_runtime.h>
#include <cuda_fp16.h>
#include <math.h>

#define N_NODES  100000
#define N_EDGES  3200000
#define N_GRAPHS 512
#define DIM      128
#define NLAYERS  3
#define DCAT     384
#define NCLS     10
#define BN_EPS   1e-5f

#define M_TILES  6252           // ceil(100000/16)
#define SCAN_NB  98             // ceil(100000/1024)

// Scratch (device globals; no allocations allowed)
__device__ __half g_aggrh[N_NODES * DIM];  // fp16 aggregation output
__device__ __half g_hh[N_NODES * DIM];     // fp16 shadow of h (gather input)
__device__ float g_pooled[N_GRAPHS * DCAT];
__device__ float g_hfin[N_GRAPHS * DCAT];
// CSR scratch
__device__ int g_counts[N_NODES + 4];
__device__ int g_rowstart[N_NODES + 4];
__device__ int g_cursor[N_NODES + 4];
__device__ int g_col[N_EDGES];
__device__ int g_bsum[SCAN_NB + 4];
// fp16 weight fragments (m16n8k16 B layout): [l2(6)][w(16)][kt(8)][lane(32)]
#define WFRAG_PER_L2 (16 * 8 * 32)
__device__ uint2 g_wfh[6 * WFRAG_PER_L2];
__device__ uint2 g_wfl[6 * WFRAG_PER_L2];

__global__ void zero_kernel(float4* __restrict__ p, int n4) {
    int i = blockIdx.x * blockDim.x + threadIdx.x;
    int stride = gridDim.x * blockDim.x;
    float4 z = make_float4(0.f, 0.f, 0.f, 0.f);
    for (; i < n4; i += stride) p[i] = z;
}

__global__ void zero_int_kernel(int* __restrict__ p, int n) {
    int i = blockIdx.x * blockDim.x + threadIdx.x;
    if (i < n) p[i] = 0;
}

// Convert x (fp32) -> fp16 shadow.
__global__ void x2h_kernel(const float2* __restrict__ x, __half2* __restrict__ hh) {
    int i = blockIdx.x * blockDim.x + threadIdx.x;
    if (i < N_NODES * DIM / 2) hh[i] = __float22half2_rn(__ldg(&x[i]));
}

// ---------------- CSR build (counting sort of edges by dst) ----------------
__global__ void hist_kernel(const int* __restrict__ ei, int* __restrict__ counts) {
    int e = blockIdx.x * blockDim.x + threadIdx.x;
    if (e < N_EDGES) atomicAdd(&counts[__ldg(&ei[N_EDGES + e])], 1);
}

__global__ void __launch_bounds__(1024) scan1_kernel(
        const int* __restrict__ counts, int* __restrict__ rowstart,
        int* __restrict__ bsum) {
    __shared__ int wsum[32];
    int t = threadIdx.x;
    int i = blockIdx.x * 1024 + t;
    int c = (i < N_NODES) ? __ldg(&counts[i]) : 0;
    int v = c;
#pragma unroll
    for (int off = 1; off < 32; off <<= 1) {
        int u = __shfl_up_sync(0xFFFFFFFFu, v, off);
        if ((t & 31) >= off) v += u;
    }
    if ((t & 31) == 31) wsum[t >> 5] = v;
    __syncthreads();
    if (t < 32) {
        int w = wsum[t];
#pragma unroll
        for (int off = 1; off < 32; off <<= 1) {
            int u = __shfl_up_sync(0xFFFFFFFFu, w, off);
            if (t >= off) w += u;
        }
        wsum[t] = w;
    }
    __syncthreads();
    int excl = v - c + ((t >= 32) ? wsum[(t >> 5) - 1] : 0);
    if (i < N_NODES) rowstart[i] = excl;
    if (t == 1023) bsum[blockIdx.x] = excl + c;
}

__global__ void __launch_bounds__(32) scan2_kernel(int* __restrict__ bsum) {
    int t = threadIdx.x;
    int v[4];
    int part = 0;
#pragma unroll
    for (int j = 0; j < 4; j++) {
        int idx = t * 4 + j;
        v[j] = (idx < SCAN_NB) ? bsum[idx] : 0;
        part += v[j];
    }
    int p = part;
#pragma unroll
    for (int off = 1; off < 32; off <<= 1) {
        int u = __shfl_up_sync(0xFFFFFFFFu, p, off);
        if (t >= off) p += u;
    }
    int run = p - part;
#pragma unroll
    for (int j = 0; j < 4; j++) {
        int idx = t * 4 + j;
        if (idx < SCAN_NB) bsum[idx] = run;
        run += v[j];
    }
}

__global__ void __launch_bounds__(1024) scan3_kernel(
        const int* __restrict__ bsum, int* __restrict__ rowstart,
        int* __restrict__ cursor) {
    int i = blockIdx.x * 1024 + threadIdx.x;
    if (i < N_NODES) {
        int v = rowstart[i] + __ldg(&bsum[blockIdx.x]);
        rowstart[i] = v;
        cursor[i] = v;
    }
    if (i == 0) rowstart[N_NODES] = N_EDGES;
}

__global__ void fill_kernel(const int* __restrict__ ei,
                            int* __restrict__ cursor, int* __restrict__ col) {
    int e = blockIdx.x * blockDim.x + threadIdx.x;
    if (e >= N_EDGES) return;
    int s = __ldg(&ei[e]);
    int d = __ldg(&ei[N_EDGES + e]);
    int pos = atomicAdd(&cursor[d], 1);
    col[pos] = s;
}

// -------- Weight fragment precompute (fp16 hi/lo, m16n8k16 B layout) -------
__global__ void wfrag_kernel(const float* __restrict__ W1,
                             const float* __restrict__ W2,
                             uint2* __restrict__ wfh, uint2* __restrict__ wfl) {
    int idx = blockIdx.x * blockDim.x + threadIdx.x;
    if (idx >= 6 * WFRAG_PER_L2) return;
    int lane = idx & 31;
    int kt   = (idx >> 5) & 7;
    int w    = (idx >> 8) & 15;
    int l2   = idx >> 12;
    int g = lane >> 2, tg = lane & 3;
    int n = w * 8 + g;
    const float* Wm = (l2 & 1) ? (W2 + (l2 >> 1) * DIM * DIM)
                               : (W1 + (l2 >> 1) * DIM * DIM);
    unsigned rh[2], rl[2];
#pragma unroll
    for (int j = 0; j < 2; j++) {
        int k0 = kt * 16 + j * 8 + tg * 2;
        float v0 = __ldg(&Wm[k0 * DIM + n]);
        float v1 = __ldg(&Wm[(k0 + 1) * DIM + n]);
        __half h0 = __float2half_rn(v0);
        __half h1 = __float2half_rn(v1);
        __half l0 = __float2half_rn(v0 - __half2float(h0));
        __half l1 = __float2half_rn(v1 - __half2float(h1));
        __half2 ph = __halves2half2(h0, h1);
        __half2 pl = __halves2half2(l0, l1);
        rh[j] = *(unsigned*)&ph;
        rl[j] = *(unsigned*)&pl;
    }
    wfh[idx] = make_uint2(rh[0], rh[1]);
    wfl[idx] = make_uint2(rl[0], rl[1]);
}

// ---------------- Gather (fp16 rows): aggrh[n] = h[n] + sum h[s] -----------
// Half-warp per node, LDG.128 per lane; HADD2 tree per 8-batch; fp32 acc;
// output rounded to fp16 and stored with streaming hint (evict-first).
__device__ __forceinline__ void acc_addh2(float* acc, __half2 vx, __half2 vy,
                                          __half2 vz, __half2 vw) {
    float2 f0 = __half22float2(vx);
    float2 f1 = __half22float2(vy);
    float2 f2 = __half22float2(vz);
    float2 f3 = __half22float2(vw);
    acc[0] += f0.x; acc[1] += f0.y; acc[2] += f1.x; acc[3] += f1.y;
    acc[4] += f2.x; acc[5] += f2.y; acc[6] += f3.x; acc[7] += f3.y;
}
#define H2(u) (*(__half2*)&(u))

__global__ void __launch_bounds__(256) gather_kernel(
        const __half* __restrict__ hh,
        const int* __restrict__ rowstart, const int* __restrict__ col,
        __half* __restrict__ aggrh) {
    unsigned gw = (blockIdx.x * 256u + threadIdx.x) >> 5;
    int lane = threadIdx.x & 31;
    int l16 = lane & 15;
    unsigned n = gw * 2 + (lane >> 4);
    if (n >= N_NODES) return;
    int beg = __ldg(&rowstart[n]);
    int end = __ldg(&rowstart[n + 1]);

    float acc[8];
    {
        uint4 r = __ldg((const uint4*)(hh + (long long)n * DIM) + l16);
        float2 f0 = __half22float2(H2(r.x));
        float2 f1 = __half22float2(H2(r.y));
        float2 f2 = __half22float2(H2(r.z));
        float2 f3 = __half22float2(H2(r.w));
        acc[0] = f0.x; acc[1] = f0.y; acc[2] = f1.x; acc[3] = f1.y;
        acc[4] = f2.x; acc[5] = f2.y; acc[6] = f3.x; acc[7] = f3.y;
    }

    int i = beg;
    for (; i + 8 <= end; i += 8) {
        uint4 r[8];
#pragma unroll
        for (int j = 0; j < 8; j++) {
            int s = __ldg(&col[i + j]);
            r[j] = __ldg((const uint4*)(hh + (long long)s * DIM) + l16);
        }
        __half2 sx = __hadd2(__hadd2(__hadd2(H2(r[0].x), H2(r[1].x)),
                                     __hadd2(H2(r[2].x), H2(r[3].x))),
                             __hadd2(__hadd2(H2(r[4].x), H2(r[5].x)),
                                     __hadd2(H2(r[6].x), H2(r[7].x))));
        __half2 sy = __hadd2(__hadd2(__hadd2(H2(r[0].y), H2(r[1].y)),
                                     __hadd2(H2(r[2].y), H2(r[3].y))),
                             __hadd2(__hadd2(H2(r[4].y), H2(r[5].y)),
                                     __hadd2(H2(r[6].y), H2(r[7].y))));
        __half2 sz = __hadd2(__hadd2(__hadd2(H2(r[0].z), H2(r[1].z)),
                                     __hadd2(H2(r[2].z), H2(r[3].z))),
                             __hadd2(__hadd2(H2(r[4].z), H2(r[5].z)),
                                     __hadd2(H2(r[6].z), H2(r[7].z))));
        __half2 sw = __hadd2(__hadd2(__hadd2(H2(r[0].w), H2(r[1].w)),
                                     __hadd2(H2(r[2].w), H2(r[3].w))),
                             __hadd2(__hadd2(H2(r[4].w), H2(r[5].w)),
                                     __hadd2(H2(r[6].w), H2(r[7].w))));
        acc_addh2(acc, sx, sy, sz, sw);
    }
    if (i + 4 <= end) {
        uint4 r[4];
#pragma unroll
        for (int j = 0; j < 4; j++) {
            int s = __ldg(&col[i + j]);
            r[j] = __ldg((const uint4*)(hh + (long long)s * DIM) + l16);
        }
        __half2 sx = __hadd2(__hadd2(H2(r[0].x), H2(r[1].x)),
                             __hadd2(H2(r[2].x), H2(r[3].x)));
        __half2 sy = __hadd2(__hadd2(H2(r[0].y), H2(r[1].y)),
                             __hadd2(H2(r[2].y), H2(r[3].y)));
        __half2 sz = __hadd2(__hadd2(H2(r[0].z), H2(r[1].z)),
                             __hadd2(H2(r[2].z), H2(r[3].z)));
        __half2 sw = __hadd2(__hadd2(H2(r[0].w), H2(r[1].w)),
                             __hadd2(H2(r[2].w), H2(r[3].w)));
        acc_addh2(acc, sx, sy, sz, sw);
        i += 4;
    }
    if (i + 2 <= end) {
        int s0 = __ldg(&col[i]);
        int s1 = __ldg(&col[i + 1]);
        uint4 r0 = __ldg((const uint4*)(hh + (long long)s0 * DIM) + l16);
        uint4 r1 = __ldg((const uint4*)(hh + (long long)s1 * DIM) + l16);
        acc_addh2(acc, __hadd2(H2(r0.x), H2(r1.x)), __hadd2(H2(r0.y), H2(r1.y)),
                  __hadd2(H2(r0.z), H2(r1.z)), __hadd2(H2(r0.w), H2(r1.w)));
        i += 2;
    }
    if (i < end) {
        int s = __ldg(&col[i]);
        uint4 r = __ldg((const uint4*)(hh + (long long)s * DIM) + l16);
        acc_addh2(acc, H2(r.x), H2(r.y), H2(r.z), H2(r.w));
    }

    // round to fp16, store streaming (evict-first: don't pollute L2)
    __half2 p0 = __float22half2_rn(make_float2(acc[0], acc[1]));
    __half2 p1 = __float22half2_rn(make_float2(acc[2], acc[3]));
    __half2 p2 = __float22half2_rn(make_float2(acc[4], acc[5]));
    __half2 p3 = __float22half2_rn(make_float2(acc[6], acc[7]));
    uint4 o;
    o.x = *(unsigned*)&p0; o.y = *(unsigned*)&p1;
    o.z = *(unsigned*)&p2; o.w = *(unsigned*)&p3;
    __stcs((uint4*)(aggrh + (long long)n * DIM) + l16, o);
}

// -------- Fused layer MLP (A fp16 direct; W fp16 hi/lo; m16n8k16) ----------
#define MMA16816(C, A0, A1, A2, A3, B0, B1)                                   \
    asm volatile("mma.sync.aligned.m16n8k16.row.col.f32.f16.f16.f32 "         \
                 "{%0,%1,%2,%3}, {%4,%5,%6,%7}, {%8,%9}, {%0,%1,%2,%3};"      \
                 : "+f"(C[0]), "+f"(C[1]), "+f"(C[2]), "+f"(C[3])             \
                 : "r"(A0), "r"(A1), "r"(A2), "r"(A3), "r"(B0), "r"(B1))

#define LDSM4(R0, R1, R2, R3, ADDR)                                           \
    asm volatile("ldmatrix.sync.aligned.m8n8.x4.shared.b16 {%0,%1,%2,%3}, [%4];" \
                 : "=r"(R0), "=r"(R1), "=r"(R2), "=r"(R3) : "r"(ADDR))

#define ZSTR 136

__global__ void __launch_bounds__(512, 1) mlp_fused_kernel(
        const __half* __restrict__ A,
        const uint2* __restrict__ w1h, const uint2* __restrict__ w1l,
        const uint2* __restrict__ w2h, const uint2* __restrict__ w2l,
        const float* __restrict__ b1,
        const float* __restrict__ gamma, const float* __restrict__ beta,
        const float* __restrict__ rmean, const float* __restrict__ rvar,
        const float* __restrict__ b2,
        const int* __restrict__ batch, float* __restrict__ pooled, int pool_off,
        __half* __restrict__ outh) {
    __shared__ __half Ah[2][16 * ZSTR];
    __shared__ __half Zh[16 * ZSTR];
    __shared__ __half Zl[16 * ZSTR];

    int tid = threadIdx.x;
    int wid = tid >> 5;
    int lane = tid & 31;
    int g = lane >> 2, tg = lane & 3;

    int col0 = wid * 8 + tg * 2;
    float sc0 = __ldg(&gamma[col0]) * rsqrtf(__ldg(&rvar[col0]) + BN_EPS);
    float sh0 = __ldg(&beta[col0]) - __ldg(&rmean[col0]) * sc0
                + sc0 * __ldg(&b1[col0]);
    float sc1 = __ldg(&gamma[col0 + 1]) * rsqrtf(__ldg(&rvar[col0 + 1]) + BN_EPS);
    float sh1 = __ldg(&beta[col0 + 1]) - __ldg(&rmean[col0 + 1]) * sc1
                + sc1 * __ldg(&b1[col0 + 1]);
    float bb0 = __ldg(&b2[col0]), bb1 = __ldg(&b2[col0 + 1]);

    unsigned baseAh0, baseAh1, baseZh, baseZl;
    {
        unsigned off = (lane & 15) * (ZSTR * 2) + (lane >> 4) * 16;
        baseAh0 = (unsigned)__cvta_generic_to_shared(&Ah[0][0]) + off;
        baseAh1 = (unsigned)__cvta_generic_to_shared(&Ah[1][0]) + off;
        baseZh  = (unsigned)__cvta_generic_to_shared(&Zh[0]) + off;
        baseZl  = (unsigned)__cvta_generic_to_shared(&Zl[0]) + off;
    }

    int sr = wid;        // warp stages row sr
    int sc4 = lane;      // lane owns halfs [4*lane, 4*lane+4)

    uint2 v = make_uint2(0u, 0u);
    {
        int row = blockIdx.x * 16 + sr;
        if (blockIdx.x < M_TILES && row < N_NODES)
            v = __ldcs((const uint2*)(A + (long long)row * DIM) + sc4);
    }

    const uint2* w1hp = w1h + (wid * 8) * 32 + lane;
    const uint2* w1lp = w1l + (wid * 8) * 32 + lane;
    const uint2* w2hp = w2h + (wid * 8) * 32 + lane;
    const uint2* w2lp = w2l + (wid * 8) * 32 + lane;

    int buf = 0;
    for (int mt = blockIdx.x; mt < M_TILES; mt += gridDim.x) {
        // stage A tile (already fp16 — direct copy)
        *(uint2*)&Ah[buf][sr * ZSTR + sc4 * 4] = v;
        __syncthreads();

        int mtn = mt + gridDim.x;
        if (mtn < M_TILES) {
            int row = mtn * 16 + sr;
            v = (row < N_NODES)
                ? __ldcs((const uint2*)(A + (long long)row * DIM) + sc4)
                : make_uint2(0u, 0u);
        }

        unsigned bah = buf ? baseAh1 : baseAh0;

        // ---- MLP1: z = BN(aggr @ W1 + b1), ReLU.  A exact fp16; W hi+lo ----
        float cm[4] = {0.f, 0.f, 0.f, 0.f};
        float cc[4] = {0.f, 0.f, 0.f, 0.f};
#pragma unroll
        for (int kt = 0; kt < 8; kt++) {
            unsigned x0, x1, x2, x3;
            LDSM4(x0, x1, x2, x3, bah + kt * 32);
            uint2 wh = __ldg(w1hp + kt * 32);
            uint2 wl = __ldg(w1lp + kt * 32);
            MMA16816(cm, x0, x1, x2, x3, wh.x, wh.y);
            MMA16816(cc, x0, x1, x2, x3, wl.x, wl.y);
        }
        {
            float y00 = fmaxf(sc0 * (cm[0] + cc[0]) + sh0, 0.f);
            float y01 = fmaxf(sc1 * (cm[1] + cc[1]) + sh1, 0.f);
            float y10 = fmaxf(sc0 * (cm[2] + cc[2]) + sh0, 0.f);
            float y11 = fmaxf(sc1 * (cm[3] + cc[3]) + sh1, 0.f);
            __half h00 = __float2half_rn(y00);
            __half h01 = __float2half_rn(y01);
            __half h10 = __float2half_rn(y10);
            __half h11 = __float2half_rn(y11);
            *(__half2*)&Zh[g * ZSTR + col0] = __halves2half2(h00, h01);
            *(__half2*)&Zh[(g + 8) * ZSTR + col0] = __halves2half2(h10, h11);
            *(__half2*)&Zl[g * ZSTR + col0] = __halves2half2(
                __float2half_rn(y00 - __half2float(h00)),
                __float2half_rn(y01 - __half2float(h01)));
            *(__half2*)&Zl[(g + 8) * ZSTR + col0] = __halves2half2(
                __float2half_rn(y10 - __half2float(h10)),
                __float2half_rn(y11 - __half2float(h11)));
        }
        __syncthreads();

        // ---- MLP2: h = ReLU(z @ W2 + b2).  z hi/lo split; W hi+lo ----
#pragma unroll
        for (int j = 0; j < 4; j++) { cm[j] = 0.f; cc[j] = 0.f; }
#pragma unroll
        for (int kt = 0; kt < 8; kt++) {
            unsigned x0, x1, x2, x3, y0, y1, y2, y3;
            LDSM4(x0, x1, x2, x3, baseZh + kt * 32);
            LDSM4(y0, y1, y2, y3, baseZl + kt * 32);
            uint2 wh = __ldg(w2hp + kt * 32);
            uint2 wl = __ldg(w2lp + kt * 32);
            MMA16816(cm, x0, x1, x2, x3, wh.x, wh.y);
            MMA16816(cc, x0, x1, x2, x3, wl.x, wl.y);
            MMA16816(cc, y0, y1, y2, y3, wh.x, wh.y);
        }
        {
            float y00 = fmaxf(cm[0] + cc[0] + bb0, 0.f);
            float y01 = fmaxf(cm[1] + cc[1] + bb1, 0.f);
            float y10 = fmaxf(cm[2] + cc[2] + bb0, 0.f);
            float y11 = fmaxf(cm[3] + cc[3] + bb1, 0.f);
            int r0 = mt * 16 + g;
            int r1 = r0 + 8;
            if (r0 < N_NODES) {
                *(__half2*)(outh + (long long)r0 * DIM + col0) =
                    __float22half2_rn(make_float2(y00, y01));
                int bi = __ldg(&batch[r0]);
                float* pb = pooled + bi * DCAT + pool_off + col0;
                asm volatile("red.global.add.v2.f32 [%0], {%1,%2};"
                             :: "l"(pb), "f"(y00), "f"(y01) : "memory");
            }
            if (r1 < N_NODES) {
                *(__half2*)(outh + (long long)r1 * DIM + col0) =
                    __float22half2_rn(make_float2(y10, y11));
                int bi = __ldg(&batch[r1]);
                float* pb = pooled + bi * DCAT + pool_off + col0;
                asm volatile("red.global.add.v2.f32 [%0], {%1,%2};"
                             :: "l"(pb), "f"(y10), "f"(y11) : "memory");
            }
        }
        buf ^= 1;
    }
}

// h_fin = relu(pooled @ Wfin + bfin)
__global__ void __launch_bounds__(DCAT) fin1_kernel(
        const float* __restrict__ pooled, const float* __restrict__ Wfin,
        const float* __restrict__ bfin, float* __restrict__ hfin) {
    __shared__ float s[DCAT];
    int g = blockIdx.x;
    int j = threadIdx.x;
    s[j] = pooled[g * DCAT + j];
    __syncthreads();
    float acc0 = 0.f, acc1 = 0.f, acc2 = 0.f, acc3 = 0.f;
#pragma unroll 4
    for (int k = 0; k < DCAT; k += 4) {
        acc0 += s[k + 0] * __ldg(&Wfin[(k + 0) * DCAT + j]);
        acc1 += s[k + 1] * __ldg(&Wfin[(k + 1) * DCAT + j]);
        acc2 += s[k + 2] * __ldg(&Wfin[(k + 2) * DCAT + j]);
        acc3 += s[k + 3] * __ldg(&Wfin[(k + 3) * DCAT + j]);
    }
    float acc = (acc0 + acc1) + (acc2 + acc3) + __ldg(&bfin[j]);
    hfin[g * DCAT + j] = fmaxf(acc, 0.f);
}

// logits + log_softmax: one warp per graph.
__global__ void __launch_bounds__(32) fin2_kernel(
        const float* __restrict__ hfin, const float* __restrict__ Wout,
        const float* __restrict__ bout, float* __restrict__ out, int out_size) {
    int g = blockIdx.x;
    int lane = threadIdx.x;
    bool valid = lane < NCLS;
    float acc = valid ? __ldg(&bout[lane]) : 0.f;
    for (int k = 0; k < DCAT; k++) {
        float v = __ldg(&hfin[g * DCAT + k]);
        if (valid) acc += v * __ldg(&Wout[k * NCLS + lane]);
    }
    float logit = acc;
    float m = valid ? logit : -INFINITY;
#pragma unroll
    for (int off = 16; off > 0; off >>= 1)
        m = fmaxf(m, __shfl_xor_sync(0xFFFFFFFFu, m, off));
    float e = valid ? expf(logit - m) : 0.f;
#pragma unroll
    for (int off = 16; off > 0; off >>= 1)
        e += __shfl_xor_sync(0xFFFFFFFFu, e, off);
    float ls = logit - m - logf(e);
    if (valid) {
        out[g * NCLS + lane] = logit;
        if (out_size >= 2 * N_GRAPHS * NCLS)
            out[N_GRAPHS * NCLS + g * NCLS + lane] = ls;
    }
}

extern "C" void kernel_launch(void* const* d_in, const int* in_sizes, int n_in,
                              void* d_out, int out_size) {
    const float* x        = (const float*)d_in[0];
    const int*   ei       = (const int*)d_in[1];
    const int*   batch    = (const int*)d_in[2];

    int w = 3;
    if (n_in >= 4 && in_sizes[3] == 1) w = 4;

    const float* W1   = (const float*)d_in[w + 0];
    const float* b1   = (const float*)d_in[w + 1];
    const float* gamma= (const float*)d_in[w + 2];
    const float* beta = (const float*)d_in[w + 3];
    const float* rmean= (const float*)d_in[w + 4];
    const float* rvar = (const float*)d_in[w + 5];
    const float* W2   = (const float*)d_in[w + 6];
    const float* b2   = (const float*)d_in[w + 7];
    const float* Wfin = (const float*)d_in[w + 8];
    const float* bfin = (const float*)d_in[w + 9];
    const float* Wout = (const float*)d_in[w + 10];
    const float* bout = (const float*)d_in[w + 11];
    float* out = (float*)d_out;

    float *pooled, *hfin;
    __half *hh, *aggrh;
    uint2 *wfh, *wfl;
    int *counts, *rowstart, *cursor, *colbuf, *bsum;
    cudaGetSymbolAddress((void**)&aggrh,    g_aggrh);
    cudaGetSymbolAddress((void**)&hh,       g_hh);
    cudaGetSymbolAddress((void**)&pooled,   g_pooled);
    cudaGetSymbolAddress((void**)&hfin,     g_hfin);
    cudaGetSymbolAddress((void**)&counts,   g_counts);
    cudaGetSymbolAddress((void**)&rowstart, g_rowstart);
    cudaGetSymbolAddress((void**)&cursor,   g_cursor);
    cudaGetSymbolAddress((void**)&colbuf,   g_col);
    cudaGetSymbolAddress((void**)&bsum,     g_bsum);
    cudaGetSymbolAddress((void**)&wfh,      g_wfh);
    cudaGetSymbolAddress((void**)&wfl,      g_wfl);

    const int EB = (N_EDGES + 255) / 256;
    const int GB = ((N_NODES + 1) / 2 * 32 + 255) / 256;

    zero_int_kernel<<<(N_NODES + 4 + 255) / 256, 256>>>(counts, N_NODES + 4);
    zero_kernel<<<192, 256>>>((float4*)pooled, N_GRAPHS * DCAT / 4);
    x2h_kernel<<<(N_NODES * DIM / 2 + 255) / 256, 256>>>(
        (const float2*)x, (__half2*)hh);
    hist_kernel<<<EB, 256>>>(ei, counts);
    scan1_kernel<<<SCAN_NB, 1024>>>(counts, rowstart, bsum);
    scan2_kernel<<<1, 32>>>(bsum);
    scan3_kernel<<<SCAN_NB, 1024>>>(bsum, rowstart, cursor);
    fill_kernel<<<EB, 256>>>(ei, cursor, colbuf);
    wfrag_kernel<<<(6 * WFRAG_PER_L2 + 255) / 256, 256>>>(W1, W2, wfh, wfl);

    for (int i = 0; i < NLAYERS; i++) {
        gather_kernel<<<GB, 256>>>(hh, rowstart, colbuf, aggrh);
        int l2a = i * 2, l2b = i * 2 + 1;
        mlp_fused_kernel<<<148, 512>>>(
            aggrh,
            wfh + l2a * WFRAG_PER_L2, wfl + l2a * WFRAG_PER_L2,
            wfh + l2b * WFRAG_PER_L2, wfl + l2b * WFRAG_PER_L2,
            b1 + i * DIM,
            gamma + i * DIM, beta + i * DIM, rmean + i * DIM, rvar + i * DIM,
            b2 + i * DIM,
            batch, pooled, i * DIM, hh);
    }

    fin1_kernel<<<N_GRAPHS, DCAT>>>(pooled, Wfin, bfin, hfin);
    fin2_kernel<<<N_GRAPHS, 32>>>(hfin, Wout, bout, out, out_size);
}

// round 13
// speedup vs baseline: 3.4652x; 1.0673x over previous
#include <cuda_runtime.h>
#include <cuda_fp16.h>
#include <math.h>

#define N_NODES  100000
#define N_EDGES  3200000
#define N_GRAPHS 512
#define DIM      128
#define NLAYERS  3
#define DCAT     384
#define NCLS     10
#define BN_EPS   1e-5f

#define M_TILES  6252           // ceil(100000/16)
#define SCAN_NB  98             // ceil(100000/1024)
#define COL_CAP  (N_EDGES + 8 * N_NODES)   // padded CSR capacity

// Scratch (device globals; no allocations allowed)
__device__ __half g_aggrh[N_NODES * DIM];        // fp16 aggregation output
__device__ __half g_hh[(N_NODES + 1) * DIM];     // fp16 h (+1 zero sentinel row)
__device__ float g_pooled[N_GRAPHS * DCAT];
__device__ float g_hfin[N_GRAPHS * DCAT];
// CSR scratch
__device__ int g_counts[N_NODES + 4];
__device__ int g_rowstart[N_NODES + 4];
__device__ int g_cursor[N_NODES + 4];
__device__ int g_col[COL_CAP];
__device__ int g_bsum[SCAN_NB + 4];
// fp16 weight fragments (m16n8k16 B layout): [l2(6)][w(16)][kt(8)][lane(32)]
#define WFRAG_PER_L2 (16 * 8 * 32)
__device__ uint2 g_wfh[6 * WFRAG_PER_L2];
__device__ uint2 g_wfl[6 * WFRAG_PER_L2];

__global__ void zero_kernel(float4* __restrict__ p, int n4) {
    int i = blockIdx.x * blockDim.x + threadIdx.x;
    int stride = gridDim.x * blockDim.x;
    float4 z = make_float4(0.f, 0.f, 0.f, 0.f);
    for (; i < n4; i += stride) p[i] = z;
}

__global__ void zero_int_kernel(int* __restrict__ p, int n) {
    int i = blockIdx.x * blockDim.x + threadIdx.x;
    if (i < n) p[i] = 0;
}

// Convert x (fp32) -> fp16 shadow; 4 floats per thread.
__global__ void x2h_kernel(const float4* __restrict__ x, uint2* __restrict__ hh) {
    int i = blockIdx.x * blockDim.x + threadIdx.x;
    if (i >= N_NODES * DIM / 4) return;
    float4 v = __ldg(&x[i]);
    __half2 a = __float22half2_rn(make_float2(v.x, v.y));
    __half2 b = __float22half2_rn(make_float2(v.z, v.w));
    hh[i] = make_uint2(*(unsigned*)&a, *(unsigned*)&b);
}

// ---------------- CSR build (counting sort of edges by dst) ----------------
// 4 edges per thread (int4 loads).
__global__ void hist_kernel(const int* __restrict__ ei, int* __restrict__ counts) {
    int i = blockIdx.x * blockDim.x + threadIdx.x;
    int e = i * 4;
    if (e + 4 <= N_EDGES) {
        int4 d = __ldg((const int4*)(ei + N_EDGES + e));
        atomicAdd(&counts[d.x], 1);
        atomicAdd(&counts[d.y], 1);
        atomicAdd(&counts[d.z], 1);
        atomicAdd(&counts[d.w], 1);
    } else {
        for (int j = e; j < N_EDGES; j++)
            atomicAdd(&counts[__ldg(&ei[N_EDGES + j])], 1);
    }
}

// Phase 1: per-block exclusive scan of PADDED counts (pad to multiple of 8).
__global__ void __launch_bounds__(1024) scan1_kernel(
        const int* __restrict__ counts, int* __restrict__ rowstart,
        int* __restrict__ bsum) {
    __shared__ int wsum[32];
    int t = threadIdx.x;
    int i = blockIdx.x * 1024 + t;
    int c = (i < N_NODES) ? ((__ldg(&counts[i]) + 7) & ~7) : 0;
    int v = c;
#pragma unroll
    for (int off = 1; off < 32; off <<= 1) {
        int u = __shfl_up_sync(0xFFFFFFFFu, v, off);
        if ((t & 31) >= off) v += u;
    }
    if ((t & 31) == 31) wsum[t >> 5] = v;
    __syncthreads();
    if (t < 32) {
        int w = wsum[t];
#pragma unroll
        for (int off = 1; off < 32; off <<= 1) {
            int u = __shfl_up_sync(0xFFFFFFFFu, w, off);
            if (t >= off) w += u;
        }
        wsum[t] = w;
    }
    __syncthreads();
    int excl = v - c + ((t >= 32) ? wsum[(t >> 5) - 1] : 0);
    if (i < N_NODES) rowstart[i] = excl;
    if (t == 1023) bsum[blockIdx.x] = excl + c;
}

__global__ void __launch_bounds__(32) scan2_kernel(int* __restrict__ bsum) {
    int t = threadIdx.x;
    int v[4];
    int part = 0;
#pragma unroll
    for (int j = 0; j < 4; j++) {
        int idx = t * 4 + j;
        v[j] = (idx < SCAN_NB) ? bsum[idx] : 0;
        part += v[j];
    }
    int p = part;
#pragma unroll
    for (int off = 1; off < 32; off <<= 1) {
        int u = __shfl_up_sync(0xFFFFFFFFu, p, off);
        if (t >= off) p += u;
    }
    int run = p - part;
#pragma unroll
    for (int j = 0; j < 4; j++) {
        int idx = t * 4 + j;
        if (idx < SCAN_NB) bsum[idx] = run;
        run += v[j];
    }
    if (t == 31) bsum[SCAN_NB] = run;   // total padded edges
}

__global__ void __launch_bounds__(1024) scan3_kernel(
        const int* __restrict__ bsum, int* __restrict__ rowstart,
        int* __restrict__ cursor) {
    int i = blockIdx.x * 1024 + threadIdx.x;
    if (i < N_NODES) {
        int v = rowstart[i] + __ldg(&bsum[blockIdx.x]);
        rowstart[i] = v;
        cursor[i] = v;
    }
    if (i == 0) rowstart[N_NODES] = bsum[SCAN_NB];
}

// Fill pad slots with sentinel N_NODES (zero row).  One thread per node.
__global__ void pad_kernel(const int* __restrict__ counts,
                           const int* __restrict__ rowstart,
                           int* __restrict__ col) {
    int n = blockIdx.x * blockDim.x + threadIdx.x;
    if (n >= N_NODES) return;
    int c = __ldg(&counts[n]);
    int pc = (c + 7) & ~7;
    int base = __ldg(&rowstart[n]) + c;
    for (int j = 0; j < pc - c; j++) col[base + j] = N_NODES;
}

// 4 edges per thread (int4 loads).
__global__ void fill_kernel(const int* __restrict__ ei,
                            int* __restrict__ cursor, int* __restrict__ col) {
    int i = blockIdx.x * blockDim.x + threadIdx.x;
    int e = i * 4;
    if (e + 4 <= N_EDGES) {
        int4 s = __ldg((const int4*)(ei + e));
        int4 d = __ldg((const int4*)(ei + N_EDGES + e));
        col[atomicAdd(&cursor[d.x], 1)] = s.x;
        col[atomicAdd(&cursor[d.y], 1)] = s.y;
        col[atomicAdd(&cursor[d.z], 1)] = s.z;
        col[atomicAdd(&cursor[d.w], 1)] = s.w;
    } else {
        for (int j = e; j < N_EDGES; j++) {
            int s = __ldg(&ei[j]);
            int d = __ldg(&ei[N_EDGES + j]);
            col[atomicAdd(&cursor[d], 1)] = s;
        }
    }
}

// -------- Weight fragment precompute (fp16 hi/lo, m16n8k16 B layout) -------
__global__ void wfrag_kernel(const float* __restrict__ W1,
                             const float* __restrict__ W2,
                             uint2* __restrict__ wfh, uint2* __restrict__ wfl) {
    int idx = blockIdx.x * blockDim.x + threadIdx.x;
    if (idx >= 6 * WFRAG_PER_L2) return;
    int lane = idx & 31;
    int kt   = (idx >> 5) & 7;
    int w    = (idx >> 8) & 15;
    int l2   = idx >> 12;
    int g = lane >> 2, tg = lane & 3;
    int n = w * 8 + g;
    const float* Wm = (l2 & 1) ? (W2 + (l2 >> 1) * DIM * DIM)
                               : (W1 + (l2 >> 1) * DIM * DIM);
    unsigned rh[2], rl[2];
#pragma unroll
    for (int j = 0; j < 2; j++) {
        int k0 = kt * 16 + j * 8 + tg * 2;
        float v0 = __ldg(&Wm[k0 * DIM + n]);
        float v1 = __ldg(&Wm[(k0 + 1) * DIM + n]);
        __half h0 = __float2half_rn(v0);
        __half h1 = __float2half_rn(v1);
        __half l0 = __float2half_rn(v0 - __half2float(h0));
        __half l1 = __float2half_rn(v1 - __half2float(h1));
        __half2 ph = __halves2half2(h0, h1);
        __half2 pl = __halves2half2(l0, l1);
        rh[j] = *(unsigned*)&ph;
        rl[j] = *(unsigned*)&pl;
    }
    wfh[idx] = make_uint2(rh[0], rh[1]);
    wfl[idx] = make_uint2(rl[0], rl[1]);
}

// ---------------- Gather (fp16 rows): aggrh[n] = h[n] + sum h[s] -----------
// Half-warp per node; LDG.128 per lane; padded segments (multiple of 8, no
// tails); col indices via 2 aligned LDG.128; HADD2 tree; fp32 acc.
__device__ __forceinline__ void acc_addh2(float* acc, __half2 vx, __half2 vy,
                                          __half2 vz, __half2 vw) {
    float2 f0 = __half22float2(vx);
    float2 f1 = __half22float2(vy);
    float2 f2 = __half22float2(vz);
    float2 f3 = __half22float2(vw);
    acc[0] += f0.x; acc[1] += f0.y; acc[2] += f1.x; acc[3] += f1.y;
    acc[4] += f2.x; acc[5] += f2.y; acc[6] += f3.x; acc[7] += f3.y;
}
#define H2(u) (*(__half2*)&(u))

__global__ void __launch_bounds__(256) gather_kernel(
        const __half* __restrict__ hh,
        const int* __restrict__ rowstart, const int* __restrict__ col,
        __half* __restrict__ aggrh) {
    unsigned gw = (blockIdx.x * 256u + threadIdx.x) >> 5;
    int lane = threadIdx.x & 31;
    int l16 = lane & 15;
    unsigned n = gw * 2 + (lane >> 4);
    if (n >= N_NODES) return;
    int beg = __ldg(&rowstart[n]);
    int end = __ldg(&rowstart[n + 1]);

    float acc[8];
    {
        uint4 r = __ldg((const uint4*)(hh + (long long)n * DIM) + l16);
        float2 f0 = __half22float2(H2(r.x));
        float2 f1 = __half22float2(H2(r.y));
        float2 f2 = __half22float2(H2(r.z));
        float2 f3 = __half22float2(H2(r.w));
        acc[0] = f0.x; acc[1] = f0.y; acc[2] = f1.x; acc[3] = f1.y;
        acc[4] = f2.x; acc[5] = f2.y; acc[6] = f3.x; acc[7] = f3.y;
    }

    for (int i = beg; i < end; i += 8) {
        int4 c0 = __ldg((const int4*)(col + i));
        int4 c1 = __ldg((const int4*)(col + i + 4));
        uint4 r[8];
        r[0] = __ldg((const uint4*)(hh + (long long)c0.x * DIM) + l16);
        r[1] = __ldg((const uint4*)(hh + (long long)c0.y * DIM) + l16);
        r[2] = __ldg((const uint4*)(hh + (long long)c0.z * DIM) + l16);
        r[3] = __ldg((const uint4*)(hh + (long long)c0.w * DIM) + l16);
        r[4] = __ldg((const uint4*)(hh + (long long)c1.x * DIM) + l16);
        r[5] = __ldg((const uint4*)(hh + (long long)c1.y * DIM) + l16);
        r[6] = __ldg((const uint4*)(hh + (long long)c1.z * DIM) + l16);
        r[7] = __ldg((const uint4*)(hh + (long long)c1.w * DIM) + l16);
        __half2 sx = __hadd2(__hadd2(__hadd2(H2(r[0].x), H2(r[1].x)),
                                     __hadd2(H2(r[2].x), H2(r[3].x))),
                             __hadd2(__hadd2(H2(r[4].x), H2(r[5].x)),
                                     __hadd2(H2(r[6].x), H2(r[7].x))));
        __half2 sy = __hadd2(__hadd2(__hadd2(H2(r[0].y), H2(r[1].y)),
                                     __hadd2(H2(r[2].y), H2(r[3].y))),
                             __hadd2(__hadd2(H2(r[4].y), H2(r[5].y)),
                                     __hadd2(H2(r[6].y), H2(r[7].y))));
        __half2 sz = __hadd2(__hadd2(__hadd2(H2(r[0].z), H2(r[1].z)),
                                     __hadd2(H2(r[2].z), H2(r[3].z))),
                             __hadd2(__hadd2(H2(r[4].z), H2(r[5].z)),
                                     __hadd2(H2(r[6].z), H2(r[7].z))));
        __half2 sw = __hadd2(__hadd2(__hadd2(H2(r[0].w), H2(r[1].w)),
                                     __hadd2(H2(r[2].w), H2(r[3].w))),
                             __hadd2(__hadd2(H2(r[4].w), H2(r[5].w)),
                                     __hadd2(H2(r[6].w), H2(r[7].w))));
        acc_addh2(acc, sx, sy, sz, sw);
    }

    __half2 p0 = __float22half2_rn(make_float2(acc[0], acc[1]));
    __half2 p1 = __float22half2_rn(make_float2(acc[2], acc[3]));
    __half2 p2 = __float22half2_rn(make_float2(acc[4], acc[5]));
    __half2 p3 = __float22half2_rn(make_float2(acc[6], acc[7]));
    uint4 o;
    o.x = *(unsigned*)&p0; o.y = *(unsigned*)&p1;
    o.z = *(unsigned*)&p2; o.w = *(unsigned*)&p3;
    __stcs((uint4*)(aggrh + (long long)n * DIM) + l16, o);
}

// -------- Fused layer MLP (A fp16 direct; W fp16 hi/lo; m16n8k16) ----------
#define MMA16816(C, A0, A1, A2, A3, B0, B1)                                   \
    asm volatile("mma.sync.aligned.m16n8k16.row.col.f32.f16.f16.f32 "         \
                 "{%0,%1,%2,%3}, {%4,%5,%6,%7}, {%8,%9}, {%0,%1,%2,%3};"      \
                 : "+f"(C[0]), "+f"(C[1]), "+f"(C[2]), "+f"(C[3])             \
                 : "r"(A0), "r"(A1), "r"(A2), "r"(A3), "r"(B0), "r"(B1))

#define LDSM4(R0, R1, R2, R3, ADDR)                                           \
    asm volatile("ldmatrix.sync.aligned.m8n8.x4.shared.b16 {%0,%1,%2,%3}, [%4];" \
                 : "=r"(R0), "=r"(R1), "=r"(R2), "=r"(R3) : "r"(ADDR))

#define ZSTR 136

__global__ void __launch_bounds__(512, 1) mlp_fused_kernel(
        const __half* __restrict__ A,
        const uint2* __restrict__ w1h, const uint2* __restrict__ w1l,
        const uint2* __restrict__ w2h, const uint2* __restrict__ w2l,
        const float* __restrict__ b1,
        const float* __restrict__ gamma, const float* __restrict__ beta,
        const float* __restrict__ rmean, const float* __restrict__ rvar,
        const float* __restrict__ b2,
        const int* __restrict__ batch, float* __restrict__ pooled, int pool_off,
        __half* __restrict__ outh) {
    __shared__ __half Ah[2][16 * ZSTR];
    __shared__ __half Zh[16 * ZSTR];

    int tid = threadIdx.x;
    int wid = tid >> 5;
    int lane = tid & 31;
    int g = lane >> 2, tg = lane & 3;

    int col0 = wid * 8 + tg * 2;
    float sc0 = __ldg(&gamma[col0]) * rsqrtf(__ldg(&rvar[col0]) + BN_EPS);
    float sh0 = __ldg(&beta[col0]) - __ldg(&rmean[col0]) * sc0
                + sc0 * __ldg(&b1[col0]);
    float sc1 = __ldg(&gamma[col0 + 1]) * rsqrtf(__ldg(&rvar[col0 + 1]) + BN_EPS);
    float sh1 = __ldg(&beta[col0 + 1]) - __ldg(&rmean[col0 + 1]) * sc1
                + sc1 * __ldg(&b1[col0 + 1]);
    float bb0 = __ldg(&b2[col0]), bb1 = __ldg(&b2[col0 + 1]);

    unsigned baseAh0, baseAh1, baseZh;
    {
        unsigned off = (lane & 15) * (ZSTR * 2) + (lane >> 4) * 16;
        baseAh0 = (unsigned)__cvta_generic_to_shared(&Ah[0][0]) + off;
        baseAh1 = (unsigned)__cvta_generic_to_shared(&Ah[1][0]) + off;
        baseZh  = (unsigned)__cvta_generic_to_shared(&Zh[0]) + off;
    }

    int sr = wid;
    int sc4 = lane;

    uint2 v = make_uint2(0u, 0u);
    {
        int row = blockIdx.x * 16 + sr;
        if (blockIdx.x < M_TILES && row < N_NODES)
            v = __ldcs((const uint2*)(A + (long long)row * DIM) + sc4);
    }

    const uint2* w1hp = w1h + (wid * 8) * 32 + lane;
    const uint2* w1lp = w1l + (wid * 8) * 32 + lane;
    const uint2* w2hp = w2h + (wid * 8) * 32 + lane;
    const uint2* w2lp = w2l + (wid * 8) * 32 + lane;

    int buf = 0;
    for (int mt = blockIdx.x; mt < M_TILES; mt += gridDim.x) {
        *(uint2*)&Ah[buf][sr * ZSTR + sc4 * 4] = v;
        __syncthreads();

        int mtn = mt + gridDim.x;
        if (mtn < M_TILES) {
            int row = mtn * 16 + sr;
            v = (row < N_NODES)
                ? __ldcs((const uint2*)(A + (long long)row * DIM) + sc4)
                : make_uint2(0u, 0u);
        }

        unsigned bah = buf ? baseAh1 : baseAh0;

        // ---- MLP1: z = BN(aggr @ W1 + b1), ReLU.  A exact fp16; W hi+lo ----
        float cm[4] = {0.f, 0.f, 0.f, 0.f};
        float cc[4] = {0.f, 0.f, 0.f, 0.f};
#pragma unroll
        for (int kt = 0; kt < 8; kt++) {
            unsigned x0, x1, x2, x3;
            LDSM4(x0, x1, x2, x3, bah + kt * 32);
            uint2 wh = __ldg(w1hp + kt * 32);
            uint2 wl = __ldg(w1lp + kt * 32);
            MMA16816(cm, x0, x1, x2, x3, wh.x, wh.y);
            MMA16816(cc, x0, x1, x2, x3, wl.x, wl.y);
        }
        {
            float y00 = fmaxf(sc0 * (cm[0] + cc[0]) + sh0, 0.f);
            float y01 = fmaxf(sc1 * (cm[1] + cc[1]) + sh1, 0.f);
            float y10 = fmaxf(sc0 * (cm[2] + cc[2]) + sh0, 0.f);
            float y11 = fmaxf(sc1 * (cm[3] + cc[3]) + sh1, 0.f);
            *(__half2*)&Zh[g * ZSTR + col0] =
                __float22half2_rn(make_float2(y00, y01));
            *(__half2*)&Zh[(g + 8) * ZSTR + col0] =
                __float22half2_rn(make_float2(y10, y11));
        }
        __syncthreads();

        // ---- MLP2: h = ReLU(z @ W2 + b2).  z fp16 (lo dropped); W hi+lo ----
#pragma unroll
        for (int j = 0; j < 4; j++) { cm[j] = 0.f; cc[j] = 0.f; }
#pragma unroll
        for (int kt = 0; kt < 8; kt++) {
            unsigned x0, x1, x2, x3;
            LDSM4(x0, x1, x2, x3, baseZh + kt * 32);
            uint2 wh = __ldg(w2hp + kt * 32);
            uint2 wl = __ldg(w2lp + kt * 32);
            MMA16816(cm, x0, x1, x2, x3, wh.x, wh.y);
            MMA16816(cc, x0, x1, x2, x3, wl.x, wl.y);
        }
        {
            float y00 = fmaxf(cm[0] + cc[0] + bb0, 0.f);
            float y01 = fmaxf(cm[1] + cc[1] + bb1, 0.f);
            float y10 = fmaxf(cm[2] + cc[2] + bb0, 0.f);
            float y11 = fmaxf(cm[3] + cc[3] + bb1, 0.f);
            int r0 = mt * 16 + g;
            int r1 = r0 + 8;
            if (r0 < N_NODES) {
                *(__half2*)(outh + (long long)r0 * DIM + col0) =
                    __float22half2_rn(make_float2(y00, y01));
                int bi = __ldg(&batch[r0]);
                float* pb = pooled + bi * DCAT + pool_off + col0;
                asm volatile("red.global.add.v2.f32 [%0], {%1,%2};"
                             :: "l"(pb), "f"(y00), "f"(y01) : "memory");
            }
            if (r1 < N_NODES) {
                *(__half2*)(outh + (long long)r1 * DIM + col0) =
                    __float22half2_rn(make_float2(y10, y11));
                int bi = __ldg(&batch[r1]);
                float* pb = pooled + bi * DCAT + pool_off + col0;
                asm volatile("red.global.add.v2.f32 [%0], {%1,%2};"
                             :: "l"(pb), "f"(y10), "f"(y11) : "memory");
            }
        }
        buf ^= 1;
    }
}

// h_fin = relu(pooled @ Wfin + bfin)
__global__ void __launch_bounds__(DCAT) fin1_kernel(
        const float* __restrict__ pooled, const float* __restrict__ Wfin,
        const float* __restrict__ bfin, float* __restrict__ hfin) {
    __shared__ float s[DCAT];
    int g = blockIdx.x;
    int j = threadIdx.x;
    s[j] = pooled[g * DCAT + j];
    __syncthreads();
    float acc0 = 0.f, acc1 = 0.f, acc2 = 0.f, acc3 = 0.f;
#pragma unroll 4
    for (int k = 0; k < DCAT; k += 4) {
        acc0 += s[k + 0] * __ldg(&Wfin[(k + 0) * DCAT + j]);
        acc1 += s[k + 1] * __ldg(&Wfin[(k + 1) * DCAT + j]);
        acc2 += s[k + 2] * __ldg(&Wfin[(k + 2) * DCAT + j]);
        acc3 += s[k + 3] * __ldg(&Wfin[(k + 3) * DCAT + j]);
    }
    float acc = (acc0 + acc1) + (acc2 + acc3) + __ldg(&bfin[j]);
    hfin[g * DCAT + j] = fmaxf(acc, 0.f);
}

// logits + log_softmax: one warp per graph.
__global__ void __launch_bounds__(32) fin2_kernel(
        const float* __restrict__ hfin, const float* __restrict__ Wout,
        const float* __restrict__ bout, float* __restrict__ out, int out_size) {
    int g = blockIdx.x;
    int lane = threadIdx.x;
    bool valid = lane < NCLS;
    float acc = valid ? __ldg(&bout[lane]) : 0.f;
    for (int k = 0; k < DCAT; k++) {
        float v = __ldg(&hfin[g * DCAT + k]);
        if (valid) acc += v * __ldg(&Wout[k * NCLS + lane]);
    }
    float logit = acc;
    float m = valid ? logit : -INFINITY;
#pragma unroll
    for (int off = 16; off > 0; off >>= 1)
        m = fmaxf(m, __shfl_xor_sync(0xFFFFFFFFu, m, off));
    float e = valid ? expf(logit - m) : 0.f;
#pragma unroll
    for (int off = 16; off > 0; off >>= 1)
        e += __shfl_xor_sync(0xFFFFFFFFu, e, off);
    float ls = logit - m - logf(e);
    if (valid) {
        out[g * NCLS + lane] = logit;
        if (out_size >= 2 * N_GRAPHS * NCLS)
            out[N_GRAPHS * NCLS + g * NCLS + lane] = ls;
    }
}

extern "C" void kernel_launch(void* const* d_in, const int* in_sizes, int n_in,
                              void* d_out, int out_size) {
    const float* x        = (const float*)d_in[0];
    const int*   ei       = (const int*)d_in[1];
    const int*   batch    = (const int*)d_in[2];

    int w = 3;
    if (n_in >= 4 && in_sizes[3] == 1) w = 4;

    const float* W1   = (const float*)d_in[w + 0];
    const float* b1   = (const float*)d_in[w + 1];
    const float* gamma= (const float*)d_in[w + 2];
    const float* beta = (const float*)d_in[w + 3];
    const float* rmean= (const float*)d_in[w + 4];
    const float* rvar = (const float*)d_in[w + 5];
    const float* W2   = (const float*)d_in[w + 6];
    const float* b2   = (const float*)d_in[w + 7];
    const float* Wfin = (const float*)d_in[w + 8];
    const float* bfin = (const float*)d_in[w + 9];
    const float* Wout = (const float*)d_in[w + 10];
    const float* bout = (const float*)d_in[w + 11];
    float* out = (float*)d_out;

    float *pooled, *hfin;
    __half *hh, *aggrh;
    uint2 *wfh, *wfl;
    int *counts, *rowstart, *cursor, *colbuf, *bsum;
    cudaGetSymbolAddress((void**)&aggrh,    g_aggrh);
    cudaGetSymbolAddress((void**)&hh,       g_hh);
    cudaGetSymbolAddress((void**)&pooled,   g_pooled);
    cudaGetSymbolAddress((void**)&hfin,     g_hfin);
    cudaGetSymbolAddress((void**)&counts,   g_counts);
    cudaGetSymbolAddress((void**)&rowstart, g_rowstart);
    cudaGetSymbolAddress((void**)&cursor,   g_cursor);
    cudaGetSymbolAddress((void**)&colbuf,   g_col);
    cudaGetSymbolAddress((void**)&bsum,     g_bsum);
    cudaGetSymbolAddress((void**)&wfh,      g_wfh);
    cudaGetSymbolAddress((void**)&wfl,      g_wfl);

    const int E4B = (N_EDGES / 4 + 255) / 256;           // 4 edges/thread
    const int GB = ((N_NODES + 1) / 2 * 32 + 255) / 256;

    zero_int_kernel<<<(N_NODES + 4 + 255) / 256, 256>>>(counts, N_NODES + 4);
    zero_kernel<<<192, 256>>>((float4*)pooled, N_GRAPHS * DCAT / 4);
    // zero sentinel row (hh row N_NODES) — 256B
    zero_kernel<<<1, 16>>>((float4*)(hh + (long long)N_NODES * DIM), 16);
    x2h_kernel<<<(N_NODES * DIM / 4 + 255) / 256, 256>>>(
        (const float4*)x, (uint2*)hh);
    hist_kernel<<<E4B, 256>>>(ei, counts);
    scan1_kernel<<<SCAN_NB, 1024>>>(counts, rowstart, bsum);
    scan2_kernel<<<1, 32>>>(bsum);
    scan3_kernel<<<SCAN_NB, 1024>>>(bsum, rowstart, cursor);
    pad_kernel<<<(N_NODES + 255) / 256, 256>>>(counts, rowstart, colbuf);
    fill_kernel<<<E4B, 256>>>(ei, cursor, colbuf);
    wfrag_kernel<<<(6 * WFRAG_PER_L2 + 255) / 256, 256>>>(W1, W2, wfh, wfl);

    for (int i = 0; i < NLAYERS; i++) {
        gather_kernel<<<GB, 256>>>(hh, rowstart, colbuf, aggrh);
        int l2a = i * 2, l2b = i * 2 + 1;
        mlp_fused_kernel<<<148, 512>>>(
            aggrh,
            wfh + l2a * WFRAG_PER_L2, wfl + l2a * WFRAG_PER_L2,
            wfh + l2b * WFRAG_PER_L2, wfl + l2b * WFRAG_PER_L2,
            b1 + i * DIM,
            gamma + i * DIM, beta + i * DIM, rmean + i * DIM, rvar + i * DIM,
            b2 + i * DIM,
            batch, pooled, i * DIM, hh);
    }

    fin1_kernel<<<N_GRAPHS, DCAT>>>(pooled, Wfin, bfin, hfin);
    fin2_kernel<<<N_GRAPHS, 32>>>(hfin, Wout, bout, out, out_size);
}

// round 14
// speedup vs baseline: 3.6510x; 1.0536x over previous
#include <cuda_runtime.h>
#include <cuda_fp16.h>
#include <math.h>

#define N_NODES  100000
#define N_EDGES  3200000
#define N_GRAPHS 512
#define DIM      128
#define NLAYERS  3
#define DCAT     384
#define NCLS     10
#define BN_EPS   1e-5f

#define M_TILES  6252           // ceil(100000/16)
#define SCAN_NB  98             // ceil(100000/1024)
#define COL_CAP  (N_EDGES + 8 * N_NODES)   // padded CSR capacity

// Scratch (device globals; no allocations allowed)
__device__ __half g_hh0[(N_NODES + 1) * DIM];   // fp16 h ping (+ zero sentinel)
__device__ __half g_hh1[(N_NODES + 1) * DIM];   // fp16 h pong (+ zero sentinel)
__device__ float g_pooled[N_GRAPHS * DCAT];
__device__ float g_hfin[N_GRAPHS * DCAT];
// CSR scratch
__device__ int g_counts[N_NODES + 4];
__device__ int g_rowstart[N_NODES + 4];
__device__ int g_cursor[N_NODES + 4];
__device__ int g_col[COL_CAP];
__device__ int g_bsum[SCAN_NB + 4];
// fp16 weight fragments (m16n8k16 B layout): [l2(6)][w(16)][kt(8)][lane(32)]
#define WFRAG_PER_L2 (16 * 8 * 32)
__device__ uint2 g_wfh[6 * WFRAG_PER_L2];
__device__ uint2 g_wfl[6 * WFRAG_PER_L2];

__global__ void zero_kernel(float4* __restrict__ p, int n4) {
    int i = blockIdx.x * blockDim.x + threadIdx.x;
    int stride = gridDim.x * blockDim.x;
    float4 z = make_float4(0.f, 0.f, 0.f, 0.f);
    for (; i < n4; i += stride) p[i] = z;
}

__global__ void zero_int_kernel(int* __restrict__ p, int n) {
    int i = blockIdx.x * blockDim.x + threadIdx.x;
    if (i < n) p[i] = 0;
}

// Convert x (fp32) -> fp16 shadow; 4 floats per thread.
__global__ void x2h_kernel(const float4* __restrict__ x, uint2* __restrict__ hh) {
    int i = blockIdx.x * blockDim.x + threadIdx.x;
    if (i >= N_NODES * DIM / 4) return;
    float4 v = __ldg(&x[i]);
    __half2 a = __float22half2_rn(make_float2(v.x, v.y));
    __half2 b = __float22half2_rn(make_float2(v.z, v.w));
    hh[i] = make_uint2(*(unsigned*)&a, *(unsigned*)&b);
}

// ---------------- CSR build (counting sort of edges by dst) ----------------
__global__ void hist_kernel(const int* __restrict__ ei, int* __restrict__ counts) {
    int i = blockIdx.x * blockDim.x + threadIdx.x;
    int e = i * 4;
    if (e + 4 <= N_EDGES) {
        int4 d = __ldg((const int4*)(ei + N_EDGES + e));
        atomicAdd(&counts[d.x], 1);
        atomicAdd(&counts[d.y], 1);
        atomicAdd(&counts[d.z], 1);
        atomicAdd(&counts[d.w], 1);
    } else {
        for (int j = e; j < N_EDGES; j++)
            atomicAdd(&counts[__ldg(&ei[N_EDGES + j])], 1);
    }
}

// Phase 1: per-block exclusive scan of PADDED counts (pad to multiple of 8).
__global__ void __launch_bounds__(1024) scan1_kernel(
        const int* __restrict__ counts, int* __restrict__ rowstart,
        int* __restrict__ bsum) {
    __shared__ int wsum[32];
    int t = threadIdx.x;
    int i = blockIdx.x * 1024 + t;
    int c = (i < N_NODES) ? ((__ldg(&counts[i]) + 7) & ~7) : 0;
    int v = c;
#pragma unroll
    for (int off = 1; off < 32; off <<= 1) {
        int u = __shfl_up_sync(0xFFFFFFFFu, v, off);
        if ((t & 31) >= off) v += u;
    }
    if ((t & 31) == 31) wsum[t >> 5] = v;
    __syncthreads();
    if (t < 32) {
        int w = wsum[t];
#pragma unroll
        for (int off = 1; off < 32; off <<= 1) {
            int u = __shfl_up_sync(0xFFFFFFFFu, w, off);
            if (t >= off) w += u;
        }
        wsum[t] = w;
    }
    __syncthreads();
    int excl = v - c + ((t >= 32) ? wsum[(t >> 5) - 1] : 0);
    if (i < N_NODES) rowstart[i] = excl;
    if (t == 1023) bsum[blockIdx.x] = excl + c;
}

__global__ void __launch_bounds__(32) scan2_kernel(int* __restrict__ bsum) {
    int t = threadIdx.x;
    int v[4];
    int part = 0;
#pragma unroll
    for (int j = 0; j < 4; j++) {
        int idx = t * 4 + j;
        v[j] = (idx < SCAN_NB) ? bsum[idx] : 0;
        part += v[j];
    }
    int p = part;
#pragma unroll
    for (int off = 1; off < 32; off <<= 1) {
        int u = __shfl_up_sync(0xFFFFFFFFu, p, off);
        if (t >= off) p += u;
    }
    int run = p - part;
#pragma unroll
    for (int j = 0; j < 4; j++) {
        int idx = t * 4 + j;
        if (idx < SCAN_NB) bsum[idx] = run;
        run += v[j];
    }
    if (t == 31) bsum[SCAN_NB] = run;   // total padded edges
}

__global__ void __launch_bounds__(1024) scan3_kernel(
        const int* __restrict__ bsum, int* __restrict__ rowstart,
        int* __restrict__ cursor) {
    int i = blockIdx.x * 1024 + threadIdx.x;
    if (i < N_NODES) {
        int v = rowstart[i] + __ldg(&bsum[blockIdx.x]);
        rowstart[i] = v;
        cursor[i] = v;
    }
    if (i == 0) rowstart[N_NODES] = bsum[SCAN_NB];
}

// Fill pad slots with sentinel N_NODES (zero row).
__global__ void pad_kernel(const int* __restrict__ counts,
                           const int* __restrict__ rowstart,
                           int* __restrict__ col) {
    int n = blockIdx.x * blockDim.x + threadIdx.x;
    if (n >= N_NODES) return;
    int c = __ldg(&counts[n]);
    int pc = (c + 7) & ~7;
    int base = __ldg(&rowstart[n]) + c;
    for (int j = 0; j < pc - c; j++) col[base + j] = N_NODES;
}

__global__ void fill_kernel(const int* __restrict__ ei,
                            int* __restrict__ cursor, int* __restrict__ col) {
    int i = blockIdx.x * blockDim.x + threadIdx.x;
    int e = i * 4;
    if (e + 4 <= N_EDGES) {
        int4 s = __ldg((const int4*)(ei + e));
        int4 d = __ldg((const int4*)(ei + N_EDGES + e));
        col[atomicAdd(&cursor[d.x], 1)] = s.x;
        col[atomicAdd(&cursor[d.y], 1)] = s.y;
        col[atomicAdd(&cursor[d.z], 1)] = s.z;
        col[atomicAdd(&cursor[d.w], 1)] = s.w;
    } else {
        for (int j = e; j < N_EDGES; j++) {
            int s = __ldg(&ei[j]);
            int d = __ldg(&ei[N_EDGES + j]);
            col[atomicAdd(&cursor[d], 1)] = s;
        }
    }
}

// -------- Weight fragment precompute (fp16 hi/lo, m16n8k16 B layout) -------
__global__ void wfrag_kernel(const float* __restrict__ W1,
                             const float* __restrict__ W2,
                             uint2* __restrict__ wfh, uint2* __restrict__ wfl) {
    int idx = blockIdx.x * blockDim.x + threadIdx.x;
    if (idx >= 6 * WFRAG_PER_L2) return;
    int lane = idx & 31;
    int kt   = (idx >> 5) & 7;
    int w    = (idx >> 8) & 15;
    int l2   = idx >> 12;
    int g = lane >> 2, tg = lane & 3;
    int n = w * 8 + g;
    const float* Wm = (l2 & 1) ? (W2 + (l2 >> 1) * DIM * DIM)
                               : (W1 + (l2 >> 1) * DIM * DIM);
    unsigned rh[2], rl[2];
#pragma unroll
    for (int j = 0; j < 2; j++) {
        int k0 = kt * 16 + j * 8 + tg * 2;
        float v0 = __ldg(&Wm[k0 * DIM + n]);
        float v1 = __ldg(&Wm[(k0 + 1) * DIM + n]);
        __half h0 = __float2half_rn(v0);
        __half h1 = __float2half_rn(v1);
        __half l0 = __float2half_rn(v0 - __half2float(h0));
        __half l1 = __float2half_rn(v1 - __half2float(h1));
        __half2 ph = __halves2half2(h0, h1);
        __half2 pl = __halves2half2(l0, l1);
        rh[j] = *(unsigned*)&ph;
        rl[j] = *(unsigned*)&pl;
    }
    wfh[idx] = make_uint2(rh[0], rh[1]);
    wfl[idx] = make_uint2(rl[0], rl[1]);
}

// ==================== FUSED LAYER: gather + MLP1 + MLP2 ====================
// 256 threads, occupancy 2 (overlap gather-LSU of one block with MMA of the
// co-resident block). Grid-stride over 16-row tiles.
//   gather: 16 half-warps, one per tile row; HADD2 tree; fp16 -> Ah smem.
//   MLP1:   8 warps, warp w owns cols [16w,16w+16) (2 B-frag groups).
//   MLP2:   same; outputs to hout (fp16) + pooled atomics.
#define MMA16816(C, A0, A1, A2, A3, B0, B1)                                   \
    asm volatile("mma.sync.aligned.m16n8k16.row.col.f32.f16.f16.f32 "         \
                 "{%0,%1,%2,%3}, {%4,%5,%6,%7}, {%8,%9}, {%0,%1,%2,%3};"      \
                 : "+f"(C[0]), "+f"(C[1]), "+f"(C[2]), "+f"(C[3])             \
                 : "r"(A0), "r"(A1), "r"(A2), "r"(A3), "r"(B0), "r"(B1))

#define LDSM4(R0, R1, R2, R3, ADDR)                                           \
    asm volatile("ldmatrix.sync.aligned.m8n8.x4.shared.b16 {%0,%1,%2,%3}, [%4];" \
                 : "=r"(R0), "=r"(R1), "=r"(R2), "=r"(R3) : "r"(ADDR))

#define ZSTR 136
#define H2(u) (*(__half2*)&(u))

__global__ void __launch_bounds__(256, 2) layer_kernel(
        const __half* __restrict__ hin, __half* __restrict__ hout,
        const uint2* __restrict__ w1h, const uint2* __restrict__ w1l,
        const uint2* __restrict__ w2h, const uint2* __restrict__ w2l,
        const float* __restrict__ b1,
        const float* __restrict__ gamma, const float* __restrict__ beta,
        const float* __restrict__ rmean, const float* __restrict__ rvar,
        const float* __restrict__ b2,
        const int* __restrict__ batch, float* __restrict__ pooled, int pool_off,
        const int* __restrict__ rowstart, const int* __restrict__ col) {
    __shared__ __half Ah[16 * ZSTR];
    __shared__ __half Zh[16 * ZSTR];

    int tid = threadIdx.x;
    int wid = tid >> 5;          // 0..7
    int lane = tid & 31;
    int g = lane >> 2, tg = lane & 3;
    int hw = tid >> 4;           // 0..15 half-warp = tile row
    int l16 = tid & 15;

    // epilogue constants for the 4 cols this thread owns
    int colA = wid * 16 + tg * 2;      // cols colA, colA+1
    int colB = colA + 8;               // cols colB, colB+1
    float scA0 = __ldg(&gamma[colA]) * rsqrtf(__ldg(&rvar[colA]) + BN_EPS);
    float shA0 = __ldg(&beta[colA]) - __ldg(&rmean[colA]) * scA0
                 + scA0 * __ldg(&b1[colA]);
    float scA1 = __ldg(&gamma[colA + 1]) * rsqrtf(__ldg(&rvar[colA + 1]) + BN_EPS);
    float shA1 = __ldg(&beta[colA + 1]) - __ldg(&rmean[colA + 1]) * scA1
                 + scA1 * __ldg(&b1[colA + 1]);
    float scB0 = __ldg(&gamma[colB]) * rsqrtf(__ldg(&rvar[colB]) + BN_EPS);
    float shB0 = __ldg(&beta[colB]) - __ldg(&rmean[colB]) * scB0
                 + scB0 * __ldg(&b1[colB]);
    float scB1 = __ldg(&gamma[colB + 1]) * rsqrtf(__ldg(&rvar[colB + 1]) + BN_EPS);
    float shB1 = __ldg(&beta[colB + 1]) - __ldg(&rmean[colB + 1]) * scB1
                 + scB1 * __ldg(&b1[colB + 1]);
    float bbA0 = __ldg(&b2[colA]), bbA1 = __ldg(&b2[colA + 1]);
    float bbB0 = __ldg(&b2[colB]), bbB1 = __ldg(&b2[colB + 1]);

    // W-frag pointers: layout index = (w*8 + kt)*32 + lane
    const uint2* w1hA = w1h + (wid * 2) * 8 * 32 + lane;
    const uint2* w1lA = w1l + (wid * 2) * 8 * 32 + lane;
    const uint2* w1hB = w1h + (wid * 2 + 1) * 8 * 32 + lane;
    const uint2* w1lB = w1l + (wid * 2 + 1) * 8 * 32 + lane;
    const uint2* w2hA = w2h + (wid * 2) * 8 * 32 + lane;
    const uint2* w2lA = w2l + (wid * 2) * 8 * 32 + lane;
    const uint2* w2hB = w2h + (wid * 2 + 1) * 8 * 32 + lane;
    const uint2* w2lB = w2l + (wid * 2 + 1) * 8 * 32 + lane;

    unsigned baseA, baseZ;
    {
        unsigned off = (lane & 15) * (ZSTR * 2) + (lane >> 4) * 16;
        baseA = (unsigned)__cvta_generic_to_shared(&Ah[0]) + off;
        baseZ = (unsigned)__cvta_generic_to_shared(&Zh[0]) + off;
    }

    for (int mt = blockIdx.x; mt < M_TILES; mt += gridDim.x) {
        // ---------- gather: row (mt*16+hw) -> Ah[hw] (fp16) ----------
        {
            int row = mt * 16 + hw;
            float acc[8] = {0.f, 0.f, 0.f, 0.f, 0.f, 0.f, 0.f, 0.f};
            if (row < N_NODES) {
                int beg = __ldg(&rowstart[row]);
                int end = __ldg(&rowstart[row + 1]);
                uint4 r0 = __ldg((const uint4*)(hin + (long long)row * DIM) + l16);
                float2 f0 = __half22float2(H2(r0.x));
                float2 f1 = __half22float2(H2(r0.y));
                float2 f2 = __half22float2(H2(r0.z));
                float2 f3 = __half22float2(H2(r0.w));
                acc[0] = f0.x; acc[1] = f0.y; acc[2] = f1.x; acc[3] = f1.y;
                acc[4] = f2.x; acc[5] = f2.y; acc[6] = f3.x; acc[7] = f3.y;
                for (int i = beg; i < end; i += 8) {
                    int4 c0 = __ldg((const int4*)(col + i));
                    int4 c1 = __ldg((const int4*)(col + i + 4));
                    uint4 r[8];
                    r[0] = __ldg((const uint4*)(hin + (long long)c0.x * DIM) + l16);
                    r[1] = __ldg((const uint4*)(hin + (long long)c0.y * DIM) + l16);
                    r[2] = __ldg((const uint4*)(hin + (long long)c0.z * DIM) + l16);
                    r[3] = __ldg((const uint4*)(hin + (long long)c0.w * DIM) + l16);
                    r[4] = __ldg((const uint4*)(hin + (long long)c1.x * DIM) + l16);
                    r[5] = __ldg((const uint4*)(hin + (long long)c1.y * DIM) + l16);
                    r[6] = __ldg((const uint4*)(hin + (long long)c1.z * DIM) + l16);
                    r[7] = __ldg((const uint4*)(hin + (long long)c1.w * DIM) + l16);
                    __half2 sx = __hadd2(
                        __hadd2(__hadd2(H2(r[0].x), H2(r[1].x)),
                                __hadd2(H2(r[2].x), H2(r[3].x))),
                        __hadd2(__hadd2(H2(r[4].x), H2(r[5].x)),
                                __hadd2(H2(r[6].x), H2(r[7].x))));
                    __half2 sy = __hadd2(
                        __hadd2(__hadd2(H2(r[0].y), H2(r[1].y)),
                                __hadd2(H2(r[2].y), H2(r[3].y))),
                        __hadd2(__hadd2(H2(r[4].y), H2(r[5].y)),
                                __hadd2(H2(r[6].y), H2(r[7].y))));
                    __half2 sz = __hadd2(
                        __hadd2(__hadd2(H2(r[0].z), H2(r[1].z)),
                                __hadd2(H2(r[2].z), H2(r[3].z))),
                        __hadd2(__hadd2(H2(r[4].z), H2(r[5].z)),
                                __hadd2(H2(r[6].z), H2(r[7].z))));
                    __half2 sw = __hadd2(
                        __hadd2(__hadd2(H2(r[0].w), H2(r[1].w)),
                                __hadd2(H2(r[2].w), H2(r[3].w))),
                        __hadd2(__hadd2(H2(r[4].w), H2(r[5].w)),
                                __hadd2(H2(r[6].w), H2(r[7].w))));
                    float2 q;
                    q = __half22float2(sx); acc[0] += q.x; acc[1] += q.y;
                    q = __half22float2(sy); acc[2] += q.x; acc[3] += q.y;
                    q = __half22float2(sz); acc[4] += q.x; acc[5] += q.y;
                    q = __half22float2(sw); acc[6] += q.x; acc[7] += q.y;
                }
            }
            __half2 p0 = __float22half2_rn(make_float2(acc[0], acc[1]));
            __half2 p1 = __float22half2_rn(make_float2(acc[2], acc[3]));
            __half2 p2 = __float22half2_rn(make_float2(acc[4], acc[5]));
            __half2 p3 = __float22half2_rn(make_float2(acc[6], acc[7]));
            uint4 o;
            o.x = *(unsigned*)&p0; o.y = *(unsigned*)&p1;
            o.z = *(unsigned*)&p2; o.w = *(unsigned*)&p3;
            *(uint4*)&Ah[hw * ZSTR + l16 * 8] = o;
        }
        __syncthreads();

        // ---------- MLP1: z = ReLU(BN(aggr @ W1 + b1)) -> Zh ----------
        float cA[4] = {0.f, 0.f, 0.f, 0.f}, eA[4] = {0.f, 0.f, 0.f, 0.f};
        float cB[4] = {0.f, 0.f, 0.f, 0.f}, eB[4] = {0.f, 0.f, 0.f, 0.f};
#pragma unroll
        for (int kt = 0; kt < 8; kt++) {
            unsigned x0, x1, x2, x3;
            LDSM4(x0, x1, x2, x3, baseA + kt * 32);
            uint2 whA = __ldg(w1hA + kt * 32);
            uint2 wlA = __ldg(w1lA + kt * 32);
            uint2 whB = __ldg(w1hB + kt * 32);
            uint2 wlB = __ldg(w1lB + kt * 32);
            MMA16816(cA, x0, x1, x2, x3, whA.x, whA.y);
            MMA16816(eA, x0, x1, x2, x3, wlA.x, wlA.y);
            MMA16816(cB, x0, x1, x2, x3, whB.x, whB.y);
            MMA16816(eB, x0, x1, x2, x3, wlB.x, wlB.y);
        }
        {
            float yA00 = fmaxf(scA0 * (cA[0] + eA[0]) + shA0, 0.f);
            float yA01 = fmaxf(scA1 * (cA[1] + eA[1]) + shA1, 0.f);
            float yA10 = fmaxf(scA0 * (cA[2] + eA[2]) + shA0, 0.f);
            float yA11 = fmaxf(scA1 * (cA[3] + eA[3]) + shA1, 0.f);
            float yB00 = fmaxf(scB0 * (cB[0] + eB[0]) + shB0, 0.f);
            float yB01 = fmaxf(scB1 * (cB[1] + eB[1]) + shB1, 0.f);
            float yB10 = fmaxf(scB0 * (cB[2] + eB[2]) + shB0, 0.f);
            float yB11 = fmaxf(scB1 * (cB[3] + eB[3]) + shB1, 0.f);
            *(__half2*)&Zh[g * ZSTR + colA] =
                __float22half2_rn(make_float2(yA00, yA01));
            *(__half2*)&Zh[(g + 8) * ZSTR + colA] =
                __float22half2_rn(make_float2(yA10, yA11));
            *(__half2*)&Zh[g * ZSTR + colB] =
                __float22half2_rn(make_float2(yB00, yB01));
            *(__half2*)&Zh[(g + 8) * ZSTR + colB] =
                __float22half2_rn(make_float2(yB10, yB11));
        }
        __syncthreads();

        // ---------- MLP2: h = ReLU(z @ W2 + b2) -> hout + pool ----------
#pragma unroll
        for (int j = 0; j < 4; j++) { cA[j] = 0.f; eA[j] = 0.f; cB[j] = 0.f; eB[j] = 0.f; }
#pragma unroll
        for (int kt = 0; kt < 8; kt++) {
            unsigned x0, x1, x2, x3;
            LDSM4(x0, x1, x2, x3, baseZ + kt * 32);
            uint2 whA = __ldg(w2hA + kt * 32);
            uint2 wlA = __ldg(w2lA + kt * 32);
            uint2 whB = __ldg(w2hB + kt * 32);
            uint2 wlB = __ldg(w2lB + kt * 32);
            MMA16816(cA, x0, x1, x2, x3, whA.x, whA.y);
            MMA16816(eA, x0, x1, x2, x3, wlA.x, wlA.y);
            MMA16816(cB, x0, x1, x2, x3, whB.x, whB.y);
            MMA16816(eB, x0, x1, x2, x3, wlB.x, wlB.y);
        }
        {
            float yA00 = fmaxf(cA[0] + eA[0] + bbA0, 0.f);
            float yA01 = fmaxf(cA[1] + eA[1] + bbA1, 0.f);
            float yA10 = fmaxf(cA[2] + eA[2] + bbA0, 0.f);
            float yA11 = fmaxf(cA[3] + eA[3] + bbA1, 0.f);
            float yB00 = fmaxf(cB[0] + eB[0] + bbB0, 0.f);
            float yB01 = fmaxf(cB[1] + eB[1] + bbB1, 0.f);
            float yB10 = fmaxf(cB[2] + eB[2] + bbB0, 0.f);
            float yB11 = fmaxf(cB[3] + eB[3] + bbB1, 0.f);
            int r0 = mt * 16 + g;
            int r1 = r0 + 8;
            if (r0 < N_NODES) {
                *(__half2*)(hout + (long long)r0 * DIM + colA) =
                    __float22half2_rn(make_float2(yA00, yA01));
                *(__half2*)(hout + (long long)r0 * DIM + colB) =
                    __float22half2_rn(make_float2(yB00, yB01));
                int bi = __ldg(&batch[r0]);
                float* pb = pooled + bi * DCAT + pool_off;
                asm volatile("red.global.add.v2.f32 [%0], {%1,%2};"
                             :: "l"(pb + colA), "f"(yA00), "f"(yA01) : "memory");
                asm volatile("red.global.add.v2.f32 [%0], {%1,%2};"
                             :: "l"(pb + colB), "f"(yB00), "f"(yB01) : "memory");
            }
            if (r1 < N_NODES) {
                *(__half2*)(hout + (long long)r1 * DIM + colA) =
                    __float22half2_rn(make_float2(yA10, yA11));
                *(__half2*)(hout + (long long)r1 * DIM + colB) =
                    __float22half2_rn(make_float2(yB10, yB11));
                int bi = __ldg(&batch[r1]);
                float* pb = pooled + bi * DCAT + pool_off;
                asm volatile("red.global.add.v2.f32 [%0], {%1,%2};"
                             :: "l"(pb + colA), "f"(yA10), "f"(yA11) : "memory");
                asm volatile("red.global.add.v2.f32 [%0], {%1,%2};"
                             :: "l"(pb + colB), "f"(yB10), "f"(yB11) : "memory");
            }
        }
        __syncthreads();   // Ah/Zh reuse next tile
    }
}

// h_fin = relu(pooled @ Wfin + bfin)
__global__ void __launch_bounds__(DCAT) fin1_kernel(
        const float* __restrict__ pooled, const float* __restrict__ Wfin,
        const float* __restrict__ bfin, float* __restrict__ hfin) {
    __shared__ float s[DCAT];
    int g = blockIdx.x;
    int j = threadIdx.x;
    s[j] = pooled[g * DCAT + j];
    __syncthreads();
    float acc0 = 0.f, acc1 = 0.f, acc2 = 0.f, acc3 = 0.f;
#pragma unroll 4
    for (int k = 0; k < DCAT; k += 4) {
        acc0 += s[k + 0] * __ldg(&Wfin[(k + 0) * DCAT + j]);
        acc1 += s[k + 1] * __ldg(&Wfin[(k + 1) * DCAT + j]);
        acc2 += s[k + 2] * __ldg(&Wfin[(k + 2) * DCAT + j]);
        acc3 += s[k + 3] * __ldg(&Wfin[(k + 3) * DCAT + j]);
    }
    float acc = (acc0 + acc1) + (acc2 + acc3) + __ldg(&bfin[j]);
    hfin[g * DCAT + j] = fmaxf(acc, 0.f);
}

// logits + log_softmax: one warp per graph.
__global__ void __launch_bounds__(32) fin2_kernel(
        const float* __restrict__ hfin, const float* __restrict__ Wout,
        const float* __restrict__ bout, float* __restrict__ out, int out_size) {
    int g = blockIdx.x;
    int lane = threadIdx.x;
    bool valid = lane < NCLS;
    float acc = valid ? __ldg(&bout[lane]) : 0.f;
    for (int k = 0; k < DCAT; k++) {
        float v = __ldg(&hfin[g * DCAT + k]);
        if (valid) acc += v * __ldg(&Wout[k * NCLS + lane]);
    }
    float logit = acc;
    float m = valid ? logit : -INFINITY;
#pragma unroll
    for (int off = 16; off > 0; off >>= 1)
        m = fmaxf(m, __shfl_xor_sync(0xFFFFFFFFu, m, off));
    float e = valid ? expf(logit - m) : 0.f;
#pragma unroll
    for (int off = 16; off > 0; off >>= 1)
        e += __shfl_xor_sync(0xFFFFFFFFu, e, off);
    float ls = logit - m - logf(e);
    if (valid) {
        out[g * NCLS + lane] = logit;
        if (out_size >= 2 * N_GRAPHS * NCLS)
            out[N_GRAPHS * NCLS + g * NCLS + lane] = ls;
    }
}

extern "C" void kernel_launch(void* const* d_in, const int* in_sizes, int n_in,
                              void* d_out, int out_size) {
    const float* x        = (const float*)d_in[0];
    const int*   ei       = (const int*)d_in[1];
    const int*   batch    = (const int*)d_in[2];

    int w = 3;
    if (n_in >= 4 && in_sizes[3] == 1) w = 4;

    const float* W1   = (const float*)d_in[w + 0];
    const float* b1   = (const float*)d_in[w + 1];
    const float* gamma= (const float*)d_in[w + 2];
    const float* beta = (const float*)d_in[w + 3];
    const float* rmean= (const float*)d_in[w + 4];
    const float* rvar = (const float*)d_in[w + 5];
    const float* W2   = (const float*)d_in[w + 6];
    const float* b2   = (const float*)d_in[w + 7];
    const float* Wfin = (const float*)d_in[w + 8];
    const float* bfin = (const float*)d_in[w + 9];
    const float* Wout = (const float*)d_in[w + 10];
    const float* bout = (const float*)d_in[w + 11];
    float* out = (float*)d_out;

    float *pooled, *hfin;
    __half *hh0, *hh1;
    uint2 *wfh, *wfl;
    int *counts, *rowstart, *cursor, *colbuf, *bsum;
    cudaGetSymbolAddress((void**)&hh0,      g_hh0);
    cudaGetSymbolAddress((void**)&hh1,      g_hh1);
    cudaGetSymbolAddress((void**)&pooled,   g_pooled);
    cudaGetSymbolAddress((void**)&hfin,     g_hfin);
    cudaGetSymbolAddress((void**)&counts,   g_counts);
    cudaGetSymbolAddress((void**)&rowstart, g_rowstart);
    cudaGetSymbolAddress((void**)&cursor,   g_cursor);
    cudaGetSymbolAddress((void**)&colbuf,   g_col);
    cudaGetSymbolAddress((void**)&bsum,     g_bsum);
    cudaGetSymbolAddress((void**)&wfh,      g_wfh);
    cudaGetSymbolAddress((void**)&wfl,      g_wfl);

    const int E4B = (N_EDGES / 4 + 255) / 256;
    const int LB = 296;   // 148 SMs x occupancy 2

    zero_int_kernel<<<(N_NODES + 4 + 255) / 256, 256>>>(counts, N_NODES + 4);
    zero_kernel<<<192, 256>>>((float4*)pooled, N_GRAPHS * DCAT / 4);
    // zero sentinel rows of both h buffers (row N_NODES, 256B each)
    zero_kernel<<<1, 16>>>((float4*)(hh0 + (long long)N_NODES * DIM), 16);
    zero_kernel<<<1, 16>>>((float4*)(hh1 + (long long)N_NODES * DIM), 16);
    x2h_kernel<<<(N_NODES * DIM / 4 + 255) / 256, 256>>>(
        (const float4*)x, (uint2*)hh0);
    hist_kernel<<<E4B, 256>>>(ei, counts);
    scan1_kernel<<<SCAN_NB, 1024>>>(counts, rowstart, bsum);
    scan2_kernel<<<1, 32>>>(bsum);
    scan3_kernel<<<SCAN_NB, 1024>>>(bsum, rowstart, cursor);
    pad_kernel<<<(N_NODES + 255) / 256, 256>>>(counts, rowstart, colbuf);
    fill_kernel<<<E4B, 256>>>(ei, cursor, colbuf);
    wfrag_kernel<<<(6 * WFRAG_PER_L2 + 255) / 256, 256>>>(W1, W2, wfh, wfl);

    const __half* hin = hh0;
    __half* hout = hh1;
    for (int i = 0; i < NLAYERS; i++) {
        int l2a = i * 2, l2b = i * 2 + 1;
        layer_kernel<<<LB, 256>>>(
            hin, hout,
            wfh + l2a * WFRAG_PER_L2, wfl + l2a * WFRAG_PER_L2,
            wfh + l2b * WFRAG_PER_L2, wfl + l2b * WFRAG_PER_L2,
            b1 + i * DIM,
            gamma + i * DIM, beta + i * DIM, rmean + i * DIM, rvar + i * DIM,
            b2 + i * DIM,
            batch, pooled, i * DIM, rowstart, colbuf);
        const __half* t = hin;
        hin = hout;
        hout = (__half*)t;
    }

    fin1_kernel<<<N_GRAPHS, DCAT>>>(pooled, Wfin, bfin, hfin);
    fin2_kernel<<<N_GRAPHS, 32>>>(hfin, Wout, bout, out, out_size);
}